// round 4
// baseline (speedup 1.0000x reference)
#include <cuda_runtime.h>
#include <cuda_bf16.h>
#include <math.h>

// ----------------------------------------------------------------------------
// Problem constants (shapes fixed by the reference)
// ----------------------------------------------------------------------------
#define MAXN 50000
#define MAXE 200000
#define F_IN 66
#define H1 8
#define C1 128
#define D1 (H1 * C1)   // 1024
#define D2 128
#define D3 64

// ----------------------------------------------------------------------------
// Device scratch (static globals: allocation-free)
// ----------------------------------------------------------------------------
__device__ float g_h1[(size_t)MAXN * D1];     // x @ W1
__device__ float g_agg1[(size_t)MAXN * D1];   // layer-1 output (in-place ELU)
__device__ float g_h2[(size_t)MAXN * D2];
__device__ float g_agg2[(size_t)MAXN * D2];
__device__ float g_h3[(size_t)MAXN * D3];
__device__ float g_agg3[(size_t)MAXN * D3];

__device__ float g_es1[MAXN * H1], g_ed1[MAXN * H1], g_z1[MAXN * H1];
__device__ float g_es2[MAXN], g_ed2[MAXN], g_z2[MAXN];
__device__ float g_es3[MAXN], g_ed3[MAXN], g_z3[MAXN];
__device__ float g_w1[(size_t)(MAXE + MAXN) * H1];
__device__ float g_w2[(MAXE + MAXN)];
__device__ float g_w3[(MAXE + MAXN)];

// ----------------------------------------------------------------------------
// Tiled fp32 GEMM: C[M,N] = A[M,K] @ B[K,N]
// Requires N % BN == 0 (true for all three GEMMs here); M and K are guarded.
// ----------------------------------------------------------------------------
template <int BM, int BN, int BK, int TM, int TN>
__global__ void sgemm_kernel(int M, int N, int K,
                             const float* __restrict__ A,
                             const float* __restrict__ B,
                             float* __restrict__ C) {
    constexpr int THREADS = (BM / TM) * (BN / TN);
    __shared__ float As[BK][BM];
    __shared__ float Bs[BK][BN];

    const int bm = blockIdx.y * BM;
    const int bn = blockIdx.x * BN;
    const int tid = threadIdx.x;
    const int trow = (tid / (BN / TN)) * TM;
    const int tcol = (tid % (BN / TN)) * TN;

    float acc[TM][TN];
#pragma unroll
    for (int i = 0; i < TM; i++)
#pragma unroll
        for (int j = 0; j < TN; j++) acc[i][j] = 0.f;

    for (int k0 = 0; k0 < K; k0 += BK) {
        // load A tile
        for (int i = tid; i < BM * BK; i += THREADS) {
            int r = i / BK, c = i % BK;
            int gr = bm + r, gc = k0 + c;
            As[c][r] = (gr < M && gc < K) ? A[(size_t)gr * K + gc] : 0.f;
        }
        // load B tile
        for (int i = tid; i < BK * BN; i += THREADS) {
            int r = i / BN, c = i % BN;
            int gk = k0 + r;
            Bs[r][c] = (gk < K) ? B[(size_t)gk * N + bn + c] : 0.f;
        }
        __syncthreads();

        float ra[TM], rb[TN];
#pragma unroll
        for (int k = 0; k < BK; k++) {
#pragma unroll
            for (int i = 0; i < TM; i++) ra[i] = As[k][trow + i];
#pragma unroll
            for (int j = 0; j < TN; j++) rb[j] = Bs[k][tcol + j];
#pragma unroll
            for (int i = 0; i < TM; i++)
#pragma unroll
                for (int j = 0; j < TN; j++) acc[i][j] += ra[i] * rb[j];
        }
        __syncthreads();
    }

#pragma unroll
    for (int i = 0; i < TM; i++) {
        int gr = bm + trow + i;
        if (gr < M) {
#pragma unroll
            for (int j = 0; j < TN; j++)
                C[(size_t)gr * N + bn + tcol + j] = acc[i][j];
        }
    }
}

// ----------------------------------------------------------------------------
// Attention coefficients: es[n,h] = <h[n,h,:], a_src[h,:]>, ed likewise.
// One warp per (node, head).
// ----------------------------------------------------------------------------
template <int C, int H>
__global__ void esed_kernel(int NN, const float* __restrict__ h,
                            const float* __restrict__ as,
                            const float* __restrict__ ad,
                            float* __restrict__ es, float* __restrict__ ed) {
    int gw = (blockIdx.x * blockDim.x + threadIdx.x) >> 5;
    int lane = threadIdx.x & 31;
    if (gw >= NN * H) return;
    int n = gw / H, hh = gw % H;
    const float* row = h + (size_t)n * (H * C) + hh * C;
    const float* av = as + hh * C;
    const float* dv = ad + hh * C;
    float s = 0.f, d = 0.f;
#pragma unroll
    for (int c = lane; c < C; c += 32) {
        float v = row[c];
        s += v * av[c];
        d += v * dv[c];
    }
#pragma unroll
    for (int off = 16; off > 0; off >>= 1) {
        s += __shfl_down_sync(0xffffffffu, s, off);
        d += __shfl_down_sync(0xffffffffu, d, off);
    }
    if (lane == 0) { es[gw] = s; ed[gw] = d; }
}

// ----------------------------------------------------------------------------
// Edge logits: w = exp(leaky_relu(es[src]+ed[dst])); z[dst] += w (atomic).
// Softmax max-subtraction omitted: exp(e)/sum exp(e) is identical and logits
// are bounded far below overflow.
// Edges [0,E): real edges from edge_index (int32); [E, E+NN): self loops.
// ----------------------------------------------------------------------------
template <int H>
__global__ void edgew_kernel(int E, int NN, const int* __restrict__ ei,
                             const float* __restrict__ es,
                             const float* __restrict__ ed,
                             float* __restrict__ w, float* __restrict__ z) {
    int idx = blockIdx.x * blockDim.x + threadIdx.x;
    int tot = (E + NN) * H;
    if (idx >= tot) return;
    int e = idx / H, hh = idx - e * H;
    int s, d;
    if (e < E) { s = ei[e]; d = ei[E + e]; }
    else       { s = d = e - E; }
    float v = es[(size_t)s * H + hh] + ed[(size_t)d * H + hh];
    v = v > 0.f ? v : 0.2f * v;      // leaky relu, slope 0.2
    float wv = expf(v);
    w[idx] = wv;
    atomicAdd(&z[(size_t)d * H + hh], wv);
}

// ----------------------------------------------------------------------------
// Aggregation: out[dst,h,:] += alpha * h[src,h,:], one warp per (edge,head).
// Vector float4 (C=128) / float2 (C=64) atomics.
// ----------------------------------------------------------------------------
template <int C, int H>
__global__ void agg_kernel(int E, int NN, const int* __restrict__ ei,
                           const float* __restrict__ h,
                           const float* __restrict__ w,
                           const float* __restrict__ z,
                           float* __restrict__ out) {
    int gw = (blockIdx.x * blockDim.x + threadIdx.x) >> 5;
    int lane = threadIdx.x & 31;
    int tot = (E + NN) * H;
    if (gw >= tot) return;
    int e = gw / H, hh = gw - e * H;
    int s, d;
    if (e < E) { s = ei[e]; d = ei[E + e]; }
    else       { s = d = e - E; }
    float alpha = w[gw] / (z[(size_t)d * H + hh] + 1e-16f);
    const float* hrow = h + (size_t)s * (H * C) + hh * C;
    float* orow = out + (size_t)d * (H * C) + hh * C;
    if (C == 128) {
        float4 v = reinterpret_cast<const float4*>(hrow)[lane];
        v.x *= alpha; v.y *= alpha; v.z *= alpha; v.w *= alpha;
        atomicAdd(reinterpret_cast<float4*>(orow) + lane, v);
    } else {  // C == 64
        float2 v = reinterpret_cast<const float2*>(hrow)[lane];
        v.x *= alpha; v.y *= alpha;
        atomicAdd(reinterpret_cast<float2*>(orow) + lane, v);
    }
}

// ----------------------------------------------------------------------------
// bias + ELU, in place
// ----------------------------------------------------------------------------
__global__ void bias_elu_kernel(float* __restrict__ a, const float* __restrict__ b,
                                long long total, int W) {
    long long i = (long long)blockIdx.x * blockDim.x + threadIdx.x;
    long long stride = (long long)gridDim.x * blockDim.x;
    for (; i < total; i += stride) {
        float v = a[i] + b[i % W];
        a[i] = v > 0.f ? v : expm1f(v);
    }
}

// ----------------------------------------------------------------------------
// Final: per node, ELU(agg3 + b3) . Wr + br -> sigmoid. One warp per node.
// ----------------------------------------------------------------------------
__global__ void final_kernel(int NN, const float* __restrict__ agg3,
                             const float* __restrict__ b3,
                             const float* __restrict__ Wr,
                             const float* __restrict__ br,
                             float* __restrict__ out) {
    int n = (blockIdx.x * blockDim.x + threadIdx.x) >> 5;
    int lane = threadIdx.x & 31;
    if (n >= NN) return;
    const float* row = agg3 + (size_t)n * D3;
    float acc = 0.f;
#pragma unroll
    for (int j = lane; j < D3; j += 32) {
        float v = row[j] + b3[j];
        v = v > 0.f ? v : expm1f(v);
        acc += v * Wr[j];
    }
#pragma unroll
    for (int off = 16; off > 0; off >>= 1)
        acc += __shfl_down_sync(0xffffffffu, acc, off);
    if (lane == 0)
        out[n] = 1.f / (1.f + expf(-(acc + br[0])));
}

// ----------------------------------------------------------------------------
// Host launcher
// ----------------------------------------------------------------------------
static inline int ceil_div(int a, int b) { return (a + b - 1) / b; }

extern "C" void kernel_launch(void* const* d_in, const int* in_sizes, int n_in,
                              void* d_out, int out_size) {
    const float* x   = (const float*)d_in[0];
    const int*   ei  = (const int*)d_in[1];   // int32: JAX default x64-disabled
    const float* W1  = (const float*)d_in[2];
    const float* as1 = (const float*)d_in[3];
    const float* ad1 = (const float*)d_in[4];
    const float* b1  = (const float*)d_in[5];
    const float* W2  = (const float*)d_in[6];
    const float* as2 = (const float*)d_in[7];
    const float* ad2 = (const float*)d_in[8];
    const float* b2  = (const float*)d_in[9];
    const float* W3  = (const float*)d_in[10];
    const float* as3 = (const float*)d_in[11];
    const float* ad3 = (const float*)d_in[12];
    const float* b3  = (const float*)d_in[13];
    const float* Wr  = (const float*)d_in[14];
    const float* br  = (const float*)d_in[15];
    float* out = (float*)d_out;

    const int N = in_sizes[0] / F_IN;
    const int E = in_sizes[1] / 2;

    float *h1, *agg1, *h2, *agg2, *h3, *agg3;
    float *es1, *ed1, *z1, *es2, *ed2, *z2, *es3, *ed3, *z3, *w1, *w2, *w3;
    cudaGetSymbolAddress((void**)&h1, g_h1);
    cudaGetSymbolAddress((void**)&agg1, g_agg1);
    cudaGetSymbolAddress((void**)&h2, g_h2);
    cudaGetSymbolAddress((void**)&agg2, g_agg2);
    cudaGetSymbolAddress((void**)&h3, g_h3);
    cudaGetSymbolAddress((void**)&agg3, g_agg3);
    cudaGetSymbolAddress((void**)&es1, g_es1);
    cudaGetSymbolAddress((void**)&ed1, g_ed1);
    cudaGetSymbolAddress((void**)&z1, g_z1);
    cudaGetSymbolAddress((void**)&es2, g_es2);
    cudaGetSymbolAddress((void**)&ed2, g_ed2);
    cudaGetSymbolAddress((void**)&z2, g_z2);
    cudaGetSymbolAddress((void**)&es3, g_es3);
    cudaGetSymbolAddress((void**)&ed3, g_ed3);
    cudaGetSymbolAddress((void**)&z3, g_z3);
    cudaGetSymbolAddress((void**)&w1, g_w1);
    cudaGetSymbolAddress((void**)&w2, g_w2);
    cudaGetSymbolAddress((void**)&w3, g_w3);

    const int ET = E + N;  // edges incl. self-loops

    // zero accumulators
    cudaMemsetAsync(agg1, 0, (size_t)N * D1 * sizeof(float));
    cudaMemsetAsync(agg2, 0, (size_t)N * D2 * sizeof(float));
    cudaMemsetAsync(agg3, 0, (size_t)N * D3 * sizeof(float));
    cudaMemsetAsync(z1, 0, (size_t)N * H1 * sizeof(float));
    cudaMemsetAsync(z2, 0, (size_t)N * sizeof(float));
    cudaMemsetAsync(z3, 0, (size_t)N * sizeof(float));

    // ---------------- Layer 1: 66 -> 8 x 128 (concat 1024) ----------------
    {
        dim3 grid(D1 / 128, ceil_div(N, 128));
        sgemm_kernel<128, 128, 16, 8, 8><<<grid, 256>>>(N, D1, F_IN, x, W1, h1);
    }
    esed_kernel<C1, H1><<<ceil_div(N * H1 * 32, 256), 256>>>(N, h1, as1, ad1, es1, ed1);
    edgew_kernel<H1><<<ceil_div(ET * H1, 256), 256>>>(E, N, ei, es1, ed1, w1, z1);
    agg_kernel<C1, H1><<<ceil_div(ET * H1 * 32, 256), 256>>>(E, N, ei, h1, w1, z1, agg1);
    bias_elu_kernel<<<2048, 256>>>(agg1, b1, (long long)N * D1, D1);

    // ---------------- Layer 2: 1024 -> 128 ----------------
    {
        dim3 grid(D2 / 128, ceil_div(N, 64));
        sgemm_kernel<64, 128, 16, 4, 8><<<grid, 256>>>(N, D2, D1, agg1, W2, h2);
    }
    esed_kernel<D2, 1><<<ceil_div(N * 32, 256), 256>>>(N, h2, as2, ad2, es2, ed2);
    edgew_kernel<1><<<ceil_div(ET, 256), 256>>>(E, N, ei, es2, ed2, w2, z2);
    agg_kernel<D2, 1><<<ceil_div(ET * 32, 256), 256>>>(E, N, ei, h2, w2, z2, agg2);
    bias_elu_kernel<<<1024, 256>>>(agg2, b2, (long long)N * D2, D2);

    // ---------------- Layer 3: 128 -> 64 ----------------
    {
        dim3 grid(D3 / 64, ceil_div(N, 64));
        sgemm_kernel<64, 64, 16, 4, 4><<<grid, 256>>>(N, D3, D2, agg2, W3, h3);
    }
    esed_kernel<D3, 1><<<ceil_div(N * 32, 256), 256>>>(N, h3, as3, ad3, es3, ed3);
    edgew_kernel<1><<<ceil_div(ET, 256), 256>>>(E, N, ei, es3, ed3, w3, z3);
    agg_kernel<D3, 1><<<ceil_div(ET * 32, 256), 256>>>(E, N, ei, h3, w3, z3, agg3);

    // ---------------- Regressor (fused bias+ELU+dot+sigmoid) ----------------
    final_kernel<<<ceil_div(N * 32, 256), 256>>>(N, agg3, b3, Wr, br, out);
}

// round 5
// speedup vs baseline: 1.4026x; 1.4026x over previous
#include <cuda_runtime.h>
#include <cuda_bf16.h>
#include <math.h>

// ----------------------------------------------------------------------------
// Problem constants (shapes fixed by the reference)
// ----------------------------------------------------------------------------
#define MAXN 50000
#define MAXE 200000
#define F_IN 66
#define H1 8
#define C1 128
#define D1 (H1 * C1)   // 1024
#define D2 128
#define D3 64
#define XH (H1 * F_IN) // 528 : per-node width of x-space aggregation buffer

// ----------------------------------------------------------------------------
// Device scratch (static globals: allocation-free)
// ----------------------------------------------------------------------------
__device__ float g_aggX[(size_t)MAXN * XH];   // layer-1 x-space aggregation
__device__ float g_agg1[(size_t)MAXN * D1];   // layer-1 output (post bias+ELU)
__device__ float g_h2[(size_t)MAXN * D2];
__device__ float g_agg2[(size_t)MAXN * D2];
__device__ float g_h3[(size_t)MAXN * D3];
__device__ float g_agg3[(size_t)MAXN * D3];

__device__ float g_qs1[H1 * F_IN], g_qd1[H1 * F_IN];  // W1-projected attention vecs
__device__ float g_es1[MAXN * H1], g_ed1[MAXN * H1], g_z1[MAXN * H1];
__device__ float g_es2[MAXN], g_ed2[MAXN], g_z2[MAXN];
__device__ float g_es3[MAXN], g_ed3[MAXN], g_z3[MAXN];
__device__ float g_w1[(size_t)(MAXE + MAXN) * H1];
__device__ float g_w2[(MAXE + MAXN)];
__device__ float g_w3[(MAXE + MAXN)];

// ----------------------------------------------------------------------------
// Tiled fp32 GEMM: C[M,N] = A[M,K] @ B[K,N]  (N % BN == 0 required)
// ----------------------------------------------------------------------------
template <int BM, int BN, int BK, int TM, int TN>
__global__ void sgemm_kernel(int M, int N, int K,
                             const float* __restrict__ A,
                             const float* __restrict__ B,
                             float* __restrict__ C) {
    constexpr int THREADS = (BM / TM) * (BN / TN);
    __shared__ float As[BK][BM];
    __shared__ float Bs[BK][BN];

    const int bm = blockIdx.y * BM;
    const int bn = blockIdx.x * BN;
    const int tid = threadIdx.x;
    const int trow = (tid / (BN / TN)) * TM;
    const int tcol = (tid % (BN / TN)) * TN;

    float acc[TM][TN];
#pragma unroll
    for (int i = 0; i < TM; i++)
#pragma unroll
        for (int j = 0; j < TN; j++) acc[i][j] = 0.f;

    for (int k0 = 0; k0 < K; k0 += BK) {
        for (int i = tid; i < BM * BK; i += THREADS) {
            int r = i / BK, c = i % BK;
            int gr = bm + r, gc = k0 + c;
            As[c][r] = (gr < M && gc < K) ? A[(size_t)gr * K + gc] : 0.f;
        }
        for (int i = tid; i < BK * BN; i += THREADS) {
            int r = i / BN, c = i % BN;
            int gk = k0 + r;
            Bs[r][c] = (gk < K) ? B[(size_t)gk * N + bn + c] : 0.f;
        }
        __syncthreads();

        float ra[TM], rb[TN];
#pragma unroll
        for (int k = 0; k < BK; k++) {
#pragma unroll
            for (int i = 0; i < TM; i++) ra[i] = As[k][trow + i];
#pragma unroll
            for (int j = 0; j < TN; j++) rb[j] = Bs[k][tcol + j];
#pragma unroll
            for (int i = 0; i < TM; i++)
#pragma unroll
                for (int j = 0; j < TN; j++) acc[i][j] += ra[i] * rb[j];
        }
        __syncthreads();
    }

#pragma unroll
    for (int i = 0; i < TM; i++) {
        int gr = bm + trow + i;
        if (gr < M) {
#pragma unroll
            for (int j = 0; j < TN; j++)
                C[(size_t)gr * N + bn + tcol + j] = acc[i][j];
        }
    }
}

// ----------------------------------------------------------------------------
// Layer-1 attention vector projection: qs[h,k] = sum_c W1[k, h*128+c]*as1[h,c]
// One warp per (h,k) pair (528 warps).
// ----------------------------------------------------------------------------
__global__ void proj1_kernel(const float* __restrict__ W1,
                             const float* __restrict__ as1,
                             const float* __restrict__ ad1,
                             float* __restrict__ qs, float* __restrict__ qd) {
    int gw = (blockIdx.x * blockDim.x + threadIdx.x) >> 5;
    int lane = threadIdx.x & 31;
    if (gw >= H1 * F_IN) return;
    int h = gw / F_IN, k = gw % F_IN;
    const float* wrow = W1 + (size_t)k * D1 + h * C1;
    const float* av = as1 + h * C1;
    const float* dv = ad1 + h * C1;
    float s = 0.f, d = 0.f;
#pragma unroll
    for (int c = lane; c < C1; c += 32) {
        float wv = wrow[c];
        s += wv * av[c];
        d += wv * dv[c];
    }
#pragma unroll
    for (int off = 16; off > 0; off >>= 1) {
        s += __shfl_down_sync(0xffffffffu, s, off);
        d += __shfl_down_sync(0xffffffffu, d, off);
    }
    if (lane == 0) { qs[gw] = s; qd[gw] = d; }
}

// ----------------------------------------------------------------------------
// Layer-1 es/ed directly from x: es[n,h] = <x[n,:], qs[h,:]> (K = 66).
// Block = 256 threads = 32 nodes x 8 heads; x tile + q vectors staged in smem.
// ----------------------------------------------------------------------------
__global__ void esed1_kernel(int NN, const float* __restrict__ x,
                             const float* __restrict__ qs,
                             const float* __restrict__ qd,
                             float* __restrict__ es, float* __restrict__ ed) {
    __shared__ float xs[32][F_IN + 2];
    __shared__ float qss[H1 * F_IN], qds[H1 * F_IN];
    int tid = threadIdx.x;
    for (int i = tid; i < H1 * F_IN; i += 256) { qss[i] = qs[i]; qds[i] = qd[i]; }
    int n0 = blockIdx.x * 32;
    for (int i = tid; i < 32 * F_IN; i += 256) {
        int r = i / F_IN, c = i % F_IN;
        int n = n0 + r;
        xs[r][c] = (n < NN) ? x[(size_t)n * F_IN + c] : 0.f;
    }
    __syncthreads();
    int r = tid >> 3, h = tid & 7;
    int n = n0 + r;
    if (n < NN) {
        float s = 0.f, d = 0.f;
#pragma unroll
        for (int k = 0; k < F_IN; k++) {
            float xv = xs[r][k];
            s += xv * qss[h * F_IN + k];
            d += xv * qds[h * F_IN + k];
        }
        es[n * H1 + h] = s;
        ed[n * H1 + h] = d;
    }
}

// ----------------------------------------------------------------------------
// Edge logits: w = exp(leaky_relu(es[src]+ed[dst])); z[dst] += w (atomic).
// Softmax max-subtraction omitted (identical result, bounded logits).
// Edges [0,E): int32 edge_index; [E, E+NN): self loops.
// ----------------------------------------------------------------------------
template <int H>
__global__ void edgew_kernel(int E, int NN, const int* __restrict__ ei,
                             const float* __restrict__ es,
                             const float* __restrict__ ed,
                             float* __restrict__ w, float* __restrict__ z) {
    int idx = blockIdx.x * blockDim.x + threadIdx.x;
    int tot = (E + NN) * H;
    if (idx >= tot) return;
    int e = idx / H, hh = idx - e * H;
    int s, d;
    if (e < E) { s = ei[e]; d = ei[E + e]; }
    else       { s = d = e - E; }
    float v = es[(size_t)s * H + hh] + ed[(size_t)d * H + hh];
    v = v > 0.f ? v : 0.2f * v;      // leaky relu, slope 0.2
    float wv = expf(v);
    w[idx] = wv;
    atomicAdd(&z[(size_t)d * H + hh], wv);
}

// ----------------------------------------------------------------------------
// Layer-1 x-space aggregation: aggX[d, h, 0:66] += alpha_eh * x[s, 0:66].
// One warp per edge; x row (66 floats) loaded once, reused for all 8 heads.
// float2 atomics: lane j covers floats [2j,2j+1]; lane 0 also covers [64,65].
// ----------------------------------------------------------------------------
__global__ void aggx_kernel(int E, int NN, const int* __restrict__ ei,
                            const float* __restrict__ x,
                            const float* __restrict__ w,
                            const float* __restrict__ z,
                            float* __restrict__ aggX) {
    int gw = (blockIdx.x * blockDim.x + threadIdx.x) >> 5;
    int lane = threadIdx.x & 31;
    int ET = E + NN;
    if (gw >= ET) return;
    int s, d;
    if (gw < E) { s = ei[gw]; d = ei[E + gw]; }
    else        { s = d = gw - E; }
    const float2* xr = reinterpret_cast<const float2*>(x + (size_t)s * F_IN);
    float2 v0 = xr[lane];
    float2 v1 = (lane == 0) ? xr[32] : make_float2(0.f, 0.f);
    const float* wrow = w + (size_t)gw * H1;
    const float* zrow = z + (size_t)d * H1;
    float* obase = aggX + (size_t)d * XH;
#pragma unroll
    for (int h = 0; h < H1; h++) {
        float alpha = wrow[h] / (zrow[h] + 1e-16f);
        float2* o2 = reinterpret_cast<float2*>(obase + h * F_IN);
        atomicAdd(o2 + lane, make_float2(v0.x * alpha, v0.y * alpha));
        if (lane == 0)
            atomicAdd(o2 + 32, make_float2(v1.x * alpha, v1.y * alpha));
    }
}

// ----------------------------------------------------------------------------
// Per-head block-diagonal GEMM with fused bias+ELU:
// out[n, h*128+c] = ELU( sum_k aggX[n, h*66+k] * W1[k, h*128+c] + b1[h*128+c] )
// blockIdx.z = head.  BM=128, BN=128(=C1), BK=16, TM=TN=8, 256 threads.
// ----------------------------------------------------------------------------
__global__ void head_gemm_bias_elu(int M,
                                   const float* __restrict__ aggX,
                                   const float* __restrict__ W1,
                                   const float* __restrict__ b1,
                                   float* __restrict__ out) {
    constexpr int BM = 128, BN = 128, BK = 16, TM = 8, TN = 8;
    constexpr int THREADS = (BM / TM) * (BN / TN);   // 256
    __shared__ float As[BK][BM];
    __shared__ float Bs[BK][BN];

    const int h = blockIdx.z;
    const float* A = aggX + h * F_IN;   // lda = XH (528)
    const float* B = W1 + h * C1;       // ldb = D1 (1024)
    float* C = out + h * C1;            // ldc = D1
    const float* bias = b1 + h * C1;

    const int bm = blockIdx.y * BM;
    const int tid = threadIdx.x;
    const int trow = (tid / (BN / TN)) * TM;
    const int tcol = (tid % (BN / TN)) * TN;

    float acc[TM][TN];
#pragma unroll
    for (int i = 0; i < TM; i++)
#pragma unroll
        for (int j = 0; j < TN; j++) acc[i][j] = 0.f;

    for (int k0 = 0; k0 < F_IN; k0 += BK) {
        for (int i = tid; i < BM * BK; i += THREADS) {
            int r = i / BK, c = i % BK;
            int gr = bm + r, gc = k0 + c;
            As[c][r] = (gr < M && gc < F_IN) ? A[(size_t)gr * XH + gc] : 0.f;
        }
        for (int i = tid; i < BK * BN; i += THREADS) {
            int r = i / BN, c = i % BN;
            int gk = k0 + r;
            Bs[r][c] = (gk < F_IN) ? B[(size_t)gk * D1 + c] : 0.f;
        }
        __syncthreads();

        float ra[TM], rb[TN];
#pragma unroll
        for (int k = 0; k < BK; k++) {
#pragma unroll
            for (int i = 0; i < TM; i++) ra[i] = As[k][trow + i];
#pragma unroll
            for (int j = 0; j < TN; j++) rb[j] = Bs[k][tcol + j];
#pragma unroll
            for (int i = 0; i < TM; i++)
#pragma unroll
                for (int j = 0; j < TN; j++) acc[i][j] += ra[i] * rb[j];
        }
        __syncthreads();
    }

#pragma unroll
    for (int i = 0; i < TM; i++) {
        int gr = bm + trow + i;
        if (gr < M) {
#pragma unroll
            for (int j = 0; j < TN; j++) {
                float v = acc[i][j] + bias[tcol + j];
                C[(size_t)gr * D1 + tcol + j] = v > 0.f ? v : expm1f(v);
            }
        }
    }
}

// ----------------------------------------------------------------------------
// Attention coefficients from features: es[n,h] = <h[n,h,:], a_src[h,:]>.
// One warp per (node, head).  (Used for layers 2/3 where features are small.)
// ----------------------------------------------------------------------------
template <int C, int H>
__global__ void esed_kernel(int NN, const float* __restrict__ h,
                            const float* __restrict__ as,
                            const float* __restrict__ ad,
                            float* __restrict__ es, float* __restrict__ ed) {
    int gw = (blockIdx.x * blockDim.x + threadIdx.x) >> 5;
    int lane = threadIdx.x & 31;
    if (gw >= NN * H) return;
    int n = gw / H, hh = gw % H;
    const float* row = h + (size_t)n * (H * C) + hh * C;
    const float* av = as + hh * C;
    const float* dv = ad + hh * C;
    float s = 0.f, d = 0.f;
#pragma unroll
    for (int c = lane; c < C; c += 32) {
        float v = row[c];
        s += v * av[c];
        d += v * dv[c];
    }
#pragma unroll
    for (int off = 16; off > 0; off >>= 1) {
        s += __shfl_down_sync(0xffffffffu, s, off);
        d += __shfl_down_sync(0xffffffffu, d, off);
    }
    if (lane == 0) { es[gw] = s; ed[gw] = d; }
}

// ----------------------------------------------------------------------------
// Output-space aggregation (layers 2/3): out[dst,:] += alpha * h[src,:].
// One warp per edge.  Vector float4 (C=128) / float2 (C=64) atomics.
// ----------------------------------------------------------------------------
template <int C>
__global__ void agg_kernel(int E, int NN, const int* __restrict__ ei,
                           const float* __restrict__ h,
                           const float* __restrict__ w,
                           const float* __restrict__ z,
                           float* __restrict__ out) {
    int gw = (blockIdx.x * blockDim.x + threadIdx.x) >> 5;
    int lane = threadIdx.x & 31;
    int ET = E + NN;
    if (gw >= ET) return;
    int s, d;
    if (gw < E) { s = ei[gw]; d = ei[E + gw]; }
    else        { s = d = gw - E; }
    float alpha = w[gw] / (z[d] + 1e-16f);
    const float* hrow = h + (size_t)s * C;
    float* orow = out + (size_t)d * C;
    if (C == 128) {
        float4 v = reinterpret_cast<const float4*>(hrow)[lane];
        v.x *= alpha; v.y *= alpha; v.z *= alpha; v.w *= alpha;
        atomicAdd(reinterpret_cast<float4*>(orow) + lane, v);
    } else {  // C == 64
        float2 v = reinterpret_cast<const float2*>(hrow)[lane];
        v.x *= alpha; v.y *= alpha;
        atomicAdd(reinterpret_cast<float2*>(orow) + lane, v);
    }
}

// ----------------------------------------------------------------------------
// bias + ELU, in place
// ----------------------------------------------------------------------------
__global__ void bias_elu_kernel(float* __restrict__ a, const float* __restrict__ b,
                                long long total, int W) {
    long long i = (long long)blockIdx.x * blockDim.x + threadIdx.x;
    long long stride = (long long)gridDim.x * blockDim.x;
    for (; i < total; i += stride) {
        float v = a[i] + b[i % W];
        a[i] = v > 0.f ? v : expm1f(v);
    }
}

// ----------------------------------------------------------------------------
// Final: per node, ELU(agg3 + b3) . Wr + br -> sigmoid. One warp per node.
// ----------------------------------------------------------------------------
__global__ void final_kernel(int NN, const float* __restrict__ agg3,
                             const float* __restrict__ b3,
                             const float* __restrict__ Wr,
                             const float* __restrict__ br,
                             float* __restrict__ out) {
    int n = (blockIdx.x * blockDim.x + threadIdx.x) >> 5;
    int lane = threadIdx.x & 31;
    if (n >= NN) return;
    const float* row = agg3 + (size_t)n * D3;
    float acc = 0.f;
#pragma unroll
    for (int j = lane; j < D3; j += 32) {
        float v = row[j] + b3[j];
        v = v > 0.f ? v : expm1f(v);
        acc += v * Wr[j];
    }
#pragma unroll
    for (int off = 16; off > 0; off >>= 1)
        acc += __shfl_down_sync(0xffffffffu, acc, off);
    if (lane == 0)
        out[n] = 1.f / (1.f + expf(-(acc + br[0])));
}

// ----------------------------------------------------------------------------
// Host launcher
// ----------------------------------------------------------------------------
static inline int ceil_div(int a, int b) { return (a + b - 1) / b; }

extern "C" void kernel_launch(void* const* d_in, const int* in_sizes, int n_in,
                              void* d_out, int out_size) {
    const float* x   = (const float*)d_in[0];
    const int*   ei  = (const int*)d_in[1];   // int32 (JAX x64 disabled)
    const float* W1  = (const float*)d_in[2];
    const float* as1 = (const float*)d_in[3];
    const float* ad1 = (const float*)d_in[4];
    const float* b1  = (const float*)d_in[5];
    const float* W2  = (const float*)d_in[6];
    const float* as2 = (const float*)d_in[7];
    const float* ad2 = (const float*)d_in[8];
    const float* b2  = (const float*)d_in[9];
    const float* W3  = (const float*)d_in[10];
    const float* as3 = (const float*)d_in[11];
    const float* ad3 = (const float*)d_in[12];
    const float* b3  = (const float*)d_in[13];
    const float* Wr  = (const float*)d_in[14];
    const float* br  = (const float*)d_in[15];
    float* out = (float*)d_out;

    const int N = in_sizes[0] / F_IN;
    const int E = in_sizes[1] / 2;
    const int ET = E + N;

    float *aggX, *agg1, *h2, *agg2, *h3, *agg3;
    float *qs1, *qd1;
    float *es1, *ed1, *z1, *es2, *ed2, *z2, *es3, *ed3, *z3, *w1, *w2, *w3;
    cudaGetSymbolAddress((void**)&aggX, g_aggX);
    cudaGetSymbolAddress((void**)&agg1, g_agg1);
    cudaGetSymbolAddress((void**)&h2, g_h2);
    cudaGetSymbolAddress((void**)&agg2, g_agg2);
    cudaGetSymbolAddress((void**)&h3, g_h3);
    cudaGetSymbolAddress((void**)&agg3, g_agg3);
    cudaGetSymbolAddress((void**)&qs1, g_qs1);
    cudaGetSymbolAddress((void**)&qd1, g_qd1);
    cudaGetSymbolAddress((void**)&es1, g_es1);
    cudaGetSymbolAddress((void**)&ed1, g_ed1);
    cudaGetSymbolAddress((void**)&z1, g_z1);
    cudaGetSymbolAddress((void**)&es2, g_es2);
    cudaGetSymbolAddress((void**)&ed2, g_ed2);
    cudaGetSymbolAddress((void**)&z2, g_z2);
    cudaGetSymbolAddress((void**)&es3, g_es3);
    cudaGetSymbolAddress((void**)&ed3, g_ed3);
    cudaGetSymbolAddress((void**)&z3, g_z3);
    cudaGetSymbolAddress((void**)&w1, g_w1);
    cudaGetSymbolAddress((void**)&w2, g_w2);
    cudaGetSymbolAddress((void**)&w3, g_w3);

    // zero accumulators
    cudaMemsetAsync(aggX, 0, (size_t)N * XH * sizeof(float));
    cudaMemsetAsync(agg2, 0, (size_t)N * D2 * sizeof(float));
    cudaMemsetAsync(agg3, 0, (size_t)N * D3 * sizeof(float));
    cudaMemsetAsync(z1, 0, (size_t)N * H1 * sizeof(float));
    cudaMemsetAsync(z2, 0, (size_t)N * sizeof(float));
    cudaMemsetAsync(z3, 0, (size_t)N * sizeof(float));

    // ---------------- Layer 1 (x-space aggregation; h1 never materialized) --
    proj1_kernel<<<ceil_div(H1 * F_IN * 32, 256), 256>>>(W1, as1, ad1, qs1, qd1);
    esed1_kernel<<<ceil_div(N, 32), 256>>>(N, x, qs1, qd1, es1, ed1);
    edgew_kernel<H1><<<ceil_div(ET * H1, 256), 256>>>(E, N, ei, es1, ed1, w1, z1);
    aggx_kernel<<<ceil_div(ET * 32, 256), 256>>>(E, N, ei, x, w1, z1, aggX);
    {
        dim3 grid(1, ceil_div(N, 128), H1);
        head_gemm_bias_elu<<<grid, 256>>>(N, aggX, W1, b1, agg1);
    }

    // ---------------- Layer 2: 1024 -> 128 ----------------
    {
        dim3 grid(1, ceil_div(N, 128));
        sgemm_kernel<128, 128, 16, 8, 8><<<grid, 256>>>(N, D2, D1, agg1, W2, h2);
    }
    esed_kernel<D2, 1><<<ceil_div(N * 32, 256), 256>>>(N, h2, as2, ad2, es2, ed2);
    edgew_kernel<1><<<ceil_div(ET, 256), 256>>>(E, N, ei, es2, ed2, w2, z2);
    agg_kernel<D2><<<ceil_div(ET * 32, 256), 256>>>(E, N, ei, h2, w2, z2, agg2);
    bias_elu_kernel<<<1024, 256>>>(agg2, b2, (long long)N * D2, D2);

    // ---------------- Layer 3: 128 -> 64 ----------------
    {
        dim3 grid(1, ceil_div(N, 64));
        sgemm_kernel<64, 64, 16, 4, 4><<<grid, 256>>>(N, D3, D2, agg2, W3, h3);
    }
    esed_kernel<D3, 1><<<ceil_div(N * 32, 256), 256>>>(N, h3, as3, ad3, es3, ed3);
    edgew_kernel<1><<<ceil_div(ET, 256), 256>>>(E, N, ei, es3, ed3, w3, z3);
    agg_kernel<D3><<<ceil_div(ET * 32, 256), 256>>>(E, N, ei, h3, w3, z3, agg3);

    // ---------------- Regressor (fused bias+ELU+dot+sigmoid) ----------------
    final_kernel<<<ceil_div(N * 32, 256), 256>>>(N, agg3, b3, Wr, br, out);
}

// round 9
// speedup vs baseline: 1.5206x; 1.0841x over previous
#include <cuda_runtime.h>
#include <cuda_bf16.h>
#include <cstdint>
#include <math.h>

// ----------------------------------------------------------------------------
// Problem constants (shapes fixed by the reference)
// ----------------------------------------------------------------------------
#define MAXN 50000
#define MAXE 200000
#define F_IN 66
#define H1 8
#define C1 128
#define D1 (H1 * C1)   // 1024
#define D2 128
#define D3 64
#define XH (H1 * F_IN) // 528 : per-node width of x-space aggregation buffer

// ----------------------------------------------------------------------------
// Device scratch (static globals: allocation-free)
// ----------------------------------------------------------------------------
__device__ float g_aggX[(size_t)MAXN * XH];   // layer-1 x-space aggregation
__device__ float g_agg1[(size_t)MAXN * D1];   // layer-1 output (post bias+ELU)
__device__ float g_h2[(size_t)MAXN * D2];
__device__ float g_agg2[(size_t)MAXN * D2];
__device__ float g_h3[(size_t)MAXN * D3];
__device__ float g_agg3[(size_t)MAXN * D3];

__device__ float g_qs1[H1 * F_IN], g_qd1[H1 * F_IN];  // W1-projected attention vecs
__device__ float g_es1[MAXN * H1], g_ed1[MAXN * H1], g_z1[MAXN * H1];
__device__ float g_es2[MAXN], g_ed2[MAXN], g_z2[MAXN];
__device__ float g_es3[MAXN], g_ed3[MAXN], g_z3[MAXN];
__device__ float g_w1[(size_t)(MAXE + MAXN) * H1];
__device__ float g_w2[(MAXE + MAXN)];
__device__ float g_w3[(MAXE + MAXN)];

// ----------------------------------------------------------------------------
// TF32 tensor-core GEMM: C[M,N] = A[M,K] @ B[K,N] via mma.sync m16n8k8.
// blockIdx.z selects a slice (per-head block-diagonal GEMM): pointers advance
// by strideAz/strideBz/strideCz elements per z.
// Optional fused bias + ELU epilogue.
// Swizzled As[k][m] layout: column (m&~7)|((m+(k>>2))&7) is conflict-free for
// both the transposing global->smem store and the m16n8k8 fragment loads.
// ----------------------------------------------------------------------------
template <int BM, int BN, int BK, int WM, int WN, bool BIAS_ELU>
__global__ void tf32_gemm_kernel(int M, int N, int K,
        const float* __restrict__ A, int lda, long long strideAz,
        const float* __restrict__ B, int ldb, long long strideBz,
        float* __restrict__ C, int ldc, long long strideCz,
        const float* __restrict__ bias) {
    constexpr int WARPS_M = BM / WM, WARPS_N = BN / WN;
    constexpr int NT = 32 * WARPS_M * WARPS_N;
    constexpr int MI = WM / 16, NI = WN / 8;

    __shared__ uint32_t As[BK][BM + 8];
    __shared__ uint32_t Bs[BK][BN + 8];

    const int tid = threadIdx.x;
    const int wid = tid >> 5, lane = tid & 31;
    const int l4 = lane & 3, l8 = lane >> 2;
    const int wm = (wid / WARPS_N) * WM;
    const int wn = (wid % WARPS_N) * WN;
    const int bm = blockIdx.y * BM;
    const int bn = blockIdx.x * BN;

    A += (long long)blockIdx.z * strideAz;
    B += (long long)blockIdx.z * strideBz;
    C += (long long)blockIdx.z * strideCz;
    if (BIAS_ELU) bias += (long long)blockIdx.z * (long long)N;

    float acc[MI][NI][4];
#pragma unroll
    for (int i = 0; i < MI; i++)
#pragma unroll
        for (int j = 0; j < NI; j++)
#pragma unroll
            for (int q = 0; q < 4; q++) acc[i][j][q] = 0.f;

    for (int k0 = 0; k0 < K; k0 += BK) {
        // A tile (BM x BK), coalesced read, transposed + swizzled store (tf32)
#pragma unroll
        for (int i = tid; i < BM * BK; i += NT) {
            int r = i / BK, c = i % BK;
            int gm = bm + r, gk = k0 + c;
            float v = (gm < M && gk < K) ? A[(size_t)gm * lda + gk] : 0.f;
            uint32_t u; asm("cvt.rna.tf32.f32 %0, %1;" : "=r"(u) : "f"(v));
            As[c][(r & ~7) | ((r + (c >> 2)) & 7)] = u;
        }
        // B tile (BK x BN), natural layout
#pragma unroll
        for (int i = tid; i < BK * BN; i += NT) {
            int r = i / BN, c = i % BN;
            int gk = k0 + r;
            float v = (gk < K) ? B[(size_t)gk * ldb + bn + c] : 0.f;
            uint32_t u; asm("cvt.rna.tf32.f32 %0, %1;" : "=r"(u) : "f"(v));
            Bs[r][c] = u;
        }
        __syncthreads();

#pragma unroll
        for (int kk = 0; kk < BK; kk += 8) {
            uint32_t bfr[NI][2];
#pragma unroll
            for (int ni = 0; ni < NI; ni++) {
                bfr[ni][0] = Bs[kk + l4][wn + ni * 8 + l8];
                bfr[ni][1] = Bs[kk + l4 + 4][wn + ni * 8 + l8];
            }
#pragma unroll
            for (int mi = 0; mi < MI; mi++) {
                const int m0 = wm + mi * 16 + l8;
                const int m1 = m0 + 8;
                const int ka = kk + l4;      // a0/a1
                const int kb = ka + 4;       // a2/a3
                uint32_t a0 = As[ka][(m0 & ~7) | ((m0 + (ka >> 2)) & 7)];
                uint32_t a1 = As[ka][(m1 & ~7) | ((m1 + (ka >> 2)) & 7)];
                uint32_t a2 = As[kb][(m0 & ~7) | ((m0 + (kb >> 2)) & 7)];
                uint32_t a3 = As[kb][(m1 & ~7) | ((m1 + (kb >> 2)) & 7)];
#pragma unroll
                for (int ni = 0; ni < NI; ni++) {
                    asm volatile(
                        "mma.sync.aligned.m16n8k8.row.col.f32.tf32.tf32.f32 "
                        "{%0,%1,%2,%3}, {%4,%5,%6,%7}, {%8,%9}, {%0,%1,%2,%3};"
                        : "+f"(acc[mi][ni][0]), "+f"(acc[mi][ni][1]),
                          "+f"(acc[mi][ni][2]), "+f"(acc[mi][ni][3])
                        : "r"(a0), "r"(a1), "r"(a2), "r"(a3),
                          "r"(bfr[ni][0]), "r"(bfr[ni][1]));
                }
            }
        }
        __syncthreads();
    }

    // epilogue
#pragma unroll
    for (int mi = 0; mi < MI; mi++) {
        int r0 = bm + wm + mi * 16 + l8;
#pragma unroll
        for (int ni = 0; ni < NI; ni++) {
            int c0 = bn + wn + ni * 8 + l4 * 2;
#pragma unroll
            for (int q = 0; q < 4; q++) {
                int gr = r0 + ((q >= 2) ? 8 : 0);
                int gc = c0 + (q & 1);
                if (gr < M) {
                    float v = acc[mi][ni][q];
                    if (BIAS_ELU) {
                        v += bias[gc];
                        v = v > 0.f ? v : expm1f(v);
                    }
                    C[(size_t)gr * ldc + gc] = v;
                }
            }
        }
    }
}

// ----------------------------------------------------------------------------
// Layer-1 attention vector projection: qs[h,k] = sum_c W1[k, h*128+c]*as1[h,c]
// ----------------------------------------------------------------------------
__global__ void proj1_kernel(const float* __restrict__ W1,
                             const float* __restrict__ as1,
                             const float* __restrict__ ad1,
                             float* __restrict__ qs, float* __restrict__ qd) {
    int gw = (blockIdx.x * blockDim.x + threadIdx.x) >> 5;
    int lane = threadIdx.x & 31;
    if (gw >= H1 * F_IN) return;
    int h = gw / F_IN, k = gw % F_IN;
    const float* wrow = W1 + (size_t)k * D1 + h * C1;
    const float* av = as1 + h * C1;
    const float* dv = ad1 + h * C1;
    float s = 0.f, d = 0.f;
#pragma unroll
    for (int c = lane; c < C1; c += 32) {
        float wv = wrow[c];
        s += wv * av[c];
        d += wv * dv[c];
    }
#pragma unroll
    for (int off = 16; off > 0; off >>= 1) {
        s += __shfl_down_sync(0xffffffffu, s, off);
        d += __shfl_down_sync(0xffffffffu, d, off);
    }
    if (lane == 0) { qs[gw] = s; qd[gw] = d; }
}

// ----------------------------------------------------------------------------
// Layer-1 es/ed directly from x: es[n,h] = <x[n,:], qs[h,:]> (K = 66).
// ----------------------------------------------------------------------------
__global__ void esed1_kernel(int NN, const float* __restrict__ x,
                             const float* __restrict__ qs,
                             const float* __restrict__ qd,
                             float* __restrict__ es, float* __restrict__ ed) {
    __shared__ float xs[32][F_IN + 2];
    __shared__ float qss[H1 * F_IN], qds[H1 * F_IN];
    int tid = threadIdx.x;
    for (int i = tid; i < H1 * F_IN; i += 256) { qss[i] = qs[i]; qds[i] = qd[i]; }
    int n0 = blockIdx.x * 32;
    for (int i = tid; i < 32 * F_IN; i += 256) {
        int r = i / F_IN, c = i % F_IN;
        int n = n0 + r;
        xs[r][c] = (n < NN) ? x[(size_t)n * F_IN + c] : 0.f;
    }
    __syncthreads();
    int r = tid >> 3, h = tid & 7;
    int n = n0 + r;
    if (n < NN) {
        float s = 0.f, d = 0.f;
#pragma unroll
        for (int k = 0; k < F_IN; k++) {
            float xv = xs[r][k];
            s += xv * qss[h * F_IN + k];
            d += xv * qds[h * F_IN + k];
        }
        es[n * H1 + h] = s;
        ed[n * H1 + h] = d;
    }
}

// ----------------------------------------------------------------------------
// Edge logits: w = exp(leaky_relu(es[src]+ed[dst])); z[dst] += w (atomic).
// ----------------------------------------------------------------------------
template <int H>
__global__ void edgew_kernel(int E, int NN, const int* __restrict__ ei,
                             const float* __restrict__ es,
                             const float* __restrict__ ed,
                             float* __restrict__ w, float* __restrict__ z) {
    int idx = blockIdx.x * blockDim.x + threadIdx.x;
    int tot = (E + NN) * H;
    if (idx >= tot) return;
    int e = idx / H, hh = idx - e * H;
    int s, d;
    if (e < E) { s = ei[e]; d = ei[E + e]; }
    else       { s = d = e - E; }
    float v = es[(size_t)s * H + hh] + ed[(size_t)d * H + hh];
    v = v > 0.f ? v : 0.2f * v;      // leaky relu, slope 0.2
    float wv = expf(v);
    w[idx] = wv;
    atomicAdd(&z[(size_t)d * H + hh], wv);
}

// ----------------------------------------------------------------------------
// Layer-1 x-space aggregation: aggX[d, h, 0:66] += alpha_eh * x[s, 0:66].
// ----------------------------------------------------------------------------
__global__ void aggx_kernel(int E, int NN, const int* __restrict__ ei,
                            const float* __restrict__ x,
                            const float* __restrict__ w,
                            const float* __restrict__ z,
                            float* __restrict__ aggX) {
    int gw = (blockIdx.x * blockDim.x + threadIdx.x) >> 5;
    int lane = threadIdx.x & 31;
    int ET = E + NN;
    if (gw >= ET) return;
    int s, d;
    if (gw < E) { s = ei[gw]; d = ei[E + gw]; }
    else        { s = d = gw - E; }
    const float2* xr = reinterpret_cast<const float2*>(x + (size_t)s * F_IN);
    float2 v0 = xr[lane];
    float2 v1 = (lane == 0) ? xr[32] : make_float2(0.f, 0.f);
    const float* wrow = w + (size_t)gw * H1;
    const float* zrow = z + (size_t)d * H1;
    float* obase = aggX + (size_t)d * XH;
#pragma unroll
    for (int h = 0; h < H1; h++) {
        float alpha = wrow[h] / (zrow[h] + 1e-16f);
        float2* o2 = reinterpret_cast<float2*>(obase + h * F_IN);
        atomicAdd(o2 + lane, make_float2(v0.x * alpha, v0.y * alpha));
        if (lane == 0)
            atomicAdd(o2 + 32, make_float2(v1.x * alpha, v1.y * alpha));
    }
}

// ----------------------------------------------------------------------------
// Attention coefficients from features (layers 2/3): one warp per (node,head).
// ----------------------------------------------------------------------------
template <int C, int H>
__global__ void esed_kernel(int NN, const float* __restrict__ h,
                            const float* __restrict__ as,
                            const float* __restrict__ ad,
                            float* __restrict__ es, float* __restrict__ ed) {
    int gw = (blockIdx.x * blockDim.x + threadIdx.x) >> 5;
    int lane = threadIdx.x & 31;
    if (gw >= NN * H) return;
    int n = gw / H, hh = gw % H;
    const float* row = h + (size_t)n * (H * C) + hh * C;
    const float* av = as + hh * C;
    const float* dv = ad + hh * C;
    float s = 0.f, d = 0.f;
#pragma unroll
    for (int c = lane; c < C; c += 32) {
        float v = row[c];
        s += v * av[c];
        d += v * dv[c];
    }
#pragma unroll
    for (int off = 16; off > 0; off >>= 1) {
        s += __shfl_down_sync(0xffffffffu, s, off);
        d += __shfl_down_sync(0xffffffffu, d, off);
    }
    if (lane == 0) { es[gw] = s; ed[gw] = d; }
}

// ----------------------------------------------------------------------------
// Output-space aggregation (layers 2/3): out[dst,:] += alpha * h[src,:].
// ----------------------------------------------------------------------------
template <int C>
__global__ void agg_kernel(int E, int NN, const int* __restrict__ ei,
                           const float* __restrict__ h,
                           const float* __restrict__ w,
                           const float* __restrict__ z,
                           float* __restrict__ out) {
    int gw = (blockIdx.x * blockDim.x + threadIdx.x) >> 5;
    int lane = threadIdx.x & 31;
    int ET = E + NN;
    if (gw >= ET) return;
    int s, d;
    if (gw < E) { s = ei[gw]; d = ei[E + gw]; }
    else        { s = d = gw - E; }
    float alpha = w[gw] / (z[d] + 1e-16f);
    const float* hrow = h + (size_t)s * C;
    float* orow = out + (size_t)d * C;
    if (C == 128) {
        float4 v = reinterpret_cast<const float4*>(hrow)[lane];
        v.x *= alpha; v.y *= alpha; v.z *= alpha; v.w *= alpha;
        atomicAdd(reinterpret_cast<float4*>(orow) + lane, v);
    } else {  // C == 64
        float2 v = reinterpret_cast<const float2*>(hrow)[lane];
        v.x *= alpha; v.y *= alpha;
        atomicAdd(reinterpret_cast<float2*>(orow) + lane, v);
    }
}

// ----------------------------------------------------------------------------
// bias + ELU, in place
// ----------------------------------------------------------------------------
__global__ void bias_elu_kernel(float* __restrict__ a, const float* __restrict__ b,
                                long long total, int W) {
    long long i = (long long)blockIdx.x * blockDim.x + threadIdx.x;
    long long stride = (long long)gridDim.x * blockDim.x;
    for (; i < total; i += stride) {
        float v = a[i] + b[i % W];
        a[i] = v > 0.f ? v : expm1f(v);
    }
}

// ----------------------------------------------------------------------------
// Final: per node, ELU(agg3 + b3) . Wr + br -> sigmoid. One warp per node.
// ----------------------------------------------------------------------------
__global__ void final_kernel(int NN, const float* __restrict__ agg3,
                             const float* __restrict__ b3,
                             const float* __restrict__ Wr,
                             const float* __restrict__ br,
                             float* __restrict__ out) {
    int n = (blockIdx.x * blockDim.x + threadIdx.x) >> 5;
    int lane = threadIdx.x & 31;
    if (n >= NN) return;
    const float* row = agg3 + (size_t)n * D3;
    float acc = 0.f;
#pragma unroll
    for (int j = lane; j < D3; j += 32) {
        float v = row[j] + b3[j];
        v = v > 0.f ? v : expm1f(v);
        acc += v * Wr[j];
    }
#pragma unroll
    for (int off = 16; off > 0; off >>= 1)
        acc += __shfl_down_sync(0xffffffffu, acc, off);
    if (lane == 0)
        out[n] = 1.f / (1.f + expf(-(acc + br[0])));
}

// ----------------------------------------------------------------------------
// Host launcher
// ----------------------------------------------------------------------------
static inline int ceil_div(int a, int b) { return (a + b - 1) / b; }

extern "C" void kernel_launch(void* const* d_in, const int* in_sizes, int n_in,
                              void* d_out, int out_size) {
    const float* x   = (const float*)d_in[0];
    const int*   ei  = (const int*)d_in[1];   // int32 (JAX x64 disabled)
    const float* W1  = (const float*)d_in[2];
    const float* as1 = (const float*)d_in[3];
    const float* ad1 = (const float*)d_in[4];
    const float* b1  = (const float*)d_in[5];
    const float* W2  = (const float*)d_in[6];
    const float* as2 = (const float*)d_in[7];
    const float* ad2 = (const float*)d_in[8];
    const float* b2  = (const float*)d_in[9];
    const float* W3  = (const float*)d_in[10];
    const float* as3 = (const float*)d_in[11];
    const float* ad3 = (const float*)d_in[12];
    const float* b3  = (const float*)d_in[13];
    const float* Wr  = (const float*)d_in[14];
    const float* br  = (const float*)d_in[15];
    float* out = (float*)d_out;

    const int N = in_sizes[0] / F_IN;
    const int E = in_sizes[1] / 2;
    const int ET = E + N;

    float *aggX, *agg1, *h2, *agg2, *h3, *agg3;
    float *qs1, *qd1;
    float *es1, *ed1, *z1, *es2, *ed2, *z2, *es3, *ed3, *z3, *w1, *w2, *w3;
    cudaGetSymbolAddress((void**)&aggX, g_aggX);
    cudaGetSymbolAddress((void**)&agg1, g_agg1);
    cudaGetSymbolAddress((void**)&h2, g_h2);
    cudaGetSymbolAddress((void**)&agg2, g_agg2);
    cudaGetSymbolAddress((void**)&h3, g_h3);
    cudaGetSymbolAddress((void**)&agg3, g_agg3);
    cudaGetSymbolAddress((void**)&qs1, g_qs1);
    cudaGetSymbolAddress((void**)&qd1, g_qd1);
    cudaGetSymbolAddress((void**)&es1, g_es1);
    cudaGetSymbolAddress((void**)&ed1, g_ed1);
    cudaGetSymbolAddress((void**)&z1, g_z1);
    cudaGetSymbolAddress((void**)&es2, g_es2);
    cudaGetSymbolAddress((void**)&ed2, g_ed2);
    cudaGetSymbolAddress((void**)&z2, g_z2);
    cudaGetSymbolAddress((void**)&es3, g_es3);
    cudaGetSymbolAddress((void**)&ed3, g_ed3);
    cudaGetSymbolAddress((void**)&z3, g_z3);
    cudaGetSymbolAddress((void**)&w1, g_w1);
    cudaGetSymbolAddress((void**)&w2, g_w2);
    cudaGetSymbolAddress((void**)&w3, g_w3);

    // zero accumulators
    cudaMemsetAsync(aggX, 0, (size_t)N * XH * sizeof(float));
    cudaMemsetAsync(agg2, 0, (size_t)N * D2 * sizeof(float));
    cudaMemsetAsync(agg3, 0, (size_t)N * D3 * sizeof(float));
    cudaMemsetAsync(z1, 0, (size_t)N * H1 * sizeof(float));
    cudaMemsetAsync(z2, 0, (size_t)N * sizeof(float));
    cudaMemsetAsync(z3, 0, (size_t)N * sizeof(float));

    // ---------------- Layer 1 (x-space aggregation; h1 never materialized) --
    proj1_kernel<<<ceil_div(H1 * F_IN * 32, 256), 256>>>(W1, as1, ad1, qs1, qd1);
    esed1_kernel<<<ceil_div(N, 32), 256>>>(N, x, qs1, qd1, es1, ed1);
    edgew_kernel<H1><<<ceil_div(ET * H1, 256), 256>>>(E, N, ei, es1, ed1, w1, z1);
    aggx_kernel<<<ceil_div(ET * 32, 256), 256>>>(E, N, ei, x, w1, z1, aggX);
    {
        // per-head block-diagonal GEMM with fused bias+ELU (tf32 tensor cores)
        dim3 grid(1, ceil_div(N, 128), H1);
        tf32_gemm_kernel<128, 128, 32, 64, 32, true><<<grid, 256>>>(
            N, C1, F_IN,
            aggX, XH, (long long)F_IN,
            W1, D1, (long long)C1,
            agg1, D1, (long long)C1,
            b1);
    }

    // ---------------- Layer 2: 1024 -> 128 (tf32 tensor cores) --------------
    {
        dim3 grid(1, ceil_div(N, 128), 1);
        tf32_gemm_kernel<128, 128, 32, 64, 32, false><<<grid, 256>>>(
            N, D2, D1, agg1, D1, 0, W2, D2, 0, h2, D2, 0, nullptr);
    }
    esed_kernel<D2, 1><<<ceil_div(N * 32, 256), 256>>>(N, h2, as2, ad2, es2, ed2);
    edgew_kernel<1><<<ceil_div(ET, 256), 256>>>(E, N, ei, es2, ed2, w2, z2);
    agg_kernel<D2><<<ceil_div(ET * 32, 256), 256>>>(E, N, ei, h2, w2, z2, agg2);
    bias_elu_kernel<<<1024, 256>>>(agg2, b2, (long long)N * D2, D2);

    // ---------------- Layer 3: 128 -> 64 (tf32 tensor cores) ----------------
    {
        dim3 grid(1, ceil_div(N, 128), 1);
        tf32_gemm_kernel<128, 64, 32, 64, 32, false><<<grid, 128>>>(
            N, D3, D2, agg2, D2, 0, W3, D3, 0, h3, D3, 0, nullptr);
    }
    esed_kernel<D3, 1><<<ceil_div(N * 32, 256), 256>>>(N, h3, as3, ad3, es3, ed3);
    edgew_kernel<1><<<ceil_div(ET, 256), 256>>>(E, N, ei, es3, ed3, w3, z3);
    agg_kernel<D3><<<ceil_div(ET * 32, 256), 256>>>(E, N, ei, h3, w3, z3, agg3);

    // ---------------- Regressor (fused bias+ELU+dot+sigmoid) ----------------
    final_kernel<<<ceil_div(N * 32, 256), 256>>>(N, agg3, b3, Wr, br, out);
}

// round 10
// speedup vs baseline: 2.4294x; 1.5976x over previous
#include <cuda_runtime.h>
#include <cuda_bf16.h>
#include <cstdint>
#include <math.h>

// ----------------------------------------------------------------------------
// Problem constants (shapes fixed by the reference)
// ----------------------------------------------------------------------------
#define MAXN 50000
#define MAXE 200000
#define F_IN 66
#define H1 8
#define C1 128
#define D1 (H1 * C1)   // 1024
#define D2 128
#define D3 64
#define XH (H1 * F_IN) // 528 : per-node width of x-space aggregation buffer

// ----------------------------------------------------------------------------
// Device scratch (static globals: allocation-free)
// One contiguous zero-initialized region -> single memset per launch.
// Layout: aggX | z1 | agg2 | z2 | agg3 | z3
// ----------------------------------------------------------------------------
#define ZW (XH + H1 + D2 + 1 + D3 + 1)   // 730 floats per node
__device__ float g_zero[(size_t)MAXN * ZW];

__device__ float g_agg1[(size_t)MAXN * D1];   // layer-1 output (post bias+ELU)
__device__ float g_h2[(size_t)MAXN * D2];
__device__ float g_h3[(size_t)MAXN * D3];

__device__ float g_qs1[H1 * F_IN], g_qd1[H1 * F_IN];  // W1-projected attention vecs
__device__ float g_es1[MAXN * H1], g_ed1[MAXN * H1];
__device__ float g_es2[MAXN], g_ed2[MAXN];
__device__ float g_es3[MAXN], g_ed3[MAXN];
__device__ float g_w1[(size_t)(MAXE + MAXN) * H1];
__device__ float g_w2[(MAXE + MAXN)];
__device__ float g_w3[(MAXE + MAXN)];

// ----------------------------------------------------------------------------
// cp.async helpers
// ----------------------------------------------------------------------------
__device__ __forceinline__ void cp_async16(uint32_t smem_dst, const void* gsrc, int sz) {
    asm volatile("cp.async.cg.shared.global [%0], [%1], 16, %2;\n"
                 :: "r"(smem_dst), "l"(gsrc), "r"(sz));
}
__device__ __forceinline__ void cp_commit() {
    asm volatile("cp.async.commit_group;\n");
}
template <int NG>
__device__ __forceinline__ void cp_wait() {
    asm volatile("cp.async.wait_group %0;\n" :: "n"(NG));
}

// ----------------------------------------------------------------------------
// 2-stage cp.async pipelined TF32 GEMM: C[M,N] = A[M,K] @ B[K,N].
// Requires: K % BK == 0, N == BN * gridDim.x (grid.x=1 used here), lda % 4 == 0.
// Raw fp32 bits fed to tf32 mma (truncation; CUTLASS fast path).
// As[m][k] stride AS=BK+4 and Bs[k][n] stride BS=BN+8: conflict-free for both
// the 16B cp.async stores and the m16n8k8 fragment loads (checked mod 32).
// ----------------------------------------------------------------------------
template <int BM, int BN, int BK, int WM, int WN>
__global__ void tf32_gemm_pipe_kernel(int M, int N, int K,
        const float* __restrict__ A, int lda,
        const float* __restrict__ B, int ldb,
        float* __restrict__ C, int ldc) {
    constexpr int WARPS_M = BM / WM, WARPS_N = BN / WN;
    constexpr int NT = 32 * WARPS_M * WARPS_N;
    constexpr int MI = WM / 16, NI = WN / 8;
    constexpr int AS = BK + 4;
    constexpr int BS = BN + 8;
    constexpr int A_CHUNKS = BM * (BK / 4);
    constexpr int B_CHUNKS = BK * (BN / 4);

    __shared__ float Asm[2][BM][AS];
    __shared__ float Bsm[2][BK][BS];

    const int tid = threadIdx.x;
    const int wid = tid >> 5, lane = tid & 31;
    const int l4 = lane & 3, l8 = lane >> 2;
    const int wm = (wid / WARPS_N) * WM;
    const int wn = (wid % WARPS_N) * WN;
    const int bm = blockIdx.y * BM;

    float acc[MI][NI][4];
#pragma unroll
    for (int i = 0; i < MI; i++)
#pragma unroll
        for (int j = 0; j < NI; j++)
#pragma unroll
            for (int q = 0; q < 4; q++) acc[i][j][q] = 0.f;

    const uint32_t a_base = (uint32_t)__cvta_generic_to_shared(&Asm[0][0][0]);
    const uint32_t b_base = (uint32_t)__cvta_generic_to_shared(&Bsm[0][0][0]);
    constexpr uint32_t A_STAGE = BM * AS * 4;
    constexpr uint32_t B_STAGE = BK * BS * 4;

    auto issue = [&](int s, int k0) {
#pragma unroll
        for (int j = tid; j < A_CHUNKS; j += NT) {
            int m = j / (BK / 4), cq = j % (BK / 4);
            int gm = bm + m;
            const float* src = A + (size_t)gm * lda + k0 + 4 * cq;
            uint32_t dst = a_base + s * A_STAGE + (m * AS + 4 * cq) * 4;
            cp_async16(dst, src, gm < M ? 16 : 0);
        }
#pragma unroll
        for (int j = tid; j < B_CHUNKS; j += NT) {
            int r = j / (BN / 4), cq = j % (BN / 4);
            const float* src = B + (size_t)(k0 + r) * ldb + 4 * cq;
            uint32_t dst = b_base + s * B_STAGE + (r * BS + 4 * cq) * 4;
            cp_async16(dst, src, 16);
        }
        cp_commit();
    };

    const int KT = K / BK;
    issue(0, 0);

    for (int t = 0; t < KT; t++) {
        if (t + 1 < KT) {
            issue((t + 1) & 1, (t + 1) * BK);
            cp_wait<1>();
        } else {
            cp_wait<0>();
        }
        __syncthreads();
        const int s = t & 1;

#pragma unroll
        for (int kk = 0; kk < BK; kk += 8) {
            uint32_t bfr[NI][2];
#pragma unroll
            for (int ni = 0; ni < NI; ni++) {
                bfr[ni][0] = __float_as_uint(Bsm[s][kk + l4][wn + ni * 8 + l8]);
                bfr[ni][1] = __float_as_uint(Bsm[s][kk + l4 + 4][wn + ni * 8 + l8]);
            }
#pragma unroll
            for (int mi = 0; mi < MI; mi++) {
                const int m0 = wm + mi * 16 + l8;
                const int m1 = m0 + 8;
                uint32_t a0 = __float_as_uint(Asm[s][m0][kk + l4]);
                uint32_t a1 = __float_as_uint(Asm[s][m1][kk + l4]);
                uint32_t a2 = __float_as_uint(Asm[s][m0][kk + l4 + 4]);
                uint32_t a3 = __float_as_uint(Asm[s][m1][kk + l4 + 4]);
#pragma unroll
                for (int ni = 0; ni < NI; ni++) {
                    asm volatile(
                        "mma.sync.aligned.m16n8k8.row.col.f32.tf32.tf32.f32 "
                        "{%0,%1,%2,%3}, {%4,%5,%6,%7}, {%8,%9}, {%0,%1,%2,%3};"
                        : "+f"(acc[mi][ni][0]), "+f"(acc[mi][ni][1]),
                          "+f"(acc[mi][ni][2]), "+f"(acc[mi][ni][3])
                        : "r"(a0), "r"(a1), "r"(a2), "r"(a3),
                          "r"(bfr[ni][0]), "r"(bfr[ni][1]));
                }
            }
        }
        __syncthreads();
    }

#pragma unroll
    for (int mi = 0; mi < MI; mi++) {
        int r0 = bm + wm + mi * 16 + l8;
#pragma unroll
        for (int ni = 0; ni < NI; ni++) {
            int c0 = wn + ni * 8 + l4 * 2;
#pragma unroll
            for (int q = 0; q < 4; q++) {
                int gr = r0 + ((q >= 2) ? 8 : 0);
                int gc = c0 + (q & 1);
                if (gr < M) C[(size_t)gr * ldc + gc] = acc[mi][ni][q];
            }
        }
    }
}

// ----------------------------------------------------------------------------
// Single-stage TF32 GEMM (kept for the K=66 head GEMM; handles K tails).
// Swizzled As[k][m]: col (m&~7)|((m+(k>>2))&7) conflict-free for store+load.
// blockIdx.z = head slice; fused bias+ELU epilogue.
// ----------------------------------------------------------------------------
template <int BM, int BN, int BK, int WM, int WN, bool BIAS_ELU>
__global__ void tf32_gemm_kernel(int M, int N, int K,
        const float* __restrict__ A, int lda, long long strideAz,
        const float* __restrict__ B, int ldb, long long strideBz,
        float* __restrict__ C, int ldc, long long strideCz,
        const float* __restrict__ bias) {
    constexpr int WARPS_M = BM / WM, WARPS_N = BN / WN;
    constexpr int NT = 32 * WARPS_M * WARPS_N;
    constexpr int MI = WM / 16, NI = WN / 8;

    __shared__ uint32_t As[BK][BM + 8];
    __shared__ uint32_t Bs[BK][BN + 8];

    const int tid = threadIdx.x;
    const int wid = tid >> 5, lane = tid & 31;
    const int l4 = lane & 3, l8 = lane >> 2;
    const int wm = (wid / WARPS_N) * WM;
    const int wn = (wid % WARPS_N) * WN;
    const int bm = blockIdx.y * BM;
    const int bn = blockIdx.x * BN;

    A += (long long)blockIdx.z * strideAz;
    B += (long long)blockIdx.z * strideBz;
    C += (long long)blockIdx.z * strideCz;
    if (BIAS_ELU) bias += (long long)blockIdx.z * (long long)N;

    float acc[MI][NI][4];
#pragma unroll
    for (int i = 0; i < MI; i++)
#pragma unroll
        for (int j = 0; j < NI; j++)
#pragma unroll
            for (int q = 0; q < 4; q++) acc[i][j][q] = 0.f;

    for (int k0 = 0; k0 < K; k0 += BK) {
#pragma unroll
        for (int i = tid; i < BM * BK; i += NT) {
            int r = i / BK, c = i % BK;
            int gm = bm + r, gk = k0 + c;
            float v = (gm < M && gk < K) ? A[(size_t)gm * lda + gk] : 0.f;
            uint32_t u; asm("cvt.rna.tf32.f32 %0, %1;" : "=r"(u) : "f"(v));
            As[c][(r & ~7) | ((r + (c >> 2)) & 7)] = u;
        }
#pragma unroll
        for (int i = tid; i < BK * BN; i += NT) {
            int r = i / BN, c = i % BN;
            int gk = k0 + r;
            float v = (gk < K) ? B[(size_t)gk * ldb + bn + c] : 0.f;
            uint32_t u; asm("cvt.rna.tf32.f32 %0, %1;" : "=r"(u) : "f"(v));
            Bs[r][c] = u;
        }
        __syncthreads();

#pragma unroll
        for (int kk = 0; kk < BK; kk += 8) {
            uint32_t bfr[NI][2];
#pragma unroll
            for (int ni = 0; ni < NI; ni++) {
                bfr[ni][0] = Bs[kk + l4][wn + ni * 8 + l8];
                bfr[ni][1] = Bs[kk + l4 + 4][wn + ni * 8 + l8];
            }
#pragma unroll
            for (int mi = 0; mi < MI; mi++) {
                const int m0 = wm + mi * 16 + l8;
                const int m1 = m0 + 8;
                const int ka = kk + l4;
                const int kb = ka + 4;
                uint32_t a0 = As[ka][(m0 & ~7) | ((m0 + (ka >> 2)) & 7)];
                uint32_t a1 = As[ka][(m1 & ~7) | ((m1 + (ka >> 2)) & 7)];
                uint32_t a2 = As[kb][(m0 & ~7) | ((m0 + (kb >> 2)) & 7)];
                uint32_t a3 = As[kb][(m1 & ~7) | ((m1 + (kb >> 2)) & 7)];
#pragma unroll
                for (int ni = 0; ni < NI; ni++) {
                    asm volatile(
                        "mma.sync.aligned.m16n8k8.row.col.f32.tf32.tf32.f32 "
                        "{%0,%1,%2,%3}, {%4,%5,%6,%7}, {%8,%9}, {%0,%1,%2,%3};"
                        : "+f"(acc[mi][ni][0]), "+f"(acc[mi][ni][1]),
                          "+f"(acc[mi][ni][2]), "+f"(acc[mi][ni][3])
                        : "r"(a0), "r"(a1), "r"(a2), "r"(a3),
                          "r"(bfr[ni][0]), "r"(bfr[ni][1]));
                }
            }
        }
        __syncthreads();
    }

#pragma unroll
    for (int mi = 0; mi < MI; mi++) {
        int r0 = bm + wm + mi * 16 + l8;
#pragma unroll
        for (int ni = 0; ni < NI; ni++) {
            int c0 = bn + wn + ni * 8 + l4 * 2;
#pragma unroll
            for (int q = 0; q < 4; q++) {
                int gr = r0 + ((q >= 2) ? 8 : 0);
                int gc = c0 + (q & 1);
                if (gr < M) {
                    float v = acc[mi][ni][q];
                    if (BIAS_ELU) {
                        v += bias[gc];
                        v = v > 0.f ? v : expm1f(v);
                    }
                    C[(size_t)gr * ldc + gc] = v;
                }
            }
        }
    }
}

// ----------------------------------------------------------------------------
// Layer-1 attention vector projection: qs[h,k] = sum_c W1[k, h*128+c]*as1[h,c]
// ----------------------------------------------------------------------------
__global__ void proj1_kernel(const float* __restrict__ W1,
                             const float* __restrict__ as1,
                             const float* __restrict__ ad1,
                             float* __restrict__ qs, float* __restrict__ qd) {
    int gw = (blockIdx.x * blockDim.x + threadIdx.x) >> 5;
    int lane = threadIdx.x & 31;
    if (gw >= H1 * F_IN) return;
    int h = gw / F_IN, k = gw % F_IN;
    const float* wrow = W1 + (size_t)k * D1 + h * C1;
    const float* av = as1 + h * C1;
    const float* dv = ad1 + h * C1;
    float s = 0.f, d = 0.f;
#pragma unroll
    for (int c = lane; c < C1; c += 32) {
        float wv = wrow[c];
        s += wv * av[c];
        d += wv * dv[c];
    }
#pragma unroll
    for (int off = 16; off > 0; off >>= 1) {
        s += __shfl_down_sync(0xffffffffu, s, off);
        d += __shfl_down_sync(0xffffffffu, d, off);
    }
    if (lane == 0) { qs[gw] = s; qd[gw] = d; }
}

// ----------------------------------------------------------------------------
// Layer-1 es/ed directly from x: es[n,h] = <x[n,:], qs[h,:]> (K = 66).
// ----------------------------------------------------------------------------
__global__ void esed1_kernel(int NN, const float* __restrict__ x,
                             const float* __restrict__ qs,
                             const float* __restrict__ qd,
                             float* __restrict__ es, float* __restrict__ ed) {
    __shared__ float xs[32][F_IN + 2];
    __shared__ float qss[H1 * F_IN], qds[H1 * F_IN];
    int tid = threadIdx.x;
    for (int i = tid; i < H1 * F_IN; i += 256) { qss[i] = qs[i]; qds[i] = qd[i]; }
    int n0 = blockIdx.x * 32;
    for (int i = tid; i < 32 * F_IN; i += 256) {
        int r = i / F_IN, c = i % F_IN;
        int n = n0 + r;
        xs[r][c] = (n < NN) ? x[(size_t)n * F_IN + c] : 0.f;
    }
    __syncthreads();
    int r = tid >> 3, h = tid & 7;
    int n = n0 + r;
    if (n < NN) {
        float s = 0.f, d = 0.f;
#pragma unroll
        for (int k = 0; k < F_IN; k++) {
            float xv = xs[r][k];
            s += xv * qss[h * F_IN + k];
            d += xv * qds[h * F_IN + k];
        }
        es[n * H1 + h] = s;
        ed[n * H1 + h] = d;
    }
}

// ----------------------------------------------------------------------------
// Edge logits: w = exp(leaky_relu(es[src]+ed[dst])); z[dst] += w (atomic).
// ----------------------------------------------------------------------------
template <int H>
__global__ void edgew_kernel(int E, int NN, const int* __restrict__ ei,
                             const float* __restrict__ es,
                             const float* __restrict__ ed,
                             float* __restrict__ w, float* __restrict__ z) {
    int idx = blockIdx.x * blockDim.x + threadIdx.x;
    int tot = (E + NN) * H;
    if (idx >= tot) return;
    int e = idx / H, hh = idx - e * H;
    int s, d;
    if (e < E) { s = ei[e]; d = ei[E + e]; }
    else       { s = d = e - E; }
    float v = es[(size_t)s * H + hh] + ed[(size_t)d * H + hh];
    v = v > 0.f ? v : 0.2f * v;      // leaky relu, slope 0.2
    float wv = expf(v);
    w[idx] = wv;
    atomicAdd(&z[(size_t)d * H + hh], wv);
}

// ----------------------------------------------------------------------------
// Layer-1 x-space aggregation: aggX[d, h, 0:66] += alpha_eh * x[s, 0:66].
// ----------------------------------------------------------------------------
__global__ void aggx_kernel(int E, int NN, const int* __restrict__ ei,
                            const float* __restrict__ x,
                            const float* __restrict__ w,
                            const float* __restrict__ z,
                            float* __restrict__ aggX) {
    int gw = (blockIdx.x * blockDim.x + threadIdx.x) >> 5;
    int lane = threadIdx.x & 31;
    int ET = E + NN;
    if (gw >= ET) return;
    int s, d;
    if (gw < E) { s = ei[gw]; d = ei[E + gw]; }
    else        { s = d = gw - E; }
    const float2* xr = reinterpret_cast<const float2*>(x + (size_t)s * F_IN);
    float2 v0 = xr[lane];
    float2 v1 = (lane == 0) ? xr[32] : make_float2(0.f, 0.f);
    const float* wrow = w + (size_t)gw * H1;
    const float* zrow = z + (size_t)d * H1;
    float* obase = aggX + (size_t)d * XH;
#pragma unroll
    for (int h = 0; h < H1; h++) {
        float alpha = wrow[h] / (zrow[h] + 1e-16f);
        float2* o2 = reinterpret_cast<float2*>(obase + h * F_IN);
        atomicAdd(o2 + lane, make_float2(v0.x * alpha, v0.y * alpha));
        if (lane == 0)
            atomicAdd(o2 + 32, make_float2(v1.x * alpha, v1.y * alpha));
    }
}

// ----------------------------------------------------------------------------
// Attention coefficients from features (layers 2/3): one warp per (node,head).
// ----------------------------------------------------------------------------
template <int C, int H>
__global__ void esed_kernel(int NN, const float* __restrict__ h,
                            const float* __restrict__ as,
                            const float* __restrict__ ad,
                            float* __restrict__ es, float* __restrict__ ed) {
    int gw = (blockIdx.x * blockDim.x + threadIdx.x) >> 5;
    int lane = threadIdx.x & 31;
    if (gw >= NN * H) return;
    int n = gw / H, hh = gw % H;
    const float* row = h + (size_t)n * (H * C) + hh * C;
    const float* av = as + hh * C;
    const float* dv = ad + hh * C;
    float s = 0.f, d = 0.f;
#pragma unroll
    for (int c = lane; c < C; c += 32) {
        float v = row[c];
        s += v * av[c];
        d += v * dv[c];
    }
#pragma unroll
    for (int off = 16; off > 0; off >>= 1) {
        s += __shfl_down_sync(0xffffffffu, s, off);
        d += __shfl_down_sync(0xffffffffu, d, off);
    }
    if (lane == 0) { es[gw] = s; ed[gw] = d; }
}

// ----------------------------------------------------------------------------
// Output-space aggregation (layers 2/3): out[dst,:] += alpha * h[src,:].
// ----------------------------------------------------------------------------
template <int C>
__global__ void agg_kernel(int E, int NN, const int* __restrict__ ei,
                           const float* __restrict__ h,
                           const float* __restrict__ w,
                           const float* __restrict__ z,
                           float* __restrict__ out) {
    int gw = (blockIdx.x * blockDim.x + threadIdx.x) >> 5;
    int lane = threadIdx.x & 31;
    int ET = E + NN;
    if (gw >= ET) return;
    int s, d;
    if (gw < E) { s = ei[gw]; d = ei[E + gw]; }
    else        { s = d = gw - E; }
    float alpha = w[gw] / (z[d] + 1e-16f);
    const float* hrow = h + (size_t)s * C;
    float* orow = out + (size_t)d * C;
    if (C == 128) {
        float4 v = reinterpret_cast<const float4*>(hrow)[lane];
        v.x *= alpha; v.y *= alpha; v.z *= alpha; v.w *= alpha;
        atomicAdd(reinterpret_cast<float4*>(orow) + lane, v);
    } else {  // C == 64
        float2 v = reinterpret_cast<const float2*>(hrow)[lane];
        v.x *= alpha; v.y *= alpha;
        atomicAdd(reinterpret_cast<float2*>(orow) + lane, v);
    }
}

// ----------------------------------------------------------------------------
// bias + ELU, in place
// ----------------------------------------------------------------------------
__global__ void bias_elu_kernel(float* __restrict__ a, const float* __restrict__ b,
                                long long total, int W) {
    long long i = (long long)blockIdx.x * blockDim.x + threadIdx.x;
    long long stride = (long long)gridDim.x * blockDim.x;
    for (; i < total; i += stride) {
        float v = a[i] + b[i % W];
        a[i] = v > 0.f ? v : expm1f(v);
    }
}

// ----------------------------------------------------------------------------
// Final: per node, ELU(agg3 + b3) . Wr + br -> sigmoid. One warp per node.
// ----------------------------------------------------------------------------
__global__ void final_kernel(int NN, const float* __restrict__ agg3,
                             const float* __restrict__ b3,
                             const float* __restrict__ Wr,
                             const float* __restrict__ br,
                             float* __restrict__ out) {
    int n = (blockIdx.x * blockDim.x + threadIdx.x) >> 5;
    int lane = threadIdx.x & 31;
    if (n >= NN) return;
    const float* row = agg3 + (size_t)n * D3;
    float acc = 0.f;
#pragma unroll
    for (int j = lane; j < D3; j += 32) {
        float v = row[j] + b3[j];
        v = v > 0.f ? v : expm1f(v);
        acc += v * Wr[j];
    }
#pragma unroll
    for (int off = 16; off > 0; off >>= 1)
        acc += __shfl_down_sync(0xffffffffu, acc, off);
    if (lane == 0)
        out[n] = 1.f / (1.f + expf(-(acc + br[0])));
}

// ----------------------------------------------------------------------------
// Host launcher
// ----------------------------------------------------------------------------
static inline int ceil_div(int a, int b) { return (a + b - 1) / b; }

extern "C" void kernel_launch(void* const* d_in, const int* in_sizes, int n_in,
                              void* d_out, int out_size) {
    const float* x   = (const float*)d_in[0];
    const int*   ei  = (const int*)d_in[1];   // int32 (JAX x64 disabled)
    const float* W1  = (const float*)d_in[2];
    const float* as1 = (const float*)d_in[3];
    const float* ad1 = (const float*)d_in[4];
    const float* b1  = (const float*)d_in[5];
    const float* W2  = (const float*)d_in[6];
    const float* as2 = (const float*)d_in[7];
    const float* ad2 = (const float*)d_in[8];
    const float* b2  = (const float*)d_in[9];
    const float* W3  = (const float*)d_in[10];
    const float* as3 = (const float*)d_in[11];
    const float* ad3 = (const float*)d_in[12];
    const float* b3  = (const float*)d_in[13];
    const float* Wr  = (const float*)d_in[14];
    const float* br  = (const float*)d_in[15];
    float* out = (float*)d_out;

    const int N = in_sizes[0] / F_IN;
    const int E = in_sizes[1] / 2;
    const int ET = E + N;

    float *zbase, *agg1, *h2, *h3;
    float *qs1, *qd1, *es1, *ed1, *es2, *ed2, *es3, *ed3, *w1, *w2, *w3;
    cudaGetSymbolAddress((void**)&zbase, g_zero);
    cudaGetSymbolAddress((void**)&agg1, g_agg1);
    cudaGetSymbolAddress((void**)&h2, g_h2);
    cudaGetSymbolAddress((void**)&h3, g_h3);
    cudaGetSymbolAddress((void**)&qs1, g_qs1);
    cudaGetSymbolAddress((void**)&qd1, g_qd1);
    cudaGetSymbolAddress((void**)&es1, g_es1);
    cudaGetSymbolAddress((void**)&ed1, g_ed1);
    cudaGetSymbolAddress((void**)&es2, g_es2);
    cudaGetSymbolAddress((void**)&ed2, g_ed2);
    cudaGetSymbolAddress((void**)&es3, g_es3);
    cudaGetSymbolAddress((void**)&ed3, g_ed3);
    cudaGetSymbolAddress((void**)&w1, g_w1);
    cudaGetSymbolAddress((void**)&w2, g_w2);
    cudaGetSymbolAddress((void**)&w3, g_w3);

    // carve the single zeroed region: aggX | z1 | agg2 | z2 | agg3 | z3
    float* aggX = zbase;
    float* z1   = aggX + (size_t)MAXN * XH;
    float* agg2 = z1   + (size_t)MAXN * H1;
    float* z2   = agg2 + (size_t)MAXN * D2;
    float* agg3 = z2   + (size_t)MAXN;
    float* z3   = agg3 + (size_t)MAXN * D3;

    // one memset for all accumulators
    cudaMemsetAsync(zbase, 0, (size_t)MAXN * ZW * sizeof(float));

    // ---------------- Layer 1 (x-space aggregation; h1 never materialized) --
    proj1_kernel<<<ceil_div(H1 * F_IN * 32, 256), 256>>>(W1, as1, ad1, qs1, qd1);
    esed1_kernel<<<ceil_div(N, 32), 256>>>(N, x, qs1, qd1, es1, ed1);
    edgew_kernel<H1><<<ceil_div(ET * H1, 256), 256>>>(E, N, ei, es1, ed1, w1, z1);
    aggx_kernel<<<ceil_div(ET * 32, 256), 256>>>(E, N, ei, x, w1, z1, aggX);
    {
        // per-head block-diagonal GEMM with fused bias+ELU (K=66 tail -> old kernel)
        dim3 grid(1, ceil_div(N, 128), H1);
        tf32_gemm_kernel<128, 128, 32, 64, 32, true><<<grid, 256>>>(
            N, C1, F_IN,
            aggX, XH, (long long)F_IN,
            W1, D1, (long long)C1,
            agg1, D1, (long long)C1,
            b1);
    }

    // ---------------- Layer 2: 1024 -> 128 (pipelined tf32) -----------------
    {
        dim3 grid(1, ceil_div(N, 128), 1);
        tf32_gemm_pipe_kernel<128, 128, 16, 64, 32><<<grid, 256>>>(
            N, D2, D1, agg1, D1, W2, D2, h2, D2);
    }
    esed_kernel<D2, 1><<<ceil_div(N * 32, 256), 256>>>(N, h2, as2, ad2, es2, ed2);
    edgew_kernel<1><<<ceil_div(ET, 256), 256>>>(E, N, ei, es2, ed2, w2, z2);
    agg_kernel<D2><<<ceil_div(ET * 32, 256), 256>>>(E, N, ei, h2, w2, z2, agg2);
    bias_elu_kernel<<<1024, 256>>>(agg2, b2, (long long)N * D2, D2);

    // ---------------- Layer 3: 128 -> 64 (pipelined tf32) -------------------
    {
        dim3 grid(1, ceil_div(N, 128), 1);
        tf32_gemm_pipe_kernel<128, 64, 16, 64, 16><<<grid, 256>>>(
            N, D3, D2, agg2, D2, W3, D3, h3, D3);
    }
    esed_kernel<D3, 1><<<ceil_div(N * 32, 256), 256>>>(N, h3, as3, ad3, es3, ed3);
    edgew_kernel<1><<<ceil_div(ET, 256), 256>>>(E, N, ei, es3, ed3, w3, z3);
    agg_kernel<D3><<<ceil_div(ET * 32, 256), 256>>>(E, N, ei, h3, w3, z3, agg3);

    // ---------------- Regressor (fused bias+ELU+dot+sigmoid) ----------------
    final_kernel<<<ceil_div(N * 32, 256), 256>>>(N, agg3, b3, Wr, br, out);
}

// round 12
// speedup vs baseline: 3.4932x; 1.4379x over previous
#include <cuda_runtime.h>
#include <cuda_bf16.h>
#include <cstdint>
#include <math.h>

// ----------------------------------------------------------------------------
// Problem constants (shapes fixed by the reference)
// ----------------------------------------------------------------------------
#define MAXN 50000
#define MAXE 200000
#define F_IN 66
#define H1 8
#define C1 128
#define D1 (H1 * C1)   // 1024
#define D2 128
#define D3 64
#define KP 80          // K=66 padded to 80 (=5*16) for the pipelined head GEMM
#define XHP (H1 * KP)  // 640 : per-node width of padded x-space agg buffer

// ----------------------------------------------------------------------------
// Device scratch (static globals: allocation-free)
// One contiguous zero-initialized region -> single memset per launch.
// Layout: aggX(padded) | z1 | agg2 | z2 | agg3 | z3
// ----------------------------------------------------------------------------
#define ZW (XHP + H1 + D2 + 1 + D3 + 1)   // 842 floats per node
__device__ float g_zero[(size_t)MAXN * ZW];

__device__ float g_agg1[(size_t)MAXN * D1];   // layer-1 output (post bias+ELU)
__device__ float g_h2[(size_t)MAXN * D2];
__device__ float g_h3[(size_t)MAXN * D3];
__device__ float g_W1p[H1 * KP * C1];         // W1 repacked per-head, K padded

__device__ float g_qs1[H1 * F_IN], g_qd1[H1 * F_IN];  // W1-projected attention vecs
__device__ float g_es1[MAXN * H1], g_ed1[MAXN * H1];
__device__ float g_es2[MAXN], g_ed2[MAXN];
__device__ float g_es3[MAXN], g_ed3[MAXN];
__device__ float g_w1[(size_t)(MAXE + MAXN) * H1];
__device__ float g_w2[(MAXE + MAXN)];
__device__ float g_w3[(MAXE + MAXN)];

// ----------------------------------------------------------------------------
// cp.async helpers
// ----------------------------------------------------------------------------
__device__ __forceinline__ void cp_async16(uint32_t smem_dst, const void* gsrc, int sz) {
    asm volatile("cp.async.cg.shared.global [%0], [%1], 16, %2;\n"
                 :: "r"(smem_dst), "l"(gsrc), "r"(sz));
}
__device__ __forceinline__ void cp_commit() {
    asm volatile("cp.async.commit_group;\n");
}
template <int NG>
__device__ __forceinline__ void cp_wait() {
    asm volatile("cp.async.wait_group %0;\n" :: "n"(NG));
}

// ----------------------------------------------------------------------------
// 2-stage cp.async pipelined TF32 GEMM: C[M,N] = A[M,K] @ B[K,N].
// blockIdx.z selects a slice (per-head GEMM): pointers advance by
// strideAz/strideBz/strideCz/(bias: N) elements per z.
// Requires: K % BK == 0, N == BN (grid.x = 1), lda % 4 == 0, strideAz % 4 == 0.
// Raw fp32 bits fed to tf32 mma (truncation; CUTLASS fast path).
// As[m][k] stride AS=BK+4 and Bs[k][n] stride BS=BN+8: conflict-free for both
// the 16B cp.async stores and the m16n8k8 fragment loads (checked mod 32).
// Optional fused bias + ELU epilogue.
// ----------------------------------------------------------------------------
template <int BM, int BN, int BK, int WM, int WN, bool BIAS_ELU>
__global__ void tf32_gemm_pipe_kernel(int M, int N, int K,
        const float* __restrict__ A, int lda, long long strideAz,
        const float* __restrict__ B, int ldb, long long strideBz,
        float* __restrict__ C, int ldc, long long strideCz,
        const float* __restrict__ bias) {
    constexpr int WARPS_M = BM / WM, WARPS_N = BN / WN;
    constexpr int NT = 32 * WARPS_M * WARPS_N;
    constexpr int MI = WM / 16, NI = WN / 8;
    constexpr int AS = BK + 4;
    constexpr int BS = BN + 8;
    constexpr int A_CHUNKS = BM * (BK / 4);
    constexpr int B_CHUNKS = BK * (BN / 4);

    __shared__ float Asm[2][BM][AS];
    __shared__ float Bsm[2][BK][BS];

    const int tid = threadIdx.x;
    const int wid = tid >> 5, lane = tid & 31;
    const int l4 = lane & 3, l8 = lane >> 2;
    const int wm = (wid / WARPS_N) * WM;
    const int wn = (wid % WARPS_N) * WN;
    const int bm = blockIdx.y * BM;

    A += (long long)blockIdx.z * strideAz;
    B += (long long)blockIdx.z * strideBz;
    C += (long long)blockIdx.z * strideCz;
    if (BIAS_ELU) bias += (long long)blockIdx.z * (long long)N;

    float acc[MI][NI][4];
#pragma unroll
    for (int i = 0; i < MI; i++)
#pragma unroll
        for (int j = 0; j < NI; j++)
#pragma unroll
            for (int q = 0; q < 4; q++) acc[i][j][q] = 0.f;

    const uint32_t a_base = (uint32_t)__cvta_generic_to_shared(&Asm[0][0][0]);
    const uint32_t b_base = (uint32_t)__cvta_generic_to_shared(&Bsm[0][0][0]);
    constexpr uint32_t A_STAGE = BM * AS * 4;
    constexpr uint32_t B_STAGE = BK * BS * 4;

    auto issue = [&](int s, int k0) {
#pragma unroll
        for (int j = tid; j < A_CHUNKS; j += NT) {
            int m = j / (BK / 4), cq = j % (BK / 4);
            int gm = bm + m;
            const float* src = A + (size_t)gm * lda + k0 + 4 * cq;
            uint32_t dst = a_base + s * A_STAGE + (m * AS + 4 * cq) * 4;
            cp_async16(dst, src, gm < M ? 16 : 0);
        }
#pragma unroll
        for (int j = tid; j < B_CHUNKS; j += NT) {
            int r = j / (BN / 4), cq = j % (BN / 4);
            const float* src = B + (size_t)(k0 + r) * ldb + 4 * cq;
            uint32_t dst = b_base + s * B_STAGE + (r * BS + 4 * cq) * 4;
            cp_async16(dst, src, 16);
        }
        cp_commit();
    };

    const int KT = K / BK;
    issue(0, 0);

    for (int t = 0; t < KT; t++) {
        if (t + 1 < KT) {
            issue((t + 1) & 1, (t + 1) * BK);
            cp_wait<1>();
        } else {
            cp_wait<0>();
        }
        __syncthreads();
        const int s = t & 1;

#pragma unroll
        for (int kk = 0; kk < BK; kk += 8) {
            uint32_t bfr[NI][2];
#pragma unroll
            for (int ni = 0; ni < NI; ni++) {
                bfr[ni][0] = __float_as_uint(Bsm[s][kk + l4][wn + ni * 8 + l8]);
                bfr[ni][1] = __float_as_uint(Bsm[s][kk + l4 + 4][wn + ni * 8 + l8]);
            }
#pragma unroll
            for (int mi = 0; mi < MI; mi++) {
                const int m0 = wm + mi * 16 + l8;
                const int m1 = m0 + 8;
                uint32_t a0 = __float_as_uint(Asm[s][m0][kk + l4]);
                uint32_t a1 = __float_as_uint(Asm[s][m1][kk + l4]);
                uint32_t a2 = __float_as_uint(Asm[s][m0][kk + l4 + 4]);
                uint32_t a3 = __float_as_uint(Asm[s][m1][kk + l4 + 4]);
#pragma unroll
                for (int ni = 0; ni < NI; ni++) {
                    asm volatile(
                        "mma.sync.aligned.m16n8k8.row.col.f32.tf32.tf32.f32 "
                        "{%0,%1,%2,%3}, {%4,%5,%6,%7}, {%8,%9}, {%0,%1,%2,%3};"
                        : "+f"(acc[mi][ni][0]), "+f"(acc[mi][ni][1]),
                          "+f"(acc[mi][ni][2]), "+f"(acc[mi][ni][3])
                        : "r"(a0), "r"(a1), "r"(a2), "r"(a3),
                          "r"(bfr[ni][0]), "r"(bfr[ni][1]));
                }
            }
        }
        __syncthreads();
    }

#pragma unroll
    for (int mi = 0; mi < MI; mi++) {
        int r0 = bm + wm + mi * 16 + l8;
#pragma unroll
        for (int ni = 0; ni < NI; ni++) {
            int c0 = wn + ni * 8 + l4 * 2;
#pragma unroll
            for (int q = 0; q < 4; q++) {
                int gr = r0 + ((q >= 2) ? 8 : 0);
                int gc = c0 + (q & 1);
                if (gr < M) {
                    float v = acc[mi][ni][q];
                    if (BIAS_ELU) {
                        v += bias[gc];
                        v = v > 0.f ? v : expm1f(v);
                    }
                    C[(size_t)gr * ldc + gc] = v;
                }
            }
        }
    }
}

// ----------------------------------------------------------------------------
// Repack W1 [66, 8*128] into W1p [8][KP=80][128], zero-padding rows 66..79.
// ----------------------------------------------------------------------------
__global__ void w1pad_kernel(const float* __restrict__ W1, float* __restrict__ W1p) {
    int i = blockIdx.x * 256 + threadIdx.x;
    if (i >= H1 * KP * C1) return;
    int c = i % C1;
    int k = (i / C1) % KP;
    int h = i / (C1 * KP);
    W1p[i] = (k < F_IN) ? W1[(size_t)k * D1 + h * C1 + c] : 0.f;
}

// ----------------------------------------------------------------------------
// Layer-1 attention vector projection: qs[h,k] = sum_c W1[k, h*128+c]*as1[h,c]
// ----------------------------------------------------------------------------
__global__ void proj1_kernel(const float* __restrict__ W1,
                             const float* __restrict__ as1,
                             const float* __restrict__ ad1,
                             float* __restrict__ qs, float* __restrict__ qd) {
    int gw = (blockIdx.x * blockDim.x + threadIdx.x) >> 5;
    int lane = threadIdx.x & 31;
    if (gw >= H1 * F_IN) return;
    int h = gw / F_IN, k = gw % F_IN;
    const float* wrow = W1 + (size_t)k * D1 + h * C1;
    const float* av = as1 + h * C1;
    const float* dv = ad1 + h * C1;
    float s = 0.f, d = 0.f;
#pragma unroll
    for (int c = lane; c < C1; c += 32) {
        float wv = wrow[c];
        s += wv * av[c];
        d += wv * dv[c];
    }
#pragma unroll
    for (int off = 16; off > 0; off >>= 1) {
        s += __shfl_down_sync(0xffffffffu, s, off);
        d += __shfl_down_sync(0xffffffffu, d, off);
    }
    if (lane == 0) { qs[gw] = s; qd[gw] = d; }
}

// ----------------------------------------------------------------------------
// Layer-1 es/ed directly from x: es[n,h] = <x[n,:], qs[h,:]> (K = 66).
// ----------------------------------------------------------------------------
__global__ void esed1_kernel(int NN, const float* __restrict__ x,
                             const float* __restrict__ qs,
                             const float* __restrict__ qd,
                             float* __restrict__ es, float* __restrict__ ed) {
    __shared__ float xs[32][F_IN + 2];
    __shared__ float qss[H1 * F_IN], qds[H1 * F_IN];
    int tid = threadIdx.x;
    for (int i = tid; i < H1 * F_IN; i += 256) { qss[i] = qs[i]; qds[i] = qd[i]; }
    int n0 = blockIdx.x * 32;
    for (int i = tid; i < 32 * F_IN; i += 256) {
        int r = i / F_IN, c = i % F_IN;
        int n = n0 + r;
        xs[r][c] = (n < NN) ? x[(size_t)n * F_IN + c] : 0.f;
    }
    __syncthreads();
    int r = tid >> 3, h = tid & 7;
    int n = n0 + r;
    if (n < NN) {
        float s = 0.f, d = 0.f;
#pragma unroll
        for (int k = 0; k < F_IN; k++) {
            float xv = xs[r][k];
            s += xv * qss[h * F_IN + k];
            d += xv * qds[h * F_IN + k];
        }
        es[n * H1 + h] = s;
        ed[n * H1 + h] = d;
    }
}

// ----------------------------------------------------------------------------
// Edge logits: w = exp(leaky_relu(es[src]+ed[dst])); z[dst] += w (atomic).
// ----------------------------------------------------------------------------
template <int H>
__global__ void edgew_kernel(int E, int NN, const int* __restrict__ ei,
                             const float* __restrict__ es,
                             const float* __restrict__ ed,
                             float* __restrict__ w, float* __restrict__ z) {
    int idx = blockIdx.x * blockDim.x + threadIdx.x;
    int tot = (E + NN) * H;
    if (idx >= tot) return;
    int e = idx / H, hh = idx - e * H;
    int s, d;
    if (e < E) { s = ei[e]; d = ei[E + e]; }
    else       { s = d = e - E; }
    float v = es[(size_t)s * H + hh] + ed[(size_t)d * H + hh];
    v = v > 0.f ? v : 0.2f * v;      // leaky relu, slope 0.2
    float wv = expf(v);
    w[idx] = wv;
    atomicAdd(&z[(size_t)d * H + hh], wv);
}

// ----------------------------------------------------------------------------
// Layer-1 x-space aggregation: aggX[d, h*KP + 0:66] += alpha_eh * x[s, 0:66].
// Pad floats [66, 80) are never written (stay zero from the memset).
// ----------------------------------------------------------------------------
__global__ void aggx_kernel(int E, int NN, const int* __restrict__ ei,
                            const float* __restrict__ x,
                            const float* __restrict__ w,
                            const float* __restrict__ z,
                            float* __restrict__ aggX) {
    int gw = (blockIdx.x * blockDim.x + threadIdx.x) >> 5;
    int lane = threadIdx.x & 31;
    int ET = E + NN;
    if (gw >= ET) return;
    int s, d;
    if (gw < E) { s = ei[gw]; d = ei[E + gw]; }
    else        { s = d = gw - E; }
    const float2* xr = reinterpret_cast<const float2*>(x + (size_t)s * F_IN);
    float2 v0 = xr[lane];
    float2 v1 = (lane == 0) ? xr[32] : make_float2(0.f, 0.f);
    const float* wrow = w + (size_t)gw * H1;
    const float* zrow = z + (size_t)d * H1;
    float* obase = aggX + (size_t)d * XHP;
#pragma unroll
    for (int h = 0; h < H1; h++) {
        float alpha = wrow[h] / (zrow[h] + 1e-16f);
        float2* o2 = reinterpret_cast<float2*>(obase + h * KP);
        atomicAdd(o2 + lane, make_float2(v0.x * alpha, v0.y * alpha));
        if (lane == 0)
            atomicAdd(o2 + 32, make_float2(v1.x * alpha, v1.y * alpha));
    }
}

// ----------------------------------------------------------------------------
// Attention coefficients from features (layers 2/3): one warp per (node,head).
// ----------------------------------------------------------------------------
template <int C, int H>
__global__ void esed_kernel(int NN, const float* __restrict__ h,
                            const float* __restrict__ as,
                            const float* __restrict__ ad,
                            float* __restrict__ es, float* __restrict__ ed) {
    int gw = (blockIdx.x * blockDim.x + threadIdx.x) >> 5;
    int lane = threadIdx.x & 31;
    if (gw >= NN * H) return;
    int n = gw / H, hh = gw % H;
    const float* row = h + (size_t)n * (H * C) + hh * C;
    const float* av = as + hh * C;
    const float* dv = ad + hh * C;
    float s = 0.f, d = 0.f;
#pragma unroll
    for (int c = lane; c < C; c += 32) {
        float v = row[c];
        s += v * av[c];
        d += v * dv[c];
    }
#pragma unroll
    for (int off = 16; off > 0; off >>= 1) {
        s += __shfl_down_sync(0xffffffffu, s, off);
        d += __shfl_down_sync(0xffffffffu, d, off);
    }
    if (lane == 0) { es[gw] = s; ed[gw] = d; }
}

// ----------------------------------------------------------------------------
// Output-space aggregation (layers 2/3): out[dst,:] += alpha * h[src,:].
// ----------------------------------------------------------------------------
template <int C>
__global__ void agg_kernel(int E, int NN, const int* __restrict__ ei,
                           const float* __restrict__ h,
                           const float* __restrict__ w,
                           const float* __restrict__ z,
                           float* __restrict__ out) {
    int gw = (blockIdx.x * blockDim.x + threadIdx.x) >> 5;
    int lane = threadIdx.x & 31;
    int ET = E + NN;
    if (gw >= ET) return;
    int s, d;
    if (gw < E) { s = ei[gw]; d = ei[E + gw]; }
    else        { s = d = gw - E; }
    float alpha = w[gw] / (z[d] + 1e-16f);
    const float* hrow = h + (size_t)s * C;
    float* orow = out + (size_t)d * C;
    if (C == 128) {
        float4 v = reinterpret_cast<const float4*>(hrow)[lane];
        v.x *= alpha; v.y *= alpha; v.z *= alpha; v.w *= alpha;
        atomicAdd(reinterpret_cast<float4*>(orow) + lane, v);
    } else {  // C == 64
        float2 v = reinterpret_cast<const float2*>(hrow)[lane];
        v.x *= alpha; v.y *= alpha;
        atomicAdd(reinterpret_cast<float2*>(orow) + lane, v);
    }
}

// ----------------------------------------------------------------------------
// bias + ELU, in place
// ----------------------------------------------------------------------------
__global__ void bias_elu_kernel(float* __restrict__ a, const float* __restrict__ b,
                                long long total, int W) {
    long long i = (long long)blockIdx.x * blockDim.x + threadIdx.x;
    long long stride = (long long)gridDim.x * blockDim.x;
    for (; i < total; i += stride) {
        float v = a[i] + b[i % W];
        a[i] = v > 0.f ? v : expm1f(v);
    }
}

// ----------------------------------------------------------------------------
// Final: per node, ELU(agg3 + b3) . Wr + br -> sigmoid. One warp per node.
// ----------------------------------------------------------------------------
__global__ void final_kernel(int NN, const float* __restrict__ agg3,
                             const float* __restrict__ b3,
                             const float* __restrict__ Wr,
                             const float* __restrict__ br,
                             float* __restrict__ out) {
    int n = (blockIdx.x * blockDim.x + threadIdx.x) >> 5;
    int lane = threadIdx.x & 31;
    if (n >= NN) return;
    const float* row = agg3 + (size_t)n * D3;
    float acc = 0.f;
#pragma unroll
    for (int j = lane; j < D3; j += 32) {
        float v = row[j] + b3[j];
        v = v > 0.f ? v : expm1f(v);
        acc += v * Wr[j];
    }
#pragma unroll
    for (int off = 16; off > 0; off >>= 1)
        acc += __shfl_down_sync(0xffffffffu, acc, off);
    if (lane == 0)
        out[n] = 1.f / (1.f + expf(-(acc + br[0])));
}

// ----------------------------------------------------------------------------
// Host launcher
// ----------------------------------------------------------------------------
static inline int ceil_div(int a, int b) { return (a + b - 1) / b; }

extern "C" void kernel_launch(void* const* d_in, const int* in_sizes, int n_in,
                              void* d_out, int out_size) {
    const float* x   = (const float*)d_in[0];
    const int*   ei  = (const int*)d_in[1];   // int32 (JAX x64 disabled)
    const float* W1  = (const float*)d_in[2];
    const float* as1 = (const float*)d_in[3];
    const float* ad1 = (const float*)d_in[4];
    const float* b1  = (const float*)d_in[5];
    const float* W2  = (const float*)d_in[6];
    const float* as2 = (const float*)d_in[7];
    const float* ad2 = (const float*)d_in[8];
    const float* b2  = (const float*)d_in[9];
    const float* W3  = (const float*)d_in[10];
    const float* as3 = (const float*)d_in[11];
    const float* ad3 = (const float*)d_in[12];
    const float* b3  = (const float*)d_in[13];
    const float* Wr  = (const float*)d_in[14];
    const float* br  = (const float*)d_in[15];
    float* out = (float*)d_out;

    const int N = in_sizes[0] / F_IN;
    const int E = in_sizes[1] / 2;
    const int ET = E + N;

    float *zbase, *agg1, *h2, *h3, *W1p;
    float *qs1, *qd1, *es1, *ed1, *es2, *ed2, *es3, *ed3, *w1, *w2, *w3;
    cudaGetSymbolAddress((void**)&zbase, g_zero);
    cudaGetSymbolAddress((void**)&agg1, g_agg1);
    cudaGetSymbolAddress((void**)&h2, g_h2);
    cudaGetSymbolAddress((void**)&h3, g_h3);
    cudaGetSymbolAddress((void**)&W1p, g_W1p);
    cudaGetSymbolAddress((void**)&qs1, g_qs1);
    cudaGetSymbolAddress((void**)&qd1, g_qd1);
    cudaGetSymbolAddress((void**)&es1, g_es1);
    cudaGetSymbolAddress((void**)&ed1, g_ed1);
    cudaGetSymbolAddress((void**)&es2, g_es2);
    cudaGetSymbolAddress((void**)&ed2, g_ed2);
    cudaGetSymbolAddress((void**)&es3, g_es3);
    cudaGetSymbolAddress((void**)&ed3, g_ed3);
    cudaGetSymbolAddress((void**)&w1, g_w1);
    cudaGetSymbolAddress((void**)&w2, g_w2);
    cudaGetSymbolAddress((void**)&w3, g_w3);

    // carve the single zeroed region: aggX | z1 | agg2 | z2 | agg3 | z3
    float* aggX = zbase;
    float* z1   = aggX + (size_t)MAXN * XHP;
    float* agg2 = z1   + (size_t)MAXN * H1;
    float* z2   = agg2 + (size_t)MAXN * D2;
    float* agg3 = z2   + (size_t)MAXN;
    float* z3   = agg3 + (size_t)MAXN * D3;

    // one memset for all accumulators
    cudaMemsetAsync(zbase, 0, (size_t)MAXN * ZW * sizeof(float));

    // ---------------- Layer 1 (x-space aggregation; h1 never materialized) --
    w1pad_kernel<<<ceil_div(H1 * KP * C1, 256), 256>>>(W1, W1p);
    proj1_kernel<<<ceil_div(H1 * F_IN * 32, 256), 256>>>(W1, as1, ad1, qs1, qd1);
    esed1_kernel<<<ceil_div(N, 32), 256>>>(N, x, qs1, qd1, es1, ed1);
    edgew_kernel<H1><<<ceil_div(ET * H1, 256), 256>>>(E, N, ei, es1, ed1, w1, z1);
    aggx_kernel<<<ceil_div(ET * 32, 256), 256>>>(E, N, ei, x, w1, z1, aggX);
    {
        // per-head block-diagonal GEMM with fused bias+ELU (pipelined, K padded)
        dim3 grid(1, ceil_div(N, 128), H1);
        tf32_gemm_pipe_kernel<128, 128, 16, 64, 32, true><<<grid, 256>>>(
            N, C1, KP,
            aggX, XHP, (long long)KP,
            W1p, C1, (long long)KP * C1,
            agg1, D1, (long long)C1,
            b1);
    }

    // ---------------- Layer 2: 1024 -> 128 (pipelined tf32) -----------------
    {
        dim3 grid(1, ceil_div(N, 128), 1);
        tf32_gemm_pipe_kernel<128, 128, 16, 64, 32, false><<<grid, 256>>>(
            N, D2, D1, agg1, D1, 0, W2, D2, 0, h2, D2, 0, nullptr);
    }
    esed_kernel<D2, 1><<<ceil_div(N * 32, 256), 256>>>(N, h2, as2, ad2, es2, ed2);
    edgew_kernel<1><<<ceil_div(ET, 256), 256>>>(E, N, ei, es2, ed2, w2, z2);
    agg_kernel<D2><<<ceil_div(ET * 32, 256), 256>>>(E, N, ei, h2, w2, z2, agg2);
    bias_elu_kernel<<<1024, 256>>>(agg2, b2, (long long)N * D2, D2);

    // ---------------- Layer 3: 128 -> 64 (pipelined tf32) -------------------
    {
        dim3 grid(1, ceil_div(N, 128), 1);
        tf32_gemm_pipe_kernel<128, 64, 16, 64, 16, false><<<grid, 256>>>(
            N, D3, D2, agg2, D2, 0, W3, D3, 0, h3, D3, 0, nullptr);
    }
    esed_kernel<D3, 1><<<ceil_div(N * 32, 256), 256>>>(N, h3, as3, ad3, es3, ed3);
    edgew_kernel<1><<<ceil_div(ET, 256), 256>>>(E, N, ei, es3, ed3, w3, z3);
    agg_kernel<D3><<<ceil_div(ET * 32, 256), 256>>>(E, N, ei, h3, w3, z3, agg3);

    // ---------------- Regressor (fused bias+ELU+dot+sigmoid) ----------------
    final_kernel<<<ceil_div(N * 32, 256), 256>>>(N, agg3, b3, Wr, br, out);
}

// round 13
// speedup vs baseline: 4.2270x; 1.2101x over previous
#include <cuda_runtime.h>
#include <cuda_bf16.h>
#include <cstdint>
#include <math.h>

// ----------------------------------------------------------------------------
// Problem constants (shapes fixed by the reference)
// ----------------------------------------------------------------------------
#define MAXN 50000
#define MAXE 200000
#define F_IN 66
#define H1 8
#define C1 128
#define D1 (H1 * C1)   // 1024
#define D2 128
#define D3 64
#define KP 80          // K=66 padded to 80 (=5*16) for the pipelined head GEMM
#define XHP (H1 * KP)  // 640 : per-node width of padded x-space agg buffer

// ----------------------------------------------------------------------------
// Device scratch (static globals: allocation-free)
// ----------------------------------------------------------------------------
__device__ float g_aggX[(size_t)MAXN * XHP];  // layer-1 x-space agg (normalized)
__device__ float g_agg1[(size_t)MAXN * D1];   // layer-1 output (post bias+ELU)
__device__ float g_h2[(size_t)MAXN * D2];
__device__ float g_agg2[(size_t)MAXN * D2];   // post bias+ELU (fused)
__device__ float g_h3[(size_t)MAXN * D3];
__device__ float g_agg3[(size_t)MAXN * D3];
__device__ float g_W1p[H1 * KP * C1];         // W1 repacked per-head, K padded

__device__ float g_qs1[H1 * F_IN], g_qd1[H1 * F_IN];
__device__ float g_es1[MAXN * H1], g_ed1[MAXN * H1];
__device__ float g_es2[MAXN], g_ed2[MAXN];
__device__ float g_es3[MAXN], g_ed3[MAXN];

// CSR by destination (self-loops handled implicitly, not stored)
__device__ int g_cntfill[2 * MAXN];           // [0:N) cnt, [N:2N) fill — memset 0
__device__ int g_offsets[MAXN];
__device__ int g_srcs[MAXE];

// ----------------------------------------------------------------------------
// cp.async helpers
// ----------------------------------------------------------------------------
__device__ __forceinline__ void cp_async16(uint32_t smem_dst, const void* gsrc, int sz) {
    asm volatile("cp.async.cg.shared.global [%0], [%1], 16, %2;\n"
                 :: "r"(smem_dst), "l"(gsrc), "r"(sz));
}
__device__ __forceinline__ void cp_commit() {
    asm volatile("cp.async.commit_group;\n");
}
template <int NG>
__device__ __forceinline__ void cp_wait() {
    asm volatile("cp.async.wait_group %0;\n" :: "n"(NG));
}

// ----------------------------------------------------------------------------
// 2-stage cp.async pipelined TF32 GEMM: C[M,N] = A[M,K] @ B[K,N].
// blockIdx.z selects a slice; optional fused bias+ELU epilogue.
// ----------------------------------------------------------------------------
template <int BM, int BN, int BK, int WM, int WN, bool BIAS_ELU>
__global__ void tf32_gemm_pipe_kernel(int M, int N, int K,
        const float* __restrict__ A, int lda, long long strideAz,
        const float* __restrict__ B, int ldb, long long strideBz,
        float* __restrict__ C, int ldc, long long strideCz,
        const float* __restrict__ bias) {
    constexpr int WARPS_M = BM / WM, WARPS_N = BN / WN;
    constexpr int NT = 32 * WARPS_M * WARPS_N;
    constexpr int MI = WM / 16, NI = WN / 8;
    constexpr int AS = BK + 4;
    constexpr int BS = BN + 8;
    constexpr int A_CHUNKS = BM * (BK / 4);
    constexpr int B_CHUNKS = BK * (BN / 4);

    __shared__ float Asm[2][BM][AS];
    __shared__ float Bsm[2][BK][BS];

    const int tid = threadIdx.x;
    const int wid = tid >> 5, lane = tid & 31;
    const int l4 = lane & 3, l8 = lane >> 2;
    const int wm = (wid / WARPS_N) * WM;
    const int wn = (wid % WARPS_N) * WN;
    const int bm = blockIdx.y * BM;

    A += (long long)blockIdx.z * strideAz;
    B += (long long)blockIdx.z * strideBz;
    C += (long long)blockIdx.z * strideCz;
    if (BIAS_ELU) bias += (long long)blockIdx.z * (long long)N;

    float acc[MI][NI][4];
#pragma unroll
    for (int i = 0; i < MI; i++)
#pragma unroll
        for (int j = 0; j < NI; j++)
#pragma unroll
            for (int q = 0; q < 4; q++) acc[i][j][q] = 0.f;

    const uint32_t a_base = (uint32_t)__cvta_generic_to_shared(&Asm[0][0][0]);
    const uint32_t b_base = (uint32_t)__cvta_generic_to_shared(&Bsm[0][0][0]);
    constexpr uint32_t A_STAGE = BM * AS * 4;
    constexpr uint32_t B_STAGE = BK * BS * 4;

    auto issue = [&](int s, int k0) {
#pragma unroll
        for (int j = tid; j < A_CHUNKS; j += NT) {
            int m = j / (BK / 4), cq = j % (BK / 4);
            int gm = bm + m;
            const float* src = A + (size_t)gm * lda + k0 + 4 * cq;
            uint32_t dst = a_base + s * A_STAGE + (m * AS + 4 * cq) * 4;
            cp_async16(dst, src, gm < M ? 16 : 0);
        }
#pragma unroll
        for (int j = tid; j < B_CHUNKS; j += NT) {
            int r = j / (BN / 4), cq = j % (BN / 4);
            const float* src = B + (size_t)(k0 + r) * ldb + 4 * cq;
            uint32_t dst = b_base + s * B_STAGE + (r * BS + 4 * cq) * 4;
            cp_async16(dst, src, 16);
        }
        cp_commit();
    };

    const int KT = K / BK;
    issue(0, 0);

    for (int t = 0; t < KT; t++) {
        if (t + 1 < KT) {
            issue((t + 1) & 1, (t + 1) * BK);
            cp_wait<1>();
        } else {
            cp_wait<0>();
        }
        __syncthreads();
        const int s = t & 1;

#pragma unroll
        for (int kk = 0; kk < BK; kk += 8) {
            uint32_t bfr[NI][2];
#pragma unroll
            for (int ni = 0; ni < NI; ni++) {
                bfr[ni][0] = __float_as_uint(Bsm[s][kk + l4][wn + ni * 8 + l8]);
                bfr[ni][1] = __float_as_uint(Bsm[s][kk + l4 + 4][wn + ni * 8 + l8]);
            }
#pragma unroll
            for (int mi = 0; mi < MI; mi++) {
                const int m0 = wm + mi * 16 + l8;
                const int m1 = m0 + 8;
                uint32_t a0 = __float_as_uint(Asm[s][m0][kk + l4]);
                uint32_t a1 = __float_as_uint(Asm[s][m1][kk + l4]);
                uint32_t a2 = __float_as_uint(Asm[s][m0][kk + l4 + 4]);
                uint32_t a3 = __float_as_uint(Asm[s][m1][kk + l4 + 4]);
#pragma unroll
                for (int ni = 0; ni < NI; ni++) {
                    asm volatile(
                        "mma.sync.aligned.m16n8k8.row.col.f32.tf32.tf32.f32 "
                        "{%0,%1,%2,%3}, {%4,%5,%6,%7}, {%8,%9}, {%0,%1,%2,%3};"
                        : "+f"(acc[mi][ni][0]), "+f"(acc[mi][ni][1]),
                          "+f"(acc[mi][ni][2]), "+f"(acc[mi][ni][3])
                        : "r"(a0), "r"(a1), "r"(a2), "r"(a3),
                          "r"(bfr[ni][0]), "r"(bfr[ni][1]));
                }
            }
        }
        __syncthreads();
    }

#pragma unroll
    for (int mi = 0; mi < MI; mi++) {
        int r0 = bm + wm + mi * 16 + l8;
#pragma unroll
        for (int ni = 0; ni < NI; ni++) {
            int c0 = wn + ni * 8 + l4 * 2;
#pragma unroll
            for (int q = 0; q < 4; q++) {
                int gr = r0 + ((q >= 2) ? 8 : 0);
                int gc = c0 + (q & 1);
                if (gr < M) {
                    float v = acc[mi][ni][q];
                    if (BIAS_ELU) {
                        v += bias[gc];
                        v = v > 0.f ? v : expm1f(v);
                    }
                    C[(size_t)gr * ldc + gc] = v;
                }
            }
        }
    }
}

// ----------------------------------------------------------------------------
// CSR build: histogram -> single-block scan -> scatter
// ----------------------------------------------------------------------------
__global__ void hist_kernel(int E, const int* __restrict__ ei, int* __restrict__ cnt) {
    int e = blockIdx.x * blockDim.x + threadIdx.x;
    if (e < E) atomicAdd(&cnt[ei[E + e]], 1);
}

__global__ void scan_kernel(int NN, const int* __restrict__ cnt, int* __restrict__ offsets) {
    __shared__ int tsum[1024];
    int tid = threadIdx.x;
    int per = (NN + 1023) / 1024;
    int lo = tid * per, hi = min(lo + per, NN);
    int s = 0;
    for (int i = lo; i < hi; i++) s += cnt[i];
    tsum[tid] = s;
    __syncthreads();
    for (int off = 1; off < 1024; off <<= 1) {
        int v = (tid >= off) ? tsum[tid - off] : 0;
        __syncthreads();
        tsum[tid] += v;
        __syncthreads();
    }
    int run = (tid > 0) ? tsum[tid - 1] : 0;
    for (int i = lo; i < hi; i++) { offsets[i] = run; run += cnt[i]; }
}

__global__ void scatter_kernel(int E, const int* __restrict__ ei,
                               const int* __restrict__ offsets,
                               int* __restrict__ fill, int* __restrict__ srcs) {
    int e = blockIdx.x * blockDim.x + threadIdx.x;
    if (e >= E) return;
    int d = ei[E + e];
    int pos = offsets[d] + atomicAdd(&fill[d], 1);
    srcs[pos] = ei[e];
}

// ----------------------------------------------------------------------------
// Repack W1 [66, 8*128] into W1p [8][KP=80][128], zero-padding rows 66..79.
// ----------------------------------------------------------------------------
__global__ void w1pad_kernel(const float* __restrict__ W1, float* __restrict__ W1p) {
    int i = blockIdx.x * 256 + threadIdx.x;
    if (i >= H1 * KP * C1) return;
    int c = i % C1;
    int k = (i / C1) % KP;
    int h = i / (C1 * KP);
    W1p[i] = (k < F_IN) ? W1[(size_t)k * D1 + h * C1 + c] : 0.f;
}

// ----------------------------------------------------------------------------
// Layer-1 attention vector projection: qs[h,k] = sum_c W1[k, h*128+c]*as1[h,c]
// ----------------------------------------------------------------------------
__global__ void proj1_kernel(const float* __restrict__ W1,
                             const float* __restrict__ as1,
                             const float* __restrict__ ad1,
                             float* __restrict__ qs, float* __restrict__ qd) {
    int gw = (blockIdx.x * blockDim.x + threadIdx.x) >> 5;
    int lane = threadIdx.x & 31;
    if (gw >= H1 * F_IN) return;
    int h = gw / F_IN, k = gw % F_IN;
    const float* wrow = W1 + (size_t)k * D1 + h * C1;
    const float* av = as1 + h * C1;
    const float* dv = ad1 + h * C1;
    float s = 0.f, d = 0.f;
#pragma unroll
    for (int c = lane; c < C1; c += 32) {
        float wv = wrow[c];
        s += wv * av[c];
        d += wv * dv[c];
    }
#pragma unroll
    for (int off = 16; off > 0; off >>= 1) {
        s += __shfl_down_sync(0xffffffffu, s, off);
        d += __shfl_down_sync(0xffffffffu, d, off);
    }
    if (lane == 0) { qs[gw] = s; qd[gw] = d; }
}

// ----------------------------------------------------------------------------
// Layer-1 es/ed directly from x: es[n,h] = <x[n,:], qs[h,:]> (K = 66).
// ----------------------------------------------------------------------------
__global__ void esed1_kernel(int NN, const float* __restrict__ x,
                             const float* __restrict__ qs,
                             const float* __restrict__ qd,
                             float* __restrict__ es, float* __restrict__ ed) {
    __shared__ float xs[32][F_IN + 2];
    __shared__ float qss[H1 * F_IN], qds[H1 * F_IN];
    int tid = threadIdx.x;
    for (int i = tid; i < H1 * F_IN; i += 256) { qss[i] = qs[i]; qds[i] = qd[i]; }
    int n0 = blockIdx.x * 32;
    for (int i = tid; i < 32 * F_IN; i += 256) {
        int r = i / F_IN, c = i % F_IN;
        int n = n0 + r;
        xs[r][c] = (n < NN) ? x[(size_t)n * F_IN + c] : 0.f;
    }
    __syncthreads();
    int r = tid >> 3, h = tid & 7;
    int n = n0 + r;
    if (n < NN) {
        float s = 0.f, d = 0.f;
#pragma unroll
        for (int k = 0; k < F_IN; k++) {
            float xv = xs[r][k];
            s += xv * qss[h * F_IN + k];
            d += xv * qds[h * F_IN + k];
        }
        es[n * H1 + h] = s;
        ed[n * H1 + h] = d;
    }
}

// ----------------------------------------------------------------------------
// Layer-1 CSR aggregation with fused softmax. One warp per dst node.
// aggX[d, h*KP + 0:66] = (Σ_e w_eh x[src_e]) / (Σ_e w_eh), pad [66,80) zeroed.
// Lane j covers x floats [2j, 2j+1]; lane 0 also covers [64, 65].
// ----------------------------------------------------------------------------
__global__ void agg1_csr_kernel(int NN, const float* __restrict__ x,
                                const float* __restrict__ es,
                                const float* __restrict__ ed,
                                const int* __restrict__ offsets,
                                const int* __restrict__ cnt,
                                const int* __restrict__ srcs,
                                float* __restrict__ aggX) {
    int d = (blockIdx.x * blockDim.x + threadIdx.x) >> 5;
    int lane = threadIdx.x & 31;
    if (d >= NN) return;

    float edv = (lane < H1) ? ed[d * H1 + lane] : 0.f;

    float2 acc[H1];
    float2 tac[H1];
    float zac[H1];
#pragma unroll
    for (int h = 0; h < H1; h++) {
        acc[h] = make_float2(0.f, 0.f);
        tac[h] = make_float2(0.f, 0.f);
        zac[h] = 0.f;
    }

    const int beg = offsets[d];
    const int deg = cnt[d];

    for (int j = 0; j <= deg; j++) {
        int s = (j < deg) ? srcs[beg + j] : d;   // last iteration = self loop
        float esv = (lane < H1) ? es[s * H1 + lane] : 0.f;
        float v8 = esv + edv;
        v8 = v8 > 0.f ? v8 : 0.2f * v8;
        float w8 = __expf(v8);
        const float2* xr = reinterpret_cast<const float2*>(x) + (size_t)s * (F_IN / 2);
        float2 v = xr[lane];
        float2 vt = (lane == 0) ? xr[32] : make_float2(0.f, 0.f);
#pragma unroll
        for (int h = 0; h < H1; h++) {
            float w = __shfl_sync(0xffffffffu, w8, h);
            acc[h].x += w * v.x;  acc[h].y += w * v.y;
            tac[h].x += w * vt.x; tac[h].y += w * vt.y;
            zac[h] += w;
        }
    }

    float* obase = aggX + (size_t)d * XHP;
#pragma unroll
    for (int h = 0; h < H1; h++) {
        float inv = 1.f / (zac[h] + 1e-16f);
        float2* o2 = reinterpret_cast<float2*>(obase + h * KP);
        o2[lane] = make_float2(acc[h].x * inv, acc[h].y * inv);
        if (lane == 0) o2[32] = make_float2(tac[h].x * inv, tac[h].y * inv);
        if (lane < 7)  o2[33 + lane] = make_float2(0.f, 0.f);  // pad [66,80)
    }
}

// ----------------------------------------------------------------------------
// Layers 2/3 CSR aggregation with fused softmax (+ optional bias+ELU).
// One warp per dst. C=128: float4/lane. C=64: float2/lane.
// ----------------------------------------------------------------------------
template <int C, bool BIAS_ELU>
__global__ void agg_csr_kernel(int NN, const float* __restrict__ hfeat,
                               const float* __restrict__ es,
                               const float* __restrict__ ed,
                               const int* __restrict__ offsets,
                               const int* __restrict__ cnt,
                               const int* __restrict__ srcs,
                               const float* __restrict__ bias,
                               float* __restrict__ out) {
    int d = (blockIdx.x * blockDim.x + threadIdx.x) >> 5;
    int lane = threadIdx.x & 31;
    if (d >= NN) return;

    float edv = ed[d];
    float z = 0.f;
    const int beg = offsets[d];
    const int deg = cnt[d];

    if (C == 128) {
        float4 acc = make_float4(0.f, 0.f, 0.f, 0.f);
        for (int j = 0; j <= deg; j++) {
            int s = (j < deg) ? srcs[beg + j] : d;
            float v = es[s] + edv;
            v = v > 0.f ? v : 0.2f * v;
            float w = __expf(v);
            float4 hv = reinterpret_cast<const float4*>(hfeat)[(size_t)s * 32 + lane];
            acc.x += w * hv.x; acc.y += w * hv.y;
            acc.z += w * hv.z; acc.w += w * hv.w;
            z += w;
        }
        float inv = 1.f / (z + 1e-16f);
        float4 r = make_float4(acc.x * inv, acc.y * inv, acc.z * inv, acc.w * inv);
        if (BIAS_ELU) {
            float4 b = reinterpret_cast<const float4*>(bias)[lane];
            r.x += b.x; r.y += b.y; r.z += b.z; r.w += b.w;
            r.x = r.x > 0.f ? r.x : expm1f(r.x);
            r.y = r.y > 0.f ? r.y : expm1f(r.y);
            r.z = r.z > 0.f ? r.z : expm1f(r.z);
            r.w = r.w > 0.f ? r.w : expm1f(r.w);
        }
        reinterpret_cast<float4*>(out)[(size_t)d * 32 + lane] = r;
    } else {  // C == 64
        float2 acc = make_float2(0.f, 0.f);
        for (int j = 0; j <= deg; j++) {
            int s = (j < deg) ? srcs[beg + j] : d;
            float v = es[s] + edv;
            v = v > 0.f ? v : 0.2f * v;
            float w = __expf(v);
            float2 hv = reinterpret_cast<const float2*>(hfeat)[(size_t)s * 32 + lane];
            acc.x += w * hv.x; acc.y += w * hv.y;
            z += w;
        }
        float inv = 1.f / (z + 1e-16f);
        float2 r = make_float2(acc.x * inv, acc.y * inv);
        if (BIAS_ELU) {
            float2 b = reinterpret_cast<const float2*>(bias)[lane];
            r.x += b.x; r.y += b.y;
            r.x = r.x > 0.f ? r.x : expm1f(r.x);
            r.y = r.y > 0.f ? r.y : expm1f(r.y);
        }
        reinterpret_cast<float2*>(out)[(size_t)d * 32 + lane] = r;
    }
}

// ----------------------------------------------------------------------------
// Attention coefficients from features (layers 2/3): one warp per (node,head).
// ----------------------------------------------------------------------------
template <int C, int H>
__global__ void esed_kernel(int NN, const float* __restrict__ h,
                            const float* __restrict__ as,
                            const float* __restrict__ ad,
                            float* __restrict__ es, float* __restrict__ ed) {
    int gw = (blockIdx.x * blockDim.x + threadIdx.x) >> 5;
    int lane = threadIdx.x & 31;
    if (gw >= NN * H) return;
    int n = gw / H, hh = gw % H;
    const float* row = h + (size_t)n * (H * C) + hh * C;
    const float* av = as + hh * C;
    const float* dv = ad + hh * C;
    float s = 0.f, d = 0.f;
#pragma unroll
    for (int c = lane; c < C; c += 32) {
        float v = row[c];
        s += v * av[c];
        d += v * dv[c];
    }
#pragma unroll
    for (int off = 16; off > 0; off >>= 1) {
        s += __shfl_down_sync(0xffffffffu, s, off);
        d += __shfl_down_sync(0xffffffffu, d, off);
    }
    if (lane == 0) { es[gw] = s; ed[gw] = d; }
}

// ----------------------------------------------------------------------------
// Final: per node, ELU(agg3 + b3) . Wr + br -> sigmoid. One warp per node.
// ----------------------------------------------------------------------------
__global__ void final_kernel(int NN, const float* __restrict__ agg3,
                             const float* __restrict__ b3,
                             const float* __restrict__ Wr,
                             const float* __restrict__ br,
                             float* __restrict__ out) {
    int n = (blockIdx.x * blockDim.x + threadIdx.x) >> 5;
    int lane = threadIdx.x & 31;
    if (n >= NN) return;
    const float* row = agg3 + (size_t)n * D3;
    float acc = 0.f;
#pragma unroll
    for (int j = lane; j < D3; j += 32) {
        float v = row[j] + b3[j];
        v = v > 0.f ? v : expm1f(v);
        acc += v * Wr[j];
    }
#pragma unroll
    for (int off = 16; off > 0; off >>= 1)
        acc += __shfl_down_sync(0xffffffffu, acc, off);
    if (lane == 0)
        out[n] = 1.f / (1.f + expf(-(acc + br[0])));
}

// ----------------------------------------------------------------------------
// Host launcher
// ----------------------------------------------------------------------------
static inline int ceil_div(int a, int b) { return (a + b - 1) / b; }

extern "C" void kernel_launch(void* const* d_in, const int* in_sizes, int n_in,
                              void* d_out, int out_size) {
    const float* x   = (const float*)d_in[0];
    const int*   ei  = (const int*)d_in[1];   // int32 (JAX x64 disabled)
    const float* W1  = (const float*)d_in[2];
    const float* as1 = (const float*)d_in[3];
    const float* ad1 = (const float*)d_in[4];
    const float* b1  = (const float*)d_in[5];
    const float* W2  = (const float*)d_in[6];
    const float* as2 = (const float*)d_in[7];
    const float* ad2 = (const float*)d_in[8];
    const float* b2  = (const float*)d_in[9];
    const float* W3  = (const float*)d_in[10];
    const float* as3 = (const float*)d_in[11];
    const float* ad3 = (const float*)d_in[12];
    const float* b3  = (const float*)d_in[13];
    const float* Wr  = (const float*)d_in[14];
    const float* br  = (const float*)d_in[15];
    float* out = (float*)d_out;

    const int N = in_sizes[0] / F_IN;
    const int E = in_sizes[1] / 2;

    float *aggX, *agg1, *h2, *agg2, *h3, *agg3, *W1p;
    float *qs1, *qd1, *es1, *ed1, *es2, *ed2, *es3, *ed3;
    int *cntfill, *offsets, *srcs;
    cudaGetSymbolAddress((void**)&aggX, g_aggX);
    cudaGetSymbolAddress((void**)&agg1, g_agg1);
    cudaGetSymbolAddress((void**)&h2, g_h2);
    cudaGetSymbolAddress((void**)&agg2, g_agg2);
    cudaGetSymbolAddress((void**)&h3, g_h3);
    cudaGetSymbolAddress((void**)&agg3, g_agg3);
    cudaGetSymbolAddress((void**)&W1p, g_W1p);
    cudaGetSymbolAddress((void**)&qs1, g_qs1);
    cudaGetSymbolAddress((void**)&qd1, g_qd1);
    cudaGetSymbolAddress((void**)&es1, g_es1);
    cudaGetSymbolAddress((void**)&ed1, g_ed1);
    cudaGetSymbolAddress((void**)&es2, g_es2);
    cudaGetSymbolAddress((void**)&ed2, g_ed2);
    cudaGetSymbolAddress((void**)&es3, g_es3);
    cudaGetSymbolAddress((void**)&ed3, g_ed3);
    cudaGetSymbolAddress((void**)&cntfill, g_cntfill);
    cudaGetSymbolAddress((void**)&offsets, g_offsets);
    cudaGetSymbolAddress((void**)&srcs, g_srcs);

    int* cnt  = cntfill;
    int* fill = cntfill + MAXN;

    // ---------------- CSR build (by destination) ----------------------------
    cudaMemsetAsync(cntfill, 0, 2 * MAXN * sizeof(int));
    hist_kernel<<<ceil_div(E, 256), 256>>>(E, ei, cnt);
    scan_kernel<<<1, 1024>>>(N, cnt, offsets);
    scatter_kernel<<<ceil_div(E, 256), 256>>>(E, ei, offsets, fill, srcs);

    // ---------------- Layer 1 (x-space aggregation; h1 never materialized) --
    w1pad_kernel<<<ceil_div(H1 * KP * C1, 256), 256>>>(W1, W1p);
    proj1_kernel<<<ceil_div(H1 * F_IN * 32, 256), 256>>>(W1, as1, ad1, qs1, qd1);
    esed1_kernel<<<ceil_div(N, 32), 256>>>(N, x, qs1, qd1, es1, ed1);
    agg1_csr_kernel<<<ceil_div(N * 32, 256), 256>>>(
        N, x, es1, ed1, offsets, cnt, srcs, aggX);
    {
        // per-head block-diagonal GEMM with fused bias+ELU (pipelined, K padded)
        dim3 grid(1, ceil_div(N, 128), H1);
        tf32_gemm_pipe_kernel<128, 128, 16, 64, 32, true><<<grid, 256>>>(
            N, C1, KP,
            aggX, XHP, (long long)KP,
            W1p, C1, (long long)KP * C1,
            agg1, D1, (long long)C1,
            b1);
    }

    // ---------------- Layer 2: 1024 -> 128 ----------------------------------
    {
        dim3 grid(1, ceil_div(N, 128), 1);
        tf32_gemm_pipe_kernel<128, 128, 16, 64, 32, false><<<grid, 256>>>(
            N, D2, D1, agg1, D1, 0, W2, D2, 0, h2, D2, 0, nullptr);
    }
    esed_kernel<D2, 1><<<ceil_div(N * 32, 256), 256>>>(N, h2, as2, ad2, es2, ed2);
    agg_csr_kernel<D2, true><<<ceil_div(N * 32, 256), 256>>>(
        N, h2, es2, ed2, offsets, cnt, srcs, b2, agg2);

    // ---------------- Layer 3: 128 -> 64 -------------------------------------
    {
        dim3 grid(1, ceil_div(N, 128), 1);
        tf32_gemm_pipe_kernel<128, 64, 16, 64, 16, false><<<grid, 256>>>(
            N, D3, D2, agg2, D2, 0, W3, D3, 0, h3, D3, 0, nullptr);
    }
    esed_kernel<D3, 1><<<ceil_div(N * 32, 256), 256>>>(N, h3, as3, ad3, es3, ed3);
    agg_csr_kernel<D3, false><<<ceil_div(N * 32, 256), 256>>>(
        N, h3, es3, ed3, offsets, cnt, srcs, nullptr, agg3);

    // ---------------- Regressor (fused bias+ELU+dot+sigmoid) ----------------
    final_kernel<<<ceil_div(N * 32, 256), 256>>>(N, agg3, b3, Wr, br, out);
}

// round 14
// speedup vs baseline: 4.2763x; 1.0116x over previous
#include <cuda_runtime.h>
#include <cuda_bf16.h>
#include <cstdint>
#include <math.h>

// ----------------------------------------------------------------------------
// Problem constants (shapes fixed by the reference)
// ----------------------------------------------------------------------------
#define MAXN 50000
#define MAXE 200000
#define F_IN 66
#define H1 8
#define C1 128
#define D1 (H1 * C1)   // 1024
#define D2 128
#define D3 64
#define KP 80          // K=66 padded to 80 (=5*16) for the pipelined head GEMM
#define XHP (H1 * KP)  // 640 : per-node width of padded x-space agg buffer

// ----------------------------------------------------------------------------
// Device scratch (static globals: allocation-free)
// ----------------------------------------------------------------------------
__device__ float g_aggX[(size_t)MAXN * XHP];  // layer-1 x-space agg (normalized)
__device__ float g_agg1[(size_t)MAXN * D1];   // layer-1 output (post bias+ELU)
__device__ float g_h2[(size_t)MAXN * D2];
__device__ float g_agg2[(size_t)MAXN * D2];   // post bias+ELU (fused)
__device__ float g_h3[(size_t)MAXN * D3];
__device__ float g_agg3[(size_t)MAXN * D3];
__device__ float g_W1p[H1 * KP * C1];         // W1 repacked per-head, K padded

__device__ float g_qs1[H1 * F_IN], g_qd1[H1 * F_IN];
__device__ float g_es1[MAXN * H1], g_ed1[MAXN * H1];
__device__ float g_es2[MAXN], g_ed2[MAXN];
__device__ float g_es3[MAXN], g_ed3[MAXN];

// CSR by destination (self-loops handled implicitly, not stored)
__device__ int g_cntfill[2 * MAXN];           // [0:N) cnt, [N:2N) fill — memset 0
__device__ int g_offsets[MAXN];
__device__ int g_srcs[MAXE];

// ----------------------------------------------------------------------------
// cp.async helpers
// ----------------------------------------------------------------------------
__device__ __forceinline__ void cp_async16(uint32_t smem_dst, const void* gsrc, int sz) {
    asm volatile("cp.async.cg.shared.global [%0], [%1], 16, %2;\n"
                 :: "r"(smem_dst), "l"(gsrc), "r"(sz));
}
__device__ __forceinline__ void cp_commit() {
    asm volatile("cp.async.commit_group;\n");
}
template <int NG>
__device__ __forceinline__ void cp_wait() {
    asm volatile("cp.async.wait_group %0;\n" :: "n"(NG));
}

// ----------------------------------------------------------------------------
// Multi-stage cp.async pipelined TF32 GEMM: C[M,N] = A[M,K] @ B[K,N].
// STAGES-deep smem pipeline (dynamic smem; host sets the attribute).
// Tail uses empty commit_groups so wait_group<STAGES-2> keeps a constant
// pending-count and tile t's group is always complete before compute.
// blockIdx.z selects a slice; optional fused bias+ELU epilogue.
// ----------------------------------------------------------------------------
template <int BM, int BN, int BK, int WM, int WN, int STAGES, bool BIAS_ELU>
__global__ void tf32_gemm_pipe_kernel(int M, int N, int K,
        const float* __restrict__ A, int lda, long long strideAz,
        const float* __restrict__ B, int ldb, long long strideBz,
        float* __restrict__ C, int ldc, long long strideCz,
        const float* __restrict__ bias) {
    constexpr int WARPS_M = BM / WM, WARPS_N = BN / WN;
    constexpr int NT = 32 * WARPS_M * WARPS_N;
    constexpr int MI = WM / 16, NI = WN / 8;
    constexpr int AS = BK + 4;
    constexpr int BS = BN + 8;
    constexpr int A_CHUNKS = BM * (BK / 4);
    constexpr int B_CHUNKS = BK * (BN / 4);
    constexpr int A_FLOATS = BM * AS;
    constexpr int B_FLOATS = BK * BS;

    extern __shared__ float smem[];
    float* Asm = smem;                       // [STAGES][BM][AS]
    float* Bsm = smem + STAGES * A_FLOATS;   // [STAGES][BK][BS]

    const int tid = threadIdx.x;
    const int wid = tid >> 5, lane = tid & 31;
    const int l4 = lane & 3, l8 = lane >> 2;
    const int wm = (wid / WARPS_N) * WM;
    const int wn = (wid % WARPS_N) * WN;
    const int bm = blockIdx.y * BM;

    A += (long long)blockIdx.z * strideAz;
    B += (long long)blockIdx.z * strideBz;
    C += (long long)blockIdx.z * strideCz;
    if (BIAS_ELU) bias += (long long)blockIdx.z * (long long)N;

    float acc[MI][NI][4];
#pragma unroll
    for (int i = 0; i < MI; i++)
#pragma unroll
        for (int j = 0; j < NI; j++)
#pragma unroll
            for (int q = 0; q < 4; q++) acc[i][j][q] = 0.f;

    const uint32_t a_base = (uint32_t)__cvta_generic_to_shared(Asm);
    const uint32_t b_base = (uint32_t)__cvta_generic_to_shared(Bsm);

    auto issue = [&](int s, int k0) {
#pragma unroll
        for (int j = tid; j < A_CHUNKS; j += NT) {
            int m = j / (BK / 4), cq = j % (BK / 4);
            int gm = bm + m;
            const float* src = A + (size_t)gm * lda + k0 + 4 * cq;
            uint32_t dst = a_base + (s * A_FLOATS + m * AS + 4 * cq) * 4;
            cp_async16(dst, src, gm < M ? 16 : 0);
        }
#pragma unroll
        for (int j = tid; j < B_CHUNKS; j += NT) {
            int r = j / (BN / 4), cq = j % (BN / 4);
            const float* src = B + (size_t)(k0 + r) * ldb + 4 * cq;
            uint32_t dst = b_base + (s * B_FLOATS + r * BS + 4 * cq) * 4;
            cp_async16(dst, src, 16);
        }
        cp_commit();
    };

    const int KT = K / BK;

    // prologue: stages 0..STAGES-2 (empty groups past KT keep the count fixed)
#pragma unroll
    for (int s = 0; s < STAGES - 1; s++) {
        if (s < KT) issue(s, s * BK); else cp_commit();
    }

    for (int t = 0; t < KT; t++) {
        int tn = t + STAGES - 1;
        if (tn < KT) issue(tn % STAGES, tn * BK); else cp_commit();
        cp_wait<STAGES - 2>();
        __syncthreads();
        const int s = t % STAGES;
        const float* As_s = Asm + s * A_FLOATS;
        const float* Bs_s = Bsm + s * B_FLOATS;

#pragma unroll
        for (int kk = 0; kk < BK; kk += 8) {
            uint32_t bfr[NI][2];
#pragma unroll
            for (int ni = 0; ni < NI; ni++) {
                bfr[ni][0] = __float_as_uint(Bs_s[(kk + l4) * BS + wn + ni * 8 + l8]);
                bfr[ni][1] = __float_as_uint(Bs_s[(kk + l4 + 4) * BS + wn + ni * 8 + l8]);
            }
#pragma unroll
            for (int mi = 0; mi < MI; mi++) {
                const int m0 = wm + mi * 16 + l8;
                const int m1 = m0 + 8;
                uint32_t a0 = __float_as_uint(As_s[m0 * AS + kk + l4]);
                uint32_t a1 = __float_as_uint(As_s[m1 * AS + kk + l4]);
                uint32_t a2 = __float_as_uint(As_s[m0 * AS + kk + l4 + 4]);
                uint32_t a3 = __float_as_uint(As_s[m1 * AS + kk + l4 + 4]);
#pragma unroll
                for (int ni = 0; ni < NI; ni++) {
                    asm volatile(
                        "mma.sync.aligned.m16n8k8.row.col.f32.tf32.tf32.f32 "
                        "{%0,%1,%2,%3}, {%4,%5,%6,%7}, {%8,%9}, {%0,%1,%2,%3};"
                        : "+f"(acc[mi][ni][0]), "+f"(acc[mi][ni][1]),
                          "+f"(acc[mi][ni][2]), "+f"(acc[mi][ni][3])
                        : "r"(a0), "r"(a1), "r"(a2), "r"(a3),
                          "r"(bfr[ni][0]), "r"(bfr[ni][1]));
                }
            }
        }
        __syncthreads();
    }

#pragma unroll
    for (int mi = 0; mi < MI; mi++) {
        int r0 = bm + wm + mi * 16 + l8;
#pragma unroll
        for (int ni = 0; ni < NI; ni++) {
            int c0 = wn + ni * 8 + l4 * 2;
#pragma unroll
            for (int q = 0; q < 4; q++) {
                int gr = r0 + ((q >= 2) ? 8 : 0);
                int gc = c0 + (q & 1);
                if (gr < M) {
                    float v = acc[mi][ni][q];
                    if (BIAS_ELU) {
                        v += bias[gc];
                        v = v > 0.f ? v : expm1f(v);
                    }
                    C[(size_t)gr * ldc + gc] = v;
                }
            }
        }
    }
}

// smem bytes for a given instantiation
template <int BM, int BN, int BK, int STAGES>
constexpr int pipe_smem_bytes() {
    return STAGES * (BM * (BK + 4) + BK * (BN + 8)) * 4;
}

// ----------------------------------------------------------------------------
// CSR build: histogram -> single-block scan -> scatter
// ----------------------------------------------------------------------------
__global__ void hist_kernel(int E, const int* __restrict__ ei, int* __restrict__ cnt) {
    int e = blockIdx.x * blockDim.x + threadIdx.x;
    if (e < E) atomicAdd(&cnt[ei[E + e]], 1);
}

__global__ void scan_kernel(int NN, const int* __restrict__ cnt, int* __restrict__ offsets) {
    __shared__ int tsum[1024];
    int tid = threadIdx.x;
    int per = (NN + 1023) / 1024;
    int lo = tid * per, hi = min(lo + per, NN);
    int s = 0;
    for (int i = lo; i < hi; i++) s += cnt[i];
    tsum[tid] = s;
    __syncthreads();
    for (int off = 1; off < 1024; off <<= 1) {
        int v = (tid >= off) ? tsum[tid - off] : 0;
        __syncthreads();
        tsum[tid] += v;
        __syncthreads();
    }
    int run = (tid > 0) ? tsum[tid - 1] : 0;
    for (int i = lo; i < hi; i++) { offsets[i] = run; run += cnt[i]; }
}

__global__ void scatter_kernel(int E, const int* __restrict__ ei,
                               const int* __restrict__ offsets,
                               int* __restrict__ fill, int* __restrict__ srcs) {
    int e = blockIdx.x * blockDim.x + threadIdx.x;
    if (e >= E) return;
    int d = ei[E + e];
    int pos = offsets[d] + atomicAdd(&fill[d], 1);
    srcs[pos] = ei[e];
}

// ----------------------------------------------------------------------------
// Repack W1 [66, 8*128] into W1p [8][KP=80][128], zero-padding rows 66..79.
// ----------------------------------------------------------------------------
__global__ void w1pad_kernel(const float* __restrict__ W1, float* __restrict__ W1p) {
    int i = blockIdx.x * 256 + threadIdx.x;
    if (i >= H1 * KP * C1) return;
    int c = i % C1;
    int k = (i / C1) % KP;
    int h = i / (C1 * KP);
    W1p[i] = (k < F_IN) ? W1[(size_t)k * D1 + h * C1 + c] : 0.f;
}

// ----------------------------------------------------------------------------
// Layer-1 attention vector projection: qs[h,k] = sum_c W1[k, h*128+c]*as1[h,c]
// ----------------------------------------------------------------------------
__global__ void proj1_kernel(const float* __restrict__ W1,
                             const float* __restrict__ as1,
                             const float* __restrict__ ad1,
                             float* __restrict__ qs, float* __restrict__ qd) {
    int gw = (blockIdx.x * blockDim.x + threadIdx.x) >> 5;
    int lane = threadIdx.x & 31;
    if (gw >= H1 * F_IN) return;
    int h = gw / F_IN, k = gw % F_IN;
    const float* wrow = W1 + (size_t)k * D1 + h * C1;
    const float* av = as1 + h * C1;
    const float* dv = ad1 + h * C1;
    float s = 0.f, d = 0.f;
#pragma unroll
    for (int c = lane; c < C1; c += 32) {
        float wv = wrow[c];
        s += wv * av[c];
        d += wv * dv[c];
    }
#pragma unroll
    for (int off = 16; off > 0; off >>= 1) {
        s += __shfl_down_sync(0xffffffffu, s, off);
        d += __shfl_down_sync(0xffffffffu, d, off);
    }
    if (lane == 0) { qs[gw] = s; qd[gw] = d; }
}

// ----------------------------------------------------------------------------
// Layer-1 es/ed directly from x: es[n,h] = <x[n,:], qs[h,:]> (K = 66).
// ----------------------------------------------------------------------------
__global__ void esed1_kernel(int NN, const float* __restrict__ x,
                             const float* __restrict__ qs,
                             const float* __restrict__ qd,
                             float* __restrict__ es, float* __restrict__ ed) {
    __shared__ float xs[32][F_IN + 2];
    __shared__ float qss[H1 * F_IN], qds[H1 * F_IN];
    int tid = threadIdx.x;
    for (int i = tid; i < H1 * F_IN; i += 256) { qss[i] = qs[i]; qds[i] = qd[i]; }
    int n0 = blockIdx.x * 32;
    for (int i = tid; i < 32 * F_IN; i += 256) {
        int r = i / F_IN, c = i % F_IN;
        int n = n0 + r;
        xs[r][c] = (n < NN) ? x[(size_t)n * F_IN + c] : 0.f;
    }
    __syncthreads();
    int r = tid >> 3, h = tid & 7;
    int n = n0 + r;
    if (n < NN) {
        float s = 0.f, d = 0.f;
#pragma unroll
        for (int k = 0; k < F_IN; k++) {
            float xv = xs[r][k];
            s += xv * qss[h * F_IN + k];
            d += xv * qds[h * F_IN + k];
        }
        es[n * H1 + h] = s;
        ed[n * H1 + h] = d;
    }
}

// ----------------------------------------------------------------------------
// Layer-1 CSR aggregation with fused softmax. One warp per dst node.
// ----------------------------------------------------------------------------
__global__ void agg1_csr_kernel(int NN, const float* __restrict__ x,
                                const float* __restrict__ es,
                                const float* __restrict__ ed,
                                const int* __restrict__ offsets,
                                const int* __restrict__ cnt,
                                const int* __restrict__ srcs,
                                float* __restrict__ aggX) {
    int d = (blockIdx.x * blockDim.x + threadIdx.x) >> 5;
    int lane = threadIdx.x & 31;
    if (d >= NN) return;

    float edv = (lane < H1) ? ed[d * H1 + lane] : 0.f;

    float2 acc[H1];
    float2 tac[H1];
    float zac[H1];
#pragma unroll
    for (int h = 0; h < H1; h++) {
        acc[h] = make_float2(0.f, 0.f);
        tac[h] = make_float2(0.f, 0.f);
        zac[h] = 0.f;
    }

    const int beg = offsets[d];
    const int deg = cnt[d];

    for (int j = 0; j <= deg; j++) {
        int s = (j < deg) ? srcs[beg + j] : d;   // last iteration = self loop
        float esv = (lane < H1) ? es[s * H1 + lane] : 0.f;
        float v8 = esv + edv;
        v8 = v8 > 0.f ? v8 : 0.2f * v8;
        float w8 = __expf(v8);
        const float2* xr = reinterpret_cast<const float2*>(x) + (size_t)s * (F_IN / 2);
        float2 v = xr[lane];
        float2 vt = (lane == 0) ? xr[32] : make_float2(0.f, 0.f);
#pragma unroll
        for (int h = 0; h < H1; h++) {
            float w = __shfl_sync(0xffffffffu, w8, h);
            acc[h].x += w * v.x;  acc[h].y += w * v.y;
            tac[h].x += w * vt.x; tac[h].y += w * vt.y;
            zac[h] += w;
        }
    }

    float* obase = aggX + (size_t)d * XHP;
#pragma unroll
    for (int h = 0; h < H1; h++) {
        float inv = 1.f / (zac[h] + 1e-16f);
        float2* o2 = reinterpret_cast<float2*>(obase + h * KP);
        o2[lane] = make_float2(acc[h].x * inv, acc[h].y * inv);
        if (lane == 0) o2[32] = make_float2(tac[h].x * inv, tac[h].y * inv);
        if (lane < 7)  o2[33 + lane] = make_float2(0.f, 0.f);  // pad [66,80)
    }
}

// ----------------------------------------------------------------------------
// Layers 2/3 CSR aggregation with fused softmax (+ optional bias+ELU).
// ----------------------------------------------------------------------------
template <int C, bool BIAS_ELU>
__global__ void agg_csr_kernel(int NN, const float* __restrict__ hfeat,
                               const float* __restrict__ es,
                               const float* __restrict__ ed,
                               const int* __restrict__ offsets,
                               const int* __restrict__ cnt,
                               const int* __restrict__ srcs,
                               const float* __restrict__ bias,
                               float* __restrict__ out) {
    int d = (blockIdx.x * blockDim.x + threadIdx.x) >> 5;
    int lane = threadIdx.x & 31;
    if (d >= NN) return;

    float edv = ed[d];
    float z = 0.f;
    const int beg = offsets[d];
    const int deg = cnt[d];

    if (C == 128) {
        float4 acc = make_float4(0.f, 0.f, 0.f, 0.f);
        for (int j = 0; j <= deg; j++) {
            int s = (j < deg) ? srcs[beg + j] : d;
            float v = es[s] + edv;
            v = v > 0.f ? v : 0.2f * v;
            float w = __expf(v);
            float4 hv = reinterpret_cast<const float4*>(hfeat)[(size_t)s * 32 + lane];
            acc.x += w * hv.x; acc.y += w * hv.y;
            acc.z += w * hv.z; acc.w += w * hv.w;
            z += w;
        }
        float inv = 1.f / (z + 1e-16f);
        float4 r = make_float4(acc.x * inv, acc.y * inv, acc.z * inv, acc.w * inv);
        if (BIAS_ELU) {
            float4 b = reinterpret_cast<const float4*>(bias)[lane];
            r.x += b.x; r.y += b.y; r.z += b.z; r.w += b.w;
            r.x = r.x > 0.f ? r.x : expm1f(r.x);
            r.y = r.y > 0.f ? r.y : expm1f(r.y);
            r.z = r.z > 0.f ? r.z : expm1f(r.z);
            r.w = r.w > 0.f ? r.w : expm1f(r.w);
        }
        reinterpret_cast<float4*>(out)[(size_t)d * 32 + lane] = r;
    } else {  // C == 64
        float2 acc = make_float2(0.f, 0.f);
        for (int j = 0; j <= deg; j++) {
            int s = (j < deg) ? srcs[beg + j] : d;
            float v = es[s] + edv;
            v = v > 0.f ? v : 0.2f * v;
            float w = __expf(v);
            float2 hv = reinterpret_cast<const float2*>(hfeat)[(size_t)s * 32 + lane];
            acc.x += w * hv.x; acc.y += w * hv.y;
            z += w;
        }
        float inv = 1.f / (z + 1e-16f);
        float2 r = make_float2(acc.x * inv, acc.y * inv);
        if (BIAS_ELU) {
            float2 b = reinterpret_cast<const float2*>(bias)[lane];
            r.x += b.x; r.y += b.y;
            r.x = r.x > 0.f ? r.x : expm1f(r.x);
            r.y = r.y > 0.f ? r.y : expm1f(r.y);
        }
        reinterpret_cast<float2*>(out)[(size_t)d * 32 + lane] = r;
    }
}

// ----------------------------------------------------------------------------
// Attention coefficients from features (layers 2/3): one warp per (node,head).
// ----------------------------------------------------------------------------
template <int C, int H>
__global__ void esed_kernel(int NN, const float* __restrict__ h,
                            const float* __restrict__ as,
                            const float* __restrict__ ad,
                            float* __restrict__ es, float* __restrict__ ed) {
    int gw = (blockIdx.x * blockDim.x + threadIdx.x) >> 5;
    int lane = threadIdx.x & 31;
    if (gw >= NN * H) return;
    int n = gw / H, hh = gw % H;
    const float* row = h + (size_t)n * (H * C) + hh * C;
    const float* av = as + hh * C;
    const float* dv = ad + hh * C;
    float s = 0.f, d = 0.f;
#pragma unroll
    for (int c = lane; c < C; c += 32) {
        float v = row[c];
        s += v * av[c];
        d += v * dv[c];
    }
#pragma unroll
    for (int off = 16; off > 0; off >>= 1) {
        s += __shfl_down_sync(0xffffffffu, s, off);
        d += __shfl_down_sync(0xffffffffu, d, off);
    }
    if (lane == 0) { es[gw] = s; ed[gw] = d; }
}

// ----------------------------------------------------------------------------
// Final: per node, ELU(agg3 + b3) . Wr + br -> sigmoid. One warp per node.
// ----------------------------------------------------------------------------
__global__ void final_kernel(int NN, const float* __restrict__ agg3,
                             const float* __restrict__ b3,
                             const float* __restrict__ Wr,
                             const float* __restrict__ br,
                             float* __restrict__ out) {
    int n = (blockIdx.x * blockDim.x + threadIdx.x) >> 5;
    int lane = threadIdx.x & 31;
    if (n >= NN) return;
    const float* row = agg3 + (size_t)n * D3;
    float acc = 0.f;
#pragma unroll
    for (int j = lane; j < D3; j += 32) {
        float v = row[j] + b3[j];
        v = v > 0.f ? v : expm1f(v);
        acc += v * Wr[j];
    }
#pragma unroll
    for (int off = 16; off > 0; off >>= 1)
        acc += __shfl_down_sync(0xffffffffu, acc, off);
    if (lane == 0)
        out[n] = 1.f / (1.f + expf(-(acc + br[0])));
}

// ----------------------------------------------------------------------------
// Host launcher
// ----------------------------------------------------------------------------
static inline int ceil_div(int a, int b) { return (a + b - 1) / b; }

extern "C" void kernel_launch(void* const* d_in, const int* in_sizes, int n_in,
                              void* d_out, int out_size) {
    const float* x   = (const float*)d_in[0];
    const int*   ei  = (const int*)d_in[1];   // int32 (JAX x64 disabled)
    const float* W1  = (const float*)d_in[2];
    const float* as1 = (const float*)d_in[3];
    const float* ad1 = (const float*)d_in[4];
    const float* b1  = (const float*)d_in[5];
    const float* W2  = (const float*)d_in[6];
    const float* as2 = (const float*)d_in[7];
    const float* ad2 = (const float*)d_in[8];
    const float* b2  = (const float*)d_in[9];
    const float* W3  = (const float*)d_in[10];
    const float* as3 = (const float*)d_in[11];
    const float* ad3 = (const float*)d_in[12];
    const float* b3  = (const float*)d_in[13];
    const float* Wr  = (const float*)d_in[14];
    const float* br  = (const float*)d_in[15];
    float* out = (float*)d_out;

    const int N = in_sizes[0] / F_IN;
    const int E = in_sizes[1] / 2;

    float *aggX, *agg1, *h2, *agg2, *h3, *agg3, *W1p;
    float *qs1, *qd1, *es1, *ed1, *es2, *ed2, *es3, *ed3;
    int *cntfill, *offsets, *srcs;
    cudaGetSymbolAddress((void**)&aggX, g_aggX);
    cudaGetSymbolAddress((void**)&agg1, g_agg1);
    cudaGetSymbolAddress((void**)&h2, g_h2);
    cudaGetSymbolAddress((void**)&agg2, g_agg2);
    cudaGetSymbolAddress((void**)&h3, g_h3);
    cudaGetSymbolAddress((void**)&agg3, g_agg3);
    cudaGetSymbolAddress((void**)&W1p, g_W1p);
    cudaGetSymbolAddress((void**)&qs1, g_qs1);
    cudaGetSymbolAddress((void**)&qd1, g_qd1);
    cudaGetSymbolAddress((void**)&es1, g_es1);
    cudaGetSymbolAddress((void**)&ed1, g_ed1);
    cudaGetSymbolAddress((void**)&es2, g_es2);
    cudaGetSymbolAddress((void**)&ed2, g_ed2);
    cudaGetSymbolAddress((void**)&es3, g_es3);
    cudaGetSymbolAddress((void**)&ed3, g_ed3);
    cudaGetSymbolAddress((void**)&cntfill, g_cntfill);
    cudaGetSymbolAddress((void**)&offsets, g_offsets);
    cudaGetSymbolAddress((void**)&srcs, g_srcs);

    int* cnt  = cntfill;
    int* fill = cntfill + MAXN;

    // dynamic smem opt-in for the 4-stage GEMMs (idempotent, host-side)
    constexpr int SM_HEAD = pipe_smem_bytes<128, 128, 16, 4>();
    constexpr int SM_G2   = pipe_smem_bytes<128, 128, 16, 4>();
    constexpr int SM_G3   = pipe_smem_bytes<128, 64, 16, 4>();
    cudaFuncSetAttribute(
        (const void*)tf32_gemm_pipe_kernel<128, 128, 16, 64, 32, 4, true>,
        cudaFuncAttributeMaxDynamicSharedMemorySize, SM_HEAD);
    cudaFuncSetAttribute(
        (const void*)tf32_gemm_pipe_kernel<128, 128, 16, 64, 32, 4, false>,
        cudaFuncAttributeMaxDynamicSharedMemorySize, SM_G2);
    cudaFuncSetAttribute(
        (const void*)tf32_gemm_pipe_kernel<128, 64, 16, 64, 16, 4, false>,
        cudaFuncAttributeMaxDynamicSharedMemorySize, SM_G3);

    // ---------------- CSR build (by destination) ----------------------------
    cudaMemsetAsync(cntfill, 0, 2 * MAXN * sizeof(int));
    hist_kernel<<<ceil_div(E, 256), 256>>>(E, ei, cnt);
    scan_kernel<<<1, 1024>>>(N, cnt, offsets);
    scatter_kernel<<<ceil_div(E, 256), 256>>>(E, ei, offsets, fill, srcs);

    // ---------------- Layer 1 (x-space aggregation; h1 never materialized) --
    w1pad_kernel<<<ceil_div(H1 * KP * C1, 256), 256>>>(W1, W1p);
    proj1_kernel<<<ceil_div(H1 * F_IN * 32, 256), 256>>>(W1, as1, ad1, qs1, qd1);
    esed1_kernel<<<ceil_div(N, 32), 256>>>(N, x, qs1, qd1, es1, ed1);
    agg1_csr_kernel<<<ceil_div(N * 32, 256), 256>>>(
        N, x, es1, ed1, offsets, cnt, srcs, aggX);
    {
        dim3 grid(1, ceil_div(N, 128), H1);
        tf32_gemm_pipe_kernel<128, 128, 16, 64, 32, 4, true>
            <<<grid, 256, SM_HEAD>>>(
            N, C1, KP,
            aggX, XHP, (long long)KP,
            W1p, C1, (long long)KP * C1,
            agg1, D1, (long long)C1,
            b1);
    }

    // ---------------- Layer 2: 1024 -> 128 ----------------------------------
    {
        dim3 grid(1, ceil_div(N, 128), 1);
        tf32_gemm_pipe_kernel<128, 128, 16, 64, 32, 4, false>
            <<<grid, 256, SM_G2>>>(
            N, D2, D1, agg1, D1, 0, W2, D2, 0, h2, D2, 0, nullptr);
    }
    esed_kernel<D2, 1><<<ceil_div(N * 32, 256), 256>>>(N, h2, as2, ad2, es2, ed2);
    agg_csr_kernel<D2, true><<<ceil_div(N * 32, 256), 256>>>(
        N, h2, es2, ed2, offsets, cnt, srcs, b2, agg2);

    // ---------------- Layer 3: 128 -> 64 -------------------------------------
    {
        dim3 grid(1, ceil_div(N, 128), 1);
        tf32_gemm_pipe_kernel<128, 64, 16, 64, 16, 4, false>
            <<<grid, 256, SM_G3>>>(
            N, D3, D2, agg2, D2, 0, W3, D3, 0, h3, D3, 0, nullptr);
    }
    esed_kernel<D3, 1><<<ceil_div(N * 32, 256), 256>>>(N, h3, as3, ad3, es3, ed3);
    agg_csr_kernel<D3, false><<<ceil_div(N * 32, 256), 256>>>(
        N, h3, es3, ed3, offsets, cnt, srcs, nullptr, agg3);

    // ---------------- Regressor (fused bias+ELU+dot+sigmoid) ----------------
    final_kernel<<<ceil_div(N * 32, 256), 256>>>(N, agg3, b3, Wr, br, out);
}

// round 16
// speedup vs baseline: 4.9650x; 1.1611x over previous
#include <cuda_runtime.h>
#include <cuda_fp16.h>
#include <cstdint>
#include <math.h>

// ----------------------------------------------------------------------------
// Problem constants (shapes fixed by the reference)
// ----------------------------------------------------------------------------
#define MAXN 50000
#define MAXE 200000
#define F_IN 66
#define H1 8
#define C1 128
#define D1 (H1 * C1)   // 1024
#define D2 128
#define D3 64
#define KP 96          // K=66 padded to 96 (=3*32) for the fp16 head GEMM
#define XHP (H1 * KP)  // 768 : per-node width of padded x-space agg buffer

// ----------------------------------------------------------------------------
// Device scratch (static globals: allocation-free)
// ----------------------------------------------------------------------------
__device__ __half g_aggX[(size_t)MAXN * XHP];  // layer-1 x-space agg (normalized)
__device__ __half g_agg1[(size_t)MAXN * D1];   // layer-1 output (post bias+ELU)
__device__ float  g_h2[(size_t)MAXN * D2];
__device__ __half g_agg2[(size_t)MAXN * D2];   // post bias+ELU (fused)
__device__ float  g_h3[(size_t)MAXN * D3];
__device__ float  g_agg3[(size_t)MAXN * D3];
__device__ __half g_W1pt[H1 * C1 * KP];        // W1 per-head, transposed [h][c][k]
__device__ __half g_W2t[D2 * D1];              // W2 transposed [n][k]
__device__ __half g_W3t[D3 * D2];              // W3 transposed [n][k]

__device__ float g_qs1[H1 * F_IN], g_qd1[H1 * F_IN];
__device__ float g_es1[MAXN * H1], g_ed1[MAXN * H1];
__device__ float g_es2[MAXN], g_ed2[MAXN];
__device__ float g_es3[MAXN], g_ed3[MAXN];

// CSR by destination (self-loops handled implicitly, not stored)
__device__ int g_cntfill[2 * MAXN];           // [0:N) cnt, [N:2N) fill — memset 0
__device__ int g_offsets[MAXN];
__device__ int g_srcs[MAXE];

// ----------------------------------------------------------------------------
// cp.async helpers
// ----------------------------------------------------------------------------
__device__ __forceinline__ void cp_async16(uint32_t smem_dst, const void* gsrc, int sz) {
    asm volatile("cp.async.cg.shared.global [%0], [%1], 16, %2;\n"
                 :: "r"(smem_dst), "l"(gsrc), "r"(sz));
}
__device__ __forceinline__ void cp_commit() {
    asm volatile("cp.async.commit_group;\n");
}
template <int NG>
__device__ __forceinline__ void cp_wait() {
    asm volatile("cp.async.wait_group %0;\n" :: "n"(NG));
}

// ----------------------------------------------------------------------------
// Multi-stage cp.async pipelined FP16 GEMM (fp32 accumulate):
//   C[M,N] = A[M,K] @ B[K,N],  B passed TRANSPOSED as Bt[N][K].
// Both smem tiles are K-contiguous: Asm[m][k], Bsm[n][k], stride BK+8 halves
// (conflict-free for the m16n8k16 fragment pattern: banks row*20+l4 distinct).
// Every fragment register is one LDS.32 of a half2.
// blockIdx.z selects a slice; optional fused bias+ELU; fp16 or fp32 output.
// Requires K % BK == 0, N == BN, lda/ldb in halves, 16B-aligned rows.
// ----------------------------------------------------------------------------
template <int BM, int BN, int BK, int WM, int WN, int STAGES,
          bool BIAS_ELU, bool OUT_HALF>
__global__ void h16_gemm_pipe_kernel(int M, int N, int K,
        const __half* __restrict__ A, int lda, long long strideAz,
        const __half* __restrict__ Bt, int ldb, long long strideBz,
        void* __restrict__ Cv, int ldc, long long strideCz,
        const float* __restrict__ bias) {
    constexpr int WARPS_M = BM / WM, WARPS_N = BN / WN;
    constexpr int NT = 32 * WARPS_M * WARPS_N;
    constexpr int MI = WM / 16, NI = WN / 8;
    constexpr int SH = BK + 8;               // halves per smem row
    constexpr int SH2 = SH / 2;              // uint32 per smem row
    constexpr int A_HALVES = BM * SH;
    constexpr int B_HALVES = BN * SH;
    constexpr int A_CHUNKS = BM * (BK / 8);
    constexpr int B_CHUNKS = BN * (BK / 8);

    extern __shared__ __half smem[];
    __half* Asm = smem;                      // [STAGES][BM][SH]
    __half* Bsm = smem + STAGES * A_HALVES;  // [STAGES][BN][SH]

    const int tid = threadIdx.x;
    const int wid = tid >> 5, lane = tid & 31;
    const int l4 = lane & 3, l8 = lane >> 2;
    const int wm = (wid / WARPS_N) * WM;
    const int wn = (wid % WARPS_N) * WN;
    const int bm = blockIdx.y * BM;

    A  += (long long)blockIdx.z * strideAz;
    Bt += (long long)blockIdx.z * strideBz;
    if (BIAS_ELU) bias += (long long)blockIdx.z * (long long)N;

    float acc[MI][NI][4];
#pragma unroll
    for (int i = 0; i < MI; i++)
#pragma unroll
        for (int j = 0; j < NI; j++)
#pragma unroll
            for (int q = 0; q < 4; q++) acc[i][j][q] = 0.f;

    const uint32_t a_base = (uint32_t)__cvta_generic_to_shared(Asm);
    const uint32_t b_base = (uint32_t)__cvta_generic_to_shared(Bsm);

    auto issue = [&](int s, int k0) {
#pragma unroll
        for (int j = tid; j < A_CHUNKS; j += NT) {
            int m = j / (BK / 8), cq = j % (BK / 8);
            int gm = bm + m;
            const __half* src = A + (size_t)gm * lda + k0 + 8 * cq;
            uint32_t dst = a_base + (s * A_HALVES + m * SH + 8 * cq) * 2;
            cp_async16(dst, src, gm < M ? 16 : 0);
        }
#pragma unroll
        for (int j = tid; j < B_CHUNKS; j += NT) {
            int n = j / (BK / 8), cq = j % (BK / 8);
            const __half* src = Bt + (size_t)n * ldb + k0 + 8 * cq;
            uint32_t dst = b_base + (s * B_HALVES + n * SH + 8 * cq) * 2;
            cp_async16(dst, src, 16);
        }
        cp_commit();
    };

    const int KT = K / BK;

    // prologue (empty groups past KT keep the pending-count fixed)
#pragma unroll
    for (int s = 0; s < STAGES - 1; s++) {
        if (s < KT) issue(s, s * BK); else cp_commit();
    }

    for (int t = 0; t < KT; t++) {
        int tn = t + STAGES - 1;
        if (tn < KT) issue(tn % STAGES, tn * BK); else cp_commit();
        cp_wait<STAGES - 2>();
        __syncthreads();
        const int s = t % STAGES;
        const uint32_t* Au = reinterpret_cast<const uint32_t*>(Asm + s * A_HALVES);
        const uint32_t* Bu = reinterpret_cast<const uint32_t*>(Bsm + s * B_HALVES);

#pragma unroll
        for (int kk2 = 0; kk2 < BK / 2; kk2 += 8) {   // k16 step (8 uint32)
            uint32_t bfr[NI][2];
#pragma unroll
            for (int ni = 0; ni < NI; ni++) {
                int n = wn + ni * 8 + l8;
                bfr[ni][0] = Bu[n * SH2 + kk2 + l4];
                bfr[ni][1] = Bu[n * SH2 + kk2 + 4 + l4];
            }
#pragma unroll
            for (int mi = 0; mi < MI; mi++) {
                const int m0 = wm + mi * 16 + l8;
                const int m1 = m0 + 8;
                uint32_t a0 = Au[m0 * SH2 + kk2 + l4];
                uint32_t a1 = Au[m1 * SH2 + kk2 + l4];
                uint32_t a2 = Au[m0 * SH2 + kk2 + 4 + l4];
                uint32_t a3 = Au[m1 * SH2 + kk2 + 4 + l4];
#pragma unroll
                for (int ni = 0; ni < NI; ni++) {
                    asm volatile(
                        "mma.sync.aligned.m16n8k16.row.col.f32.f16.f16.f32 "
                        "{%0,%1,%2,%3}, {%4,%5,%6,%7}, {%8,%9}, {%0,%1,%2,%3};"
                        : "+f"(acc[mi][ni][0]), "+f"(acc[mi][ni][1]),
                          "+f"(acc[mi][ni][2]), "+f"(acc[mi][ni][3])
                        : "r"(a0), "r"(a1), "r"(a2), "r"(a3),
                          "r"(bfr[ni][0]), "r"(bfr[ni][1]));
                }
            }
        }
        __syncthreads();
    }

    // epilogue
    __half* Ch = (__half*)Cv;
    float*  Cf = (float*)Cv;
    if (OUT_HALF) Ch += (long long)blockIdx.z * strideCz;
    else          Cf += (long long)blockIdx.z * strideCz;

#pragma unroll
    for (int mi = 0; mi < MI; mi++) {
        int r0 = bm + wm + mi * 16 + l8;
#pragma unroll
        for (int ni = 0; ni < NI; ni++) {
            int c0 = wn + ni * 8 + l4 * 2;
#pragma unroll
            for (int half_row = 0; half_row < 2; half_row++) {
                int gr = r0 + half_row * 8;
                if (gr >= M) continue;
                float v0 = acc[mi][ni][half_row * 2 + 0];
                float v1 = acc[mi][ni][half_row * 2 + 1];
                if (BIAS_ELU) {
                    v0 += bias[c0];     v1 += bias[c0 + 1];
                    v0 = v0 > 0.f ? v0 : expm1f(v0);
                    v1 = v1 > 0.f ? v1 : expm1f(v1);
                }
                if (OUT_HALF) {
                    *reinterpret_cast<__half2*>(Ch + (size_t)gr * ldc + c0) =
                        __floats2half2_rn(v0, v1);
                } else {
                    Cf[(size_t)gr * ldc + c0] = v0;
                    Cf[(size_t)gr * ldc + c0 + 1] = v1;
                }
            }
        }
    }
}

template <int BM, int BN, int BK, int STAGES>
constexpr int pipe_smem_bytes() {
    return STAGES * (BM + BN) * (BK + 8) * 2;
}

// ----------------------------------------------------------------------------
// CSR build: histogram -> single-block scan -> scatter
// ----------------------------------------------------------------------------
__global__ void hist_kernel(int E, const int* __restrict__ ei, int* __restrict__ cnt) {
    int e = blockIdx.x * blockDim.x + threadIdx.x;
    if (e < E) atomicAdd(&cnt[ei[E + e]], 1);
}

__global__ void scan_kernel(int NN, const int* __restrict__ cnt, int* __restrict__ offsets) {
    __shared__ int tsum[1024];
    int tid = threadIdx.x;
    int per = (NN + 1023) / 1024;
    int lo = tid * per, hi = min(lo + per, NN);
    int s = 0;
    for (int i = lo; i < hi; i++) s += cnt[i];
    tsum[tid] = s;
    __syncthreads();
    for (int off = 1; off < 1024; off <<= 1) {
        int v = (tid >= off) ? tsum[tid - off] : 0;
        __syncthreads();
        tsum[tid] += v;
        __syncthreads();
    }
    int run = (tid > 0) ? tsum[tid - 1] : 0;
    for (int i = lo; i < hi; i++) { offsets[i] = run; run += cnt[i]; }
}

__global__ void scatter_kernel(int E, const int* __restrict__ ei,
                               const int* __restrict__ offsets,
                               int* __restrict__ fill, int* __restrict__ srcs) {
    int e = blockIdx.x * blockDim.x + threadIdx.x;
    if (e >= E) return;
    int d = ei[E + e];
    int pos = offsets[d] + atomicAdd(&fill[d], 1);
    srcs[pos] = ei[e];
}

// ----------------------------------------------------------------------------
// Weight prep: fp16 transposed copies.
// W1pt[h][c][k] = W1[k][h*C1+c] (k<F_IN else 0);  W2t[n][k] = W2[k][n];  W3t.
// ----------------------------------------------------------------------------
__global__ void w1pt_kernel(const float* __restrict__ W1, __half* __restrict__ W1pt) {
    int i = blockIdx.x * 256 + threadIdx.x;
    if (i >= H1 * C1 * KP) return;
    int k = i % KP;
    int c = (i / KP) % C1;
    int h = i / (KP * C1);
    W1pt[i] = __float2half((k < F_IN) ? W1[(size_t)k * D1 + h * C1 + c] : 0.f);
}
__global__ void w2t_kernel(const float* __restrict__ W2, __half* __restrict__ W2t) {
    int i = blockIdx.x * 256 + threadIdx.x;
    if (i >= D2 * D1) return;
    int k = i % D1, n = i / D1;
    W2t[i] = __float2half(W2[(size_t)k * D2 + n]);
}
__global__ void w3t_kernel(const float* __restrict__ W3, __half* __restrict__ W3t) {
    int i = blockIdx.x * 256 + threadIdx.x;
    if (i >= D3 * D2) return;
    int k = i % D2, n = i / D2;
    W3t[i] = __float2half(W3[(size_t)k * D3 + n]);
}

// ----------------------------------------------------------------------------
// Layer-1 attention vector projection: qs[h,k] = sum_c W1[k, h*128+c]*as1[h,c]
// ----------------------------------------------------------------------------
__global__ void proj1_kernel(const float* __restrict__ W1,
                             const float* __restrict__ as1,
                             const float* __restrict__ ad1,
                             float* __restrict__ qs, float* __restrict__ qd) {
    int gw = (blockIdx.x * blockDim.x + threadIdx.x) >> 5;
    int lane = threadIdx.x & 31;
    if (gw >= H1 * F_IN) return;
    int h = gw / F_IN, k = gw % F_IN;
    const float* wrow = W1 + (size_t)k * D1 + h * C1;
    const float* av = as1 + h * C1;
    const float* dv = ad1 + h * C1;
    float s = 0.f, d = 0.f;
#pragma unroll
    for (int c = lane; c < C1; c += 32) {
        float wv = wrow[c];
        s += wv * av[c];
        d += wv * dv[c];
    }
#pragma unroll
    for (int off = 16; off > 0; off >>= 1) {
        s += __shfl_down_sync(0xffffffffu, s, off);
        d += __shfl_down_sync(0xffffffffu, d, off);
    }
    if (lane == 0) { qs[gw] = s; qd[gw] = d; }
}

// ----------------------------------------------------------------------------
// Layer-1 es/ed directly from x: es[n,h] = <x[n,:], qs[h,:]> (K = 66).
// ----------------------------------------------------------------------------
__global__ void esed1_kernel(int NN, const float* __restrict__ x,
                             const float* __restrict__ qs,
                             const float* __restrict__ qd,
                             float* __restrict__ es, float* __restrict__ ed) {
    __shared__ float xs[32][F_IN + 2];
    __shared__ float qss[H1 * F_IN], qds[H1 * F_IN];
    int tid = threadIdx.x;
    for (int i = tid; i < H1 * F_IN; i += 256) { qss[i] = qs[i]; qds[i] = qd[i]; }
    int n0 = blockIdx.x * 32;
    for (int i = tid; i < 32 * F_IN; i += 256) {
        int r = i / F_IN, c = i % F_IN;
        int n = n0 + r;
        xs[r][c] = (n < NN) ? x[(size_t)n * F_IN + c] : 0.f;
    }
    __syncthreads();
    int r = tid >> 3, h = tid & 7;
    int n = n0 + r;
    if (n < NN) {
        float s = 0.f, d = 0.f;
#pragma unroll
        for (int k = 0; k < F_IN; k++) {
            float xv = xs[r][k];
            s += xv * qss[h * F_IN + k];
            d += xv * qds[h * F_IN + k];
        }
        es[n * H1 + h] = s;
        ed[n * H1 + h] = d;
    }
}

// ----------------------------------------------------------------------------
// Layer-1 CSR aggregation with fused softmax; writes fp16 aggX.
// One warp per dst node. Lane j covers x floats [2j,2j+1]; lane 0 also [64,65].
// Pad half2 slots [33,48) zeroed by lanes 0..14.
// ----------------------------------------------------------------------------
__global__ void agg1_csr_kernel(int NN, const float* __restrict__ x,
                                const float* __restrict__ es,
                                const float* __restrict__ ed,
                                const int* __restrict__ offsets,
                                const int* __restrict__ cnt,
                                const int* __restrict__ srcs,
                                __half* __restrict__ aggX) {
    int d = (blockIdx.x * blockDim.x + threadIdx.x) >> 5;
    int lane = threadIdx.x & 31;
    if (d >= NN) return;

    float edv = (lane < H1) ? ed[d * H1 + lane] : 0.f;

    float2 acc[H1];
    float2 tac[H1];
    float zac[H1];
#pragma unroll
    for (int h = 0; h < H1; h++) {
        acc[h] = make_float2(0.f, 0.f);
        tac[h] = make_float2(0.f, 0.f);
        zac[h] = 0.f;
    }

    const int beg = offsets[d];
    const int deg = cnt[d];

    for (int j = 0; j <= deg; j++) {
        int s = (j < deg) ? srcs[beg + j] : d;   // last iteration = self loop
        float esv = (lane < H1) ? es[s * H1 + lane] : 0.f;
        float v8 = esv + edv;
        v8 = v8 > 0.f ? v8 : 0.2f * v8;
        float w8 = __expf(v8);
        const float2* xr = reinterpret_cast<const float2*>(x) + (size_t)s * (F_IN / 2);
        float2 v = xr[lane];
        float2 vt = (lane == 0) ? xr[32] : make_float2(0.f, 0.f);
#pragma unroll
        for (int h = 0; h < H1; h++) {
            float w = __shfl_sync(0xffffffffu, w8, h);
            acc[h].x += w * v.x;  acc[h].y += w * v.y;
            tac[h].x += w * vt.x; tac[h].y += w * vt.y;
            zac[h] += w;
        }
    }

    __half* obase = aggX + (size_t)d * XHP;
#pragma unroll
    for (int h = 0; h < H1; h++) {
        float inv = 1.f / (zac[h] + 1e-16f);
        __half2* o2 = reinterpret_cast<__half2*>(obase + h * KP);
        o2[lane] = __floats2half2_rn(acc[h].x * inv, acc[h].y * inv);
        if (lane == 0) o2[32] = __floats2half2_rn(tac[h].x * inv, tac[h].y * inv);
        if (lane < 15) o2[33 + lane] = __floats2half2_rn(0.f, 0.f);  // pad [66,96)
    }
}

// ----------------------------------------------------------------------------
// Layers 2/3 CSR aggregation with fused softmax (+ optional bias+ELU).
// OUT_HALF writes __half (for the next GEMM's A operand).
// ----------------------------------------------------------------------------
template <int C, bool BIAS_ELU, bool OUT_HALF>
__global__ void agg_csr_kernel(int NN, const float* __restrict__ hfeat,
                               const float* __restrict__ es,
                               const float* __restrict__ ed,
                               const int* __restrict__ offsets,
                               const int* __restrict__ cnt,
                               const int* __restrict__ srcs,
                               const float* __restrict__ bias,
                               void* __restrict__ outv) {
    int d = (blockIdx.x * blockDim.x + threadIdx.x) >> 5;
    int lane = threadIdx.x & 31;
    if (d >= NN) return;

    float edv = ed[d];
    float z = 0.f;
    const int beg = offsets[d];
    const int deg = cnt[d];

    if (C == 128) {
        float4 acc = make_float4(0.f, 0.f, 0.f, 0.f);
        for (int j = 0; j <= deg; j++) {
            int s = (j < deg) ? srcs[beg + j] : d;
            float v = es[s] + edv;
            v = v > 0.f ? v : 0.2f * v;
            float w = __expf(v);
            float4 hv = reinterpret_cast<const float4*>(hfeat)[(size_t)s * 32 + lane];
            acc.x += w * hv.x; acc.y += w * hv.y;
            acc.z += w * hv.z; acc.w += w * hv.w;
            z += w;
        }
        float inv = 1.f / (z + 1e-16f);
        float4 r = make_float4(acc.x * inv, acc.y * inv, acc.z * inv, acc.w * inv);
        if (BIAS_ELU) {
            float4 b = reinterpret_cast<const float4*>(bias)[lane];
            r.x += b.x; r.y += b.y; r.z += b.z; r.w += b.w;
            r.x = r.x > 0.f ? r.x : expm1f(r.x);
            r.y = r.y > 0.f ? r.y : expm1f(r.y);
            r.z = r.z > 0.f ? r.z : expm1f(r.z);
            r.w = r.w > 0.f ? r.w : expm1f(r.w);
        }
        if (OUT_HALF) {
            __half2* o = reinterpret_cast<__half2*>((__half*)outv + (size_t)d * C);
            o[lane * 2]     = __floats2half2_rn(r.x, r.y);
            o[lane * 2 + 1] = __floats2half2_rn(r.z, r.w);
        } else {
            reinterpret_cast<float4*>((float*)outv)[(size_t)d * 32 + lane] = r;
        }
    } else {  // C == 64
        float2 acc = make_float2(0.f, 0.f);
        for (int j = 0; j <= deg; j++) {
            int s = (j < deg) ? srcs[beg + j] : d;
            float v = es[s] + edv;
            v = v > 0.f ? v : 0.2f * v;
            float w = __expf(v);
            float2 hv = reinterpret_cast<const float2*>(hfeat)[(size_t)s * 32 + lane];
            acc.x += w * hv.x; acc.y += w * hv.y;
            z += w;
        }
        float inv = 1.f / (z + 1e-16f);
        float2 r = make_float2(acc.x * inv, acc.y * inv);
        if (BIAS_ELU) {
            float2 b = reinterpret_cast<const float2*>(bias)[lane];
            r.x += b.x; r.y += b.y;
            r.x = r.x > 0.f ? r.x : expm1f(r.x);
            r.y = r.y > 0.f ? r.y : expm1f(r.y);
        }
        if (OUT_HALF) {
            __half2* o = reinterpret_cast<__half2*>((__half*)outv + (size_t)d * C);
            o[lane] = __floats2half2_rn(r.x, r.y);
        } else {
            reinterpret_cast<float2*>((float*)outv)[(size_t)d * 32 + lane] = r;
        }
    }
}

// ----------------------------------------------------------------------------
// Attention coefficients from features (layers 2/3): one warp per (node,head).
// ----------------------------------------------------------------------------
template <int C, int H>
__global__ void esed_kernel(int NN, const float* __restrict__ h,
                            const float* __restrict__ as,
                            const float* __restrict__ ad,
                            float* __restrict__ es, float* __restrict__ ed) {
    int gw = (blockIdx.x * blockDim.x + threadIdx.x) >> 5;
    int lane = threadIdx.x & 31;
    if (gw >= NN * H) return;
    int n = gw / H, hh = gw % H;
    const float* row = h + (size_t)n * (H * C) + hh * C;
    const float* av = as + hh * C;
    const float* dv = ad + hh * C;
    float s = 0.f, d = 0.f;
#pragma unroll
    for (int c = lane; c < C; c += 32) {
        float v = row[c];
        s += v * av[c];
        d += v * dv[c];
    }
#pragma unroll
    for (int off = 16; off > 0; off >>= 1) {
        s += __shfl_down_sync(0xffffffffu, s, off);
        d += __shfl_down_sync(0xffffffffu, d, off);
    }
    if (lane == 0) { es[gw] = s; ed[gw] = d; }
}

// ----------------------------------------------------------------------------
// Final: per node, ELU(agg3 + b3) . Wr + br -> sigmoid. One warp per node.
// ----------------------------------------------------------------------------
__global__ void final_kernel(int NN, const float* __restrict__ agg3,
                             const float* __restrict__ b3,
                             const float* __restrict__ Wr,
                             const float* __restrict__ br,
                             float* __restrict__ out) {
    int n = (blockIdx.x * blockDim.x + threadIdx.x) >> 5;
    int lane = threadIdx.x & 31;
    if (n >= NN) return;
    const float* row = agg3 + (size_t)n * D3;
    float acc = 0.f;
#pragma unroll
    for (int j = lane; j < D3; j += 32) {
        float v = row[j] + b3[j];
        v = v > 0.f ? v : expm1f(v);
        acc += v * Wr[j];
    }
#pragma unroll
    for (int off = 16; off > 0; off >>= 1)
        acc += __shfl_down_sync(0xffffffffu, acc, off);
    if (lane == 0)
        out[n] = 1.f / (1.f + expf(-(acc + br[0])));
}

// ----------------------------------------------------------------------------
// Host launcher
// ----------------------------------------------------------------------------
static inline int ceil_div(int a, int b) { return (a + b - 1) / b; }

extern "C" void kernel_launch(void* const* d_in, const int* in_sizes, int n_in,
                              void* d_out, int out_size) {
    const float* x   = (const float*)d_in[0];
    const int*   ei  = (const int*)d_in[1];   // int32 (JAX x64 disabled)
    const float* W1  = (const float*)d_in[2];
    const float* as1 = (const float*)d_in[3];
    const float* ad1 = (const float*)d_in[4];
    const float* b1  = (const float*)d_in[5];
    const float* W2  = (const float*)d_in[6];
    const float* as2 = (const float*)d_in[7];
    const float* ad2 = (const float*)d_in[8];
    const float* b2  = (const float*)d_in[9];
    const float* W3  = (const float*)d_in[10];
    const float* as3 = (const float*)d_in[11];
    const float* ad3 = (const float*)d_in[12];
    const float* b3  = (const float*)d_in[13];
    const float* Wr  = (const float*)d_in[14];
    const float* br  = (const float*)d_in[15];
    float* out = (float*)d_out;

    const int N = in_sizes[0] / F_IN;
    const int E = in_sizes[1] / 2;

    __half *aggX, *agg1, *agg2, *W1pt, *W2t, *W3t;
    float *h2, *h3, *agg3;
    float *qs1, *qd1, *es1, *ed1, *es2, *ed2, *es3, *ed3;
    int *cntfill, *offsets, *srcs;
    cudaGetSymbolAddress((void**)&aggX, g_aggX);
    cudaGetSymbolAddress((void**)&agg1, g_agg1);
    cudaGetSymbolAddress((void**)&h2, g_h2);
    cudaGetSymbolAddress((void**)&agg2, g_agg2);
    cudaGetSymbolAddress((void**)&h3, g_h3);
    cudaGetSymbolAddress((void**)&agg3, g_agg3);
    cudaGetSymbolAddress((void**)&W1pt, g_W1pt);
    cudaGetSymbolAddress((void**)&W2t, g_W2t);
    cudaGetSymbolAddress((void**)&W3t, g_W3t);
    cudaGetSymbolAddress((void**)&qs1, g_qs1);
    cudaGetSymbolAddress((void**)&qd1, g_qd1);
    cudaGetSymbolAddress((void**)&es1, g_es1);
    cudaGetSymbolAddress((void**)&ed1, g_ed1);
    cudaGetSymbolAddress((void**)&es2, g_es2);
    cudaGetSymbolAddress((void**)&ed2, g_ed2);
    cudaGetSymbolAddress((void**)&es3, g_es3);
    cudaGetSymbolAddress((void**)&ed3, g_ed3);
    cudaGetSymbolAddress((void**)&cntfill, g_cntfill);
    cudaGetSymbolAddress((void**)&offsets, g_offsets);
    cudaGetSymbolAddress((void**)&srcs, g_srcs);

    int* cnt  = cntfill;
    int* fill = cntfill + MAXN;

    // dynamic smem opt-in (idempotent, host-side, capture-legal)
    constexpr int SM_128 = pipe_smem_bytes<128, 128, 32, 4>();  // 80 KB
    constexpr int SM_64  = pipe_smem_bytes<128, 64, 32, 4>();   // 60 KB
    cudaFuncSetAttribute(
        (const void*)h16_gemm_pipe_kernel<128, 128, 32, 64, 32, 4, true, true>,
        cudaFuncAttributeMaxDynamicSharedMemorySize, SM_128);
    cudaFuncSetAttribute(
        (const void*)h16_gemm_pipe_kernel<128, 128, 32, 64, 32, 4, false, false>,
        cudaFuncAttributeMaxDynamicSharedMemorySize, SM_128);
    cudaFuncSetAttribute(
        (const void*)h16_gemm_pipe_kernel<128, 64, 32, 64, 16, 4, false, false>,
        cudaFuncAttributeMaxDynamicSharedMemorySize, SM_64);

    // ---------------- CSR build (by destination) ----------------------------
    cudaMemsetAsync(cntfill, 0, 2 * MAXN * sizeof(int));
    hist_kernel<<<ceil_div(E, 256), 256>>>(E, ei, cnt);
    scan_kernel<<<1, 1024>>>(N, cnt, offsets);
    scatter_kernel<<<ceil_div(E, 256), 256>>>(E, ei, offsets, fill, srcs);

    // ---------------- Weight prep (fp16 transposed) -------------------------
    w1pt_kernel<<<ceil_div(H1 * C1 * KP, 256), 256>>>(W1, W1pt);
    w2t_kernel<<<ceil_div(D2 * D1, 256), 256>>>(W2, W2t);
    w3t_kernel<<<ceil_div(D3 * D2, 256), 256>>>(W3, W3t);

    // ---------------- Layer 1 (x-space aggregation; h1 never materialized) --
    proj1_kernel<<<ceil_div(H1 * F_IN * 32, 256), 256>>>(W1, as1, ad1, qs1, qd1);
    esed1_kernel<<<ceil_div(N, 32), 256>>>(N, x, qs1, qd1, es1, ed1);
    agg1_csr_kernel<<<ceil_div(N * 32, 256), 256>>>(
        N, x, es1, ed1, offsets, cnt, srcs, aggX);
    {
        // per-head block-diagonal fp16 GEMM with fused bias+ELU -> agg1 (half)
        dim3 grid(1, ceil_div(N, 128), H1);
        h16_gemm_pipe_kernel<128, 128, 32, 64, 32, 4, true, true>
            <<<grid, 256, SM_128>>>(
            N, C1, KP,
            aggX, XHP, (long long)KP,
            W1pt, KP, (long long)C1 * KP,
            agg1, D1, (long long)C1,
            b1);
    }

    // ---------------- Layer 2: 1024 -> 128 -----------------------------------
    {
        dim3 grid(1, ceil_div(N, 128), 1);
        h16_gemm_pipe_kernel<128, 128, 32, 64, 32, 4, false, false>
            <<<grid, 256, SM_128>>>(
            N, D2, D1, agg1, D1, 0, W2t, D1, 0, h2, D2, 0, nullptr);
    }
    esed_kernel<D2, 1><<<ceil_div(N * 32, 256), 256>>>(N, h2, as2, ad2, es2, ed2);
    agg_csr_kernel<D2, true, true><<<ceil_div(N * 32, 256), 256>>>(
        N, h2, es2, ed2, offsets, cnt, srcs, b2, agg2);

    // ---------------- Layer 3: 128 -> 64 -------------------------------------
    {
        dim3 grid(1, ceil_div(N, 128), 1);
        h16_gemm_pipe_kernel<128, 64, 32, 64, 16, 4, false, false>
            <<<grid, 256, SM_64>>>(
            N, D3, D2, agg2, D2, 0, W3t, D2, 0, h3, D3, 0, nullptr);
    }
    esed_kernel<D3, 1><<<ceil_div(N * 32, 256), 256>>>(N, h3, as3, ad3, es3, ed3);
    agg_csr_kernel<D3, false, false><<<ceil_div(N * 32, 256), 256>>>(
        N, h3, es3, ed3, offsets, cnt, srcs, nullptr, agg3);

    // ---------------- Regressor (fused bias+ELU+dot+sigmoid) ----------------
    final_kernel<<<ceil_div(N * 32, 256), 256>>>(N, agg3, b3, Wr, br, out);
}

// round 17
// speedup vs baseline: 5.0592x; 1.0190x over previous
#include <cuda_runtime.h>
#include <cuda_fp16.h>
#include <cstdint>
#include <math.h>

// ----------------------------------------------------------------------------
// Problem constants (shapes fixed by the reference)
// ----------------------------------------------------------------------------
#define MAXN 50000
#define MAXE 200000
#define F_IN 66
#define H1 8
#define C1 128
#define D1 (H1 * C1)   // 1024
#define D2 128
#define D3 64
#define KP 96          // K=66 padded to 96 (=3*32) for the fp16 head GEMM
#define XHP (H1 * KP)  // 768 : per-node width of padded x-space agg buffer

// ----------------------------------------------------------------------------
// Device scratch (static globals: allocation-free)
// ----------------------------------------------------------------------------
__device__ __half g_aggX[(size_t)MAXN * XHP];  // layer-1 x-space agg (normalized)
__device__ __half g_agg1[(size_t)MAXN * D1];   // layer-1 output (post bias+ELU)
__device__ __half g_h2[(size_t)MAXN * D2];     // fp16 features (gathered)
__device__ __half g_agg2[(size_t)MAXN * D2];   // post bias+ELU (fused)
__device__ __half g_h3[(size_t)MAXN * D3];     // fp16 features (gathered)
__device__ float  g_agg3[(size_t)MAXN * D3];
__device__ __half g_W1pt[H1 * C1 * KP];        // W1 per-head, transposed [h][c][k]
__device__ __half g_W2t[D2 * D1];              // W2 transposed [n][k]
__device__ __half g_W3t[D3 * D2];              // W3 transposed [n][k]

__device__ float g_qs1[H1 * F_IN], g_qd1[H1 * F_IN];
__device__ float g_es1[MAXN * H1], g_ed1[MAXN * H1];
__device__ float g_es2[MAXN], g_ed2[MAXN];
__device__ float g_es3[MAXN], g_ed3[MAXN];

// CSR by destination (self-loops handled implicitly, not stored)
__device__ int g_cntfill[2 * MAXN];           // [0:N) cnt, [N:2N) fill — memset 0
__device__ int g_offsets[MAXN];
__device__ int g_srcs[MAXE];

// ----------------------------------------------------------------------------
// cp.async helpers
// ----------------------------------------------------------------------------
__device__ __forceinline__ void cp_async16(uint32_t smem_dst, const void* gsrc, int sz) {
    asm volatile("cp.async.cg.shared.global [%0], [%1], 16, %2;\n"
                 :: "r"(smem_dst), "l"(gsrc), "r"(sz));
}
__device__ __forceinline__ void cp_commit() {
    asm volatile("cp.async.commit_group;\n");
}
template <int NG>
__device__ __forceinline__ void cp_wait() {
    asm volatile("cp.async.wait_group %0;\n" :: "n"(NG));
}

// ----------------------------------------------------------------------------
// Multi-stage cp.async pipelined FP16 GEMM (fp32 accumulate):
//   C[M,N] = A[M,K] @ B[K,N],  B passed TRANSPOSED as Bt[N][K].
// Single barrier per K-tile: wait -> sync -> issue(t+S-1) -> compute(t).
// After the sync all warps finished tile t-1, so overwriting slot (t-1)%S is
// safe; pending cp.async group count stays constant via empty tail commits.
// Both smem tiles K-contiguous, stride BK+8 halves (conflict-free).
// blockIdx.z selects a slice; optional fused bias+ELU; fp16 or fp32 output.
// Requires K % BK == 0, N == BN, 16B-aligned rows.
// ----------------------------------------------------------------------------
template <int BM, int BN, int BK, int WM, int WN, int STAGES,
          bool BIAS_ELU, bool OUT_HALF>
__global__ void h16_gemm_pipe_kernel(int M, int N, int K,
        const __half* __restrict__ A, int lda, long long strideAz,
        const __half* __restrict__ Bt, int ldb, long long strideBz,
        void* __restrict__ Cv, int ldc, long long strideCz,
        const float* __restrict__ bias) {
    constexpr int WARPS_M = BM / WM, WARPS_N = BN / WN;
    constexpr int NT = 32 * WARPS_M * WARPS_N;
    constexpr int MI = WM / 16, NI = WN / 8;
    constexpr int SH = BK + 8;               // halves per smem row
    constexpr int SH2 = SH / 2;              // uint32 per smem row
    constexpr int A_HALVES = BM * SH;
    constexpr int B_HALVES = BN * SH;
    constexpr int A_CHUNKS = BM * (BK / 8);
    constexpr int B_CHUNKS = BN * (BK / 8);

    extern __shared__ __half smem[];
    __half* Asm = smem;                      // [STAGES][BM][SH]
    __half* Bsm = smem + STAGES * A_HALVES;  // [STAGES][BN][SH]

    const int tid = threadIdx.x;
    const int wid = tid >> 5, lane = tid & 31;
    const int l4 = lane & 3, l8 = lane >> 2;
    const int wm = (wid / WARPS_N) * WM;
    const int wn = (wid % WARPS_N) * WN;
    const int bm = blockIdx.y * BM;

    A  += (long long)blockIdx.z * strideAz;
    Bt += (long long)blockIdx.z * strideBz;
    if (BIAS_ELU) bias += (long long)blockIdx.z * (long long)N;

    float acc[MI][NI][4];
#pragma unroll
    for (int i = 0; i < MI; i++)
#pragma unroll
        for (int j = 0; j < NI; j++)
#pragma unroll
            for (int q = 0; q < 4; q++) acc[i][j][q] = 0.f;

    const uint32_t a_base = (uint32_t)__cvta_generic_to_shared(Asm);
    const uint32_t b_base = (uint32_t)__cvta_generic_to_shared(Bsm);

    auto issue = [&](int s, int k0) {
#pragma unroll
        for (int j = tid; j < A_CHUNKS; j += NT) {
            int m = j / (BK / 8), cq = j % (BK / 8);
            int gm = bm + m;
            const __half* src = A + (size_t)gm * lda + k0 + 8 * cq;
            uint32_t dst = a_base + (s * A_HALVES + m * SH + 8 * cq) * 2;
            cp_async16(dst, src, gm < M ? 16 : 0);
        }
#pragma unroll
        for (int j = tid; j < B_CHUNKS; j += NT) {
            int n = j / (BK / 8), cq = j % (BK / 8);
            const __half* src = Bt + (size_t)n * ldb + k0 + 8 * cq;
            uint32_t dst = b_base + (s * B_HALVES + n * SH + 8 * cq) * 2;
            cp_async16(dst, src, 16);
        }
        cp_commit();
    };

    const int KT = K / BK;

    // prologue (empty groups past KT keep the pending-count fixed)
#pragma unroll
    for (int s = 0; s < STAGES - 1; s++) {
        if (s < KT) issue(s, s * BK); else cp_commit();
    }

    for (int t = 0; t < KT; t++) {
        cp_wait<STAGES - 2>();          // group for tile t complete
        __syncthreads();                // all warps done with tile t-1
        int tn = t + STAGES - 1;
        if (tn < KT) issue(tn % STAGES, tn * BK); else cp_commit();

        const int s = t % STAGES;
        const uint32_t* Au = reinterpret_cast<const uint32_t*>(Asm + s * A_HALVES);
        const uint32_t* Bu = reinterpret_cast<const uint32_t*>(Bsm + s * B_HALVES);

#pragma unroll
        for (int kk2 = 0; kk2 < BK / 2; kk2 += 8) {   // k16 step (8 uint32)
            uint32_t bfr[NI][2];
#pragma unroll
            for (int ni = 0; ni < NI; ni++) {
                int n = wn + ni * 8 + l8;
                bfr[ni][0] = Bu[n * SH2 + kk2 + l4];
                bfr[ni][1] = Bu[n * SH2 + kk2 + 4 + l4];
            }
#pragma unroll
            for (int mi = 0; mi < MI; mi++) {
                const int m0 = wm + mi * 16 + l8;
                const int m1 = m0 + 8;
                uint32_t a0 = Au[m0 * SH2 + kk2 + l4];
                uint32_t a1 = Au[m1 * SH2 + kk2 + l4];
                uint32_t a2 = Au[m0 * SH2 + kk2 + 4 + l4];
                uint32_t a3 = Au[m1 * SH2 + kk2 + 4 + l4];
#pragma unroll
                for (int ni = 0; ni < NI; ni++) {
                    asm volatile(
                        "mma.sync.aligned.m16n8k16.row.col.f32.f16.f16.f32 "
                        "{%0,%1,%2,%3}, {%4,%5,%6,%7}, {%8,%9}, {%0,%1,%2,%3};"
                        : "+f"(acc[mi][ni][0]), "+f"(acc[mi][ni][1]),
                          "+f"(acc[mi][ni][2]), "+f"(acc[mi][ni][3])
                        : "r"(a0), "r"(a1), "r"(a2), "r"(a3),
                          "r"(bfr[ni][0]), "r"(bfr[ni][1]));
                }
            }
        }
    }

    // epilogue
    __half* Ch = (__half*)Cv;
    float*  Cf = (float*)Cv;
    if (OUT_HALF) Ch += (long long)blockIdx.z * strideCz;
    else          Cf += (long long)blockIdx.z * strideCz;

#pragma unroll
    for (int mi = 0; mi < MI; mi++) {
        int r0 = bm + wm + mi * 16 + l8;
#pragma unroll
        for (int ni = 0; ni < NI; ni++) {
            int c0 = wn + ni * 8 + l4 * 2;
#pragma unroll
            for (int half_row = 0; half_row < 2; half_row++) {
                int gr = r0 + half_row * 8;
                if (gr >= M) continue;
                float v0 = acc[mi][ni][half_row * 2 + 0];
                float v1 = acc[mi][ni][half_row * 2 + 1];
                if (BIAS_ELU) {
                    v0 += bias[c0];     v1 += bias[c0 + 1];
                    v0 = v0 > 0.f ? v0 : expm1f(v0);
                    v1 = v1 > 0.f ? v1 : expm1f(v1);
                }
                if (OUT_HALF) {
                    *reinterpret_cast<__half2*>(Ch + (size_t)gr * ldc + c0) =
                        __floats2half2_rn(v0, v1);
                } else {
                    Cf[(size_t)gr * ldc + c0] = v0;
                    Cf[(size_t)gr * ldc + c0 + 1] = v1;
                }
            }
        }
    }
}

template <int BM, int BN, int BK, int STAGES>
constexpr int pipe_smem_bytes() {
    return STAGES * (BM + BN) * (BK + 8) * 2;
}

// ----------------------------------------------------------------------------
// CSR build: histogram -> single-block scan -> scatter
// ----------------------------------------------------------------------------
__global__ void hist_kernel(int E, const int* __restrict__ ei, int* __restrict__ cnt) {
    int e = blockIdx.x * blockDim.x + threadIdx.x;
    if (e < E) atomicAdd(&cnt[ei[E + e]], 1);
}

__global__ void scan_kernel(int NN, const int* __restrict__ cnt, int* __restrict__ offsets) {
    __shared__ int tsum[1024];
    int tid = threadIdx.x;
    int per = (NN + 1023) / 1024;
    int lo = tid * per, hi = min(lo + per, NN);
    int s = 0;
    for (int i = lo; i < hi; i++) s += cnt[i];
    tsum[tid] = s;
    __syncthreads();
    for (int off = 1; off < 1024; off <<= 1) {
        int v = (tid >= off) ? tsum[tid - off] : 0;
        __syncthreads();
        tsum[tid] += v;
        __syncthreads();
    }
    int run = (tid > 0) ? tsum[tid - 1] : 0;
    for (int i = lo; i < hi; i++) { offsets[i] = run; run += cnt[i]; }
}

__global__ void scatter_kernel(int E, const int* __restrict__ ei,
                               const int* __restrict__ offsets,
                               int* __restrict__ fill, int* __restrict__ srcs) {
    int e = blockIdx.x * blockDim.x + threadIdx.x;
    if (e >= E) return;
    int d = ei[E + e];
    int pos = offsets[d] + atomicAdd(&fill[d], 1);
    srcs[pos] = ei[e];
}

// ----------------------------------------------------------------------------
// Weight prep: fp16 transposed copies.
// ----------------------------------------------------------------------------
__global__ void w1pt_kernel(const float* __restrict__ W1, __half* __restrict__ W1pt) {
    int i = blockIdx.x * 256 + threadIdx.x;
    if (i >= H1 * C1 * KP) return;
    int k = i % KP;
    int c = (i / KP) % C1;
    int h = i / (KP * C1);
    W1pt[i] = __float2half((k < F_IN) ? W1[(size_t)k * D1 + h * C1 + c] : 0.f);
}
__global__ void w2t_kernel(const float* __restrict__ W2, __half* __restrict__ W2t) {
    int i = blockIdx.x * 256 + threadIdx.x;
    if (i >= D2 * D1) return;
    int k = i % D1, n = i / D1;
    W2t[i] = __float2half(W2[(size_t)k * D2 + n]);
}
__global__ void w3t_kernel(const float* __restrict__ W3, __half* __restrict__ W3t) {
    int i = blockIdx.x * 256 + threadIdx.x;
    if (i >= D3 * D2) return;
    int k = i % D2, n = i / D2;
    W3t[i] = __float2half(W3[(size_t)k * D3 + n]);
}

// ----------------------------------------------------------------------------
// Layer-1 attention vector projection: qs[h,k] = sum_c W1[k, h*128+c]*as1[h,c]
// ----------------------------------------------------------------------------
__global__ void proj1_kernel(const float* __restrict__ W1,
                             const float* __restrict__ as1,
                             const float* __restrict__ ad1,
                             float* __restrict__ qs, float* __restrict__ qd) {
    int gw = (blockIdx.x * blockDim.x + threadIdx.x) >> 5;
    int lane = threadIdx.x & 31;
    if (gw >= H1 * F_IN) return;
    int h = gw / F_IN, k = gw % F_IN;
    const float* wrow = W1 + (size_t)k * D1 + h * C1;
    const float* av = as1 + h * C1;
    const float* dv = ad1 + h * C1;
    float s = 0.f, d = 0.f;
#pragma unroll
    for (int c = lane; c < C1; c += 32) {
        float wv = wrow[c];
        s += wv * av[c];
        d += wv * dv[c];
    }
#pragma unroll
    for (int off = 16; off > 0; off >>= 1) {
        s += __shfl_down_sync(0xffffffffu, s, off);
        d += __shfl_down_sync(0xffffffffu, d, off);
    }
    if (lane == 0) { qs[gw] = s; qd[gw] = d; }
}

// ----------------------------------------------------------------------------
// Layer-1 es/ed directly from x: es[n,h] = <x[n,:], qs[h,:]> (K = 66).
// ----------------------------------------------------------------------------
__global__ void esed1_kernel(int NN, const float* __restrict__ x,
                             const float* __restrict__ qs,
                             const float* __restrict__ qd,
                             float* __restrict__ es, float* __restrict__ ed) {
    __shared__ float xs[32][F_IN + 2];
    __shared__ float qss[H1 * F_IN], qds[H1 * F_IN];
    int tid = threadIdx.x;
    for (int i = tid; i < H1 * F_IN; i += 256) { qss[i] = qs[i]; qds[i] = qd[i]; }
    int n0 = blockIdx.x * 32;
    for (int i = tid; i < 32 * F_IN; i += 256) {
        int r = i / F_IN, c = i % F_IN;
        int n = n0 + r;
        xs[r][c] = (n < NN) ? x[(size_t)n * F_IN + c] : 0.f;
    }
    __syncthreads();
    int r = tid >> 3, h = tid & 7;
    int n = n0 + r;
    if (n < NN) {
        float s = 0.f, d = 0.f;
#pragma unroll
        for (int k = 0; k < F_IN; k++) {
            float xv = xs[r][k];
            s += xv * qss[h * F_IN + k];
            d += xv * qds[h * F_IN + k];
        }
        es[n * H1 + h] = s;
        ed[n * H1 + h] = d;
    }
}

// ----------------------------------------------------------------------------
// Layer-1 CSR aggregation with fused softmax; writes fp16 aggX.
// ----------------------------------------------------------------------------
__global__ void agg1_csr_kernel(int NN, const float* __restrict__ x,
                                const float* __restrict__ es,
                                const float* __restrict__ ed,
                                const int* __restrict__ offsets,
                                const int* __restrict__ cnt,
                                const int* __restrict__ srcs,
                                __half* __restrict__ aggX) {
    int d = (blockIdx.x * blockDim.x + threadIdx.x) >> 5;
    int lane = threadIdx.x & 31;
    if (d >= NN) return;

    float edv = (lane < H1) ? ed[d * H1 + lane] : 0.f;

    float2 acc[H1];
    float2 tac[H1];
    float zac[H1];
#pragma unroll
    for (int h = 0; h < H1; h++) {
        acc[h] = make_float2(0.f, 0.f);
        tac[h] = make_float2(0.f, 0.f);
        zac[h] = 0.f;
    }

    const int beg = offsets[d];
    const int deg = cnt[d];

    for (int j = 0; j <= deg; j++) {
        int s = (j < deg) ? srcs[beg + j] : d;   // last iteration = self loop
        float esv = (lane < H1) ? es[s * H1 + lane] : 0.f;
        float v8 = esv + edv;
        v8 = v8 > 0.f ? v8 : 0.2f * v8;
        float w8 = __expf(v8);
        const float2* xr = reinterpret_cast<const float2*>(x) + (size_t)s * (F_IN / 2);
        float2 v = xr[lane];
        float2 vt = (lane == 0) ? xr[32] : make_float2(0.f, 0.f);
#pragma unroll
        for (int h = 0; h < H1; h++) {
            float w = __shfl_sync(0xffffffffu, w8, h);
            acc[h].x += w * v.x;  acc[h].y += w * v.y;
            tac[h].x += w * vt.x; tac[h].y += w * vt.y;
            zac[h] += w;
        }
    }

    __half* obase = aggX + (size_t)d * XHP;
#pragma unroll
    for (int h = 0; h < H1; h++) {
        float inv = 1.f / (zac[h] + 1e-16f);
        __half2* o2 = reinterpret_cast<__half2*>(obase + h * KP);
        o2[lane] = __floats2half2_rn(acc[h].x * inv, acc[h].y * inv);
        if (lane == 0) o2[32] = __floats2half2_rn(tac[h].x * inv, tac[h].y * inv);
        if (lane < 15) o2[33 + lane] = __floats2half2_rn(0.f, 0.f);  // pad [66,96)
    }
}

// ----------------------------------------------------------------------------
// Layers 2/3 CSR aggregation over fp16 features, fused softmax (+bias+ELU).
// C=128: one uint2 (4 halves) per lane.  C=64: one uint (2 halves) per lane.
// ----------------------------------------------------------------------------
template <int C, bool BIAS_ELU, bool OUT_HALF>
__global__ void agg_csr_kernel(int NN, const __half* __restrict__ hfeat,
                               const float* __restrict__ es,
                               const float* __restrict__ ed,
                               const int* __restrict__ offsets,
                               const int* __restrict__ cnt,
                               const int* __restrict__ srcs,
                               const float* __restrict__ bias,
                               void* __restrict__ outv) {
    int d = (blockIdx.x * blockDim.x + threadIdx.x) >> 5;
    int lane = threadIdx.x & 31;
    if (d >= NN) return;

    float edv = ed[d];
    float z = 0.f;
    const int beg = offsets[d];
    const int deg = cnt[d];

    if (C == 128) {
        float4 acc = make_float4(0.f, 0.f, 0.f, 0.f);
        for (int j = 0; j <= deg; j++) {
            int s = (j < deg) ? srcs[beg + j] : d;
            float v = es[s] + edv;
            v = v > 0.f ? v : 0.2f * v;
            float w = __expf(v);
            const __half2* hr = reinterpret_cast<const __half2*>(hfeat + (size_t)s * C);
            __half2 p0 = hr[lane * 2], p1 = hr[lane * 2 + 1];
            float2 f0 = __half22float2(p0), f1 = __half22float2(p1);
            acc.x += w * f0.x; acc.y += w * f0.y;
            acc.z += w * f1.x; acc.w += w * f1.y;
            z += w;
        }
        float inv = 1.f / (z + 1e-16f);
        float4 r = make_float4(acc.x * inv, acc.y * inv, acc.z * inv, acc.w * inv);
        if (BIAS_ELU) {
            float4 b = reinterpret_cast<const float4*>(bias)[lane];
            r.x += b.x; r.y += b.y; r.z += b.z; r.w += b.w;
            r.x = r.x > 0.f ? r.x : expm1f(r.x);
            r.y = r.y > 0.f ? r.y : expm1f(r.y);
            r.z = r.z > 0.f ? r.z : expm1f(r.z);
            r.w = r.w > 0.f ? r.w : expm1f(r.w);
        }
        if (OUT_HALF) {
            __half2* o = reinterpret_cast<__half2*>((__half*)outv + (size_t)d * C);
            o[lane * 2]     = __floats2half2_rn(r.x, r.y);
            o[lane * 2 + 1] = __floats2half2_rn(r.z, r.w);
        } else {
            reinterpret_cast<float4*>((float*)outv)[(size_t)d * 32 + lane] = r;
        }
    } else {  // C == 64
        float2 acc = make_float2(0.f, 0.f);
        for (int j = 0; j <= deg; j++) {
            int s = (j < deg) ? srcs[beg + j] : d;
            float v = es[s] + edv;
            v = v > 0.f ? v : 0.2f * v;
            float w = __expf(v);
            __half2 p = reinterpret_cast<const __half2*>(hfeat + (size_t)s * C)[lane];
            float2 f = __half22float2(p);
            acc.x += w * f.x; acc.y += w * f.y;
            z += w;
        }
        float inv = 1.f / (z + 1e-16f);
        float2 r = make_float2(acc.x * inv, acc.y * inv);
        if (BIAS_ELU) {
            float2 b = reinterpret_cast<const float2*>(bias)[lane];
            r.x += b.x; r.y += b.y;
            r.x = r.x > 0.f ? r.x : expm1f(r.x);
            r.y = r.y > 0.f ? r.y : expm1f(r.y);
        }
        if (OUT_HALF) {
            __half2* o = reinterpret_cast<__half2*>((__half*)outv + (size_t)d * C);
            o[lane] = __floats2half2_rn(r.x, r.y);
        } else {
            reinterpret_cast<float2*>((float*)outv)[(size_t)d * 32 + lane] = r;
        }
    }
}

// ----------------------------------------------------------------------------
// Attention coefficients from fp16 features: one warp per node (H=1 layers).
// ----------------------------------------------------------------------------
template <int C>
__global__ void esed_h_kernel(int NN, const __half* __restrict__ h,
                              const float* __restrict__ as,
                              const float* __restrict__ ad,
                              float* __restrict__ es, float* __restrict__ ed) {
    int n = (blockIdx.x * blockDim.x + threadIdx.x) >> 5;
    int lane = threadIdx.x & 31;
    if (n >= NN) return;
    const __half2* row = reinterpret_cast<const __half2*>(h + (size_t)n * C);
    float s = 0.f, d = 0.f;
#pragma unroll
    for (int c2 = lane; c2 < C / 2; c2 += 32) {
        float2 v = __half22float2(row[c2]);
        s += v.x * as[c2 * 2] + v.y * as[c2 * 2 + 1];
        d += v.x * ad[c2 * 2] + v.y * ad[c2 * 2 + 1];
    }
#pragma unroll
    for (int off = 16; off > 0; off >>= 1) {
        s += __shfl_down_sync(0xffffffffu, s, off);
        d += __shfl_down_sync(0xffffffffu, d, off);
    }
    if (lane == 0) { es[n] = s; ed[n] = d; }
}

// ----------------------------------------------------------------------------
// Final: per node, ELU(agg3 + b3) . Wr + br -> sigmoid. One warp per node.
// ----------------------------------------------------------------------------
__global__ void final_kernel(int NN, const float* __restrict__ agg3,
                             const float* __restrict__ b3,
                             const float* __restrict__ Wr,
                             const float* __restrict__ br,
                             float* __restrict__ out) {
    int n = (blockIdx.x * blockDim.x + threadIdx.x) >> 5;
    int lane = threadIdx.x & 31;
    if (n >= NN) return;
    const float* row = agg3 + (size_t)n * D3;
    float acc = 0.f;
#pragma unroll
    for (int j = lane; j < D3; j += 32) {
        float v = row[j] + b3[j];
        v = v > 0.f ? v : expm1f(v);
        acc += v * Wr[j];
    }
#pragma unroll
    for (int off = 16; off > 0; off >>= 1)
        acc += __shfl_down_sync(0xffffffffu, acc, off);
    if (lane == 0)
        out[n] = 1.f / (1.f + expf(-(acc + br[0])));
}

// ----------------------------------------------------------------------------
// Host launcher
// ----------------------------------------------------------------------------
static inline int ceil_div(int a, int b) { return (a + b - 1) / b; }

extern "C" void kernel_launch(void* const* d_in, const int* in_sizes, int n_in,
                              void* d_out, int out_size) {
    const float* x   = (const float*)d_in[0];
    const int*   ei  = (const int*)d_in[1];   // int32 (JAX x64 disabled)
    const float* W1  = (const float*)d_in[2];
    const float* as1 = (const float*)d_in[3];
    const float* ad1 = (const float*)d_in[4];
    const float* b1  = (const float*)d_in[5];
    const float* W2  = (const float*)d_in[6];
    const float* as2 = (const float*)d_in[7];
    const float* ad2 = (const float*)d_in[8];
    const float* b2  = (const float*)d_in[9];
    const float* W3  = (const float*)d_in[10];
    const float* as3 = (const float*)d_in[11];
    const float* ad3 = (const float*)d_in[12];
    const float* b3  = (const float*)d_in[13];
    const float* Wr  = (const float*)d_in[14];
    const float* br  = (const float*)d_in[15];
    float* out = (float*)d_out;

    const int N = in_sizes[0] / F_IN;
    const int E = in_sizes[1] / 2;

    __half *aggX, *agg1, *h2, *agg2, *h3, *W1pt, *W2t, *W3t;
    float *agg3;
    float *qs1, *qd1, *es1, *ed1, *es2, *ed2, *es3, *ed3;
    int *cntfill, *offsets, *srcs;
    cudaGetSymbolAddress((void**)&aggX, g_aggX);
    cudaGetSymbolAddress((void**)&agg1, g_agg1);
    cudaGetSymbolAddress((void**)&h2, g_h2);
    cudaGetSymbolAddress((void**)&agg2, g_agg2);
    cudaGetSymbolAddress((void**)&h3, g_h3);
    cudaGetSymbolAddress((void**)&agg3, g_agg3);
    cudaGetSymbolAddress((void**)&W1pt, g_W1pt);
    cudaGetSymbolAddress((void**)&W2t, g_W2t);
    cudaGetSymbolAddress((void**)&W3t, g_W3t);
    cudaGetSymbolAddress((void**)&qs1, g_qs1);
    cudaGetSymbolAddress((void**)&qd1, g_qd1);
    cudaGetSymbolAddress((void**)&es1, g_es1);
    cudaGetSymbolAddress((void**)&ed1, g_ed1);
    cudaGetSymbolAddress((void**)&es2, g_es2);
    cudaGetSymbolAddress((void**)&ed2, g_ed2);
    cudaGetSymbolAddress((void**)&es3, g_es3);
    cudaGetSymbolAddress((void**)&ed3, g_ed3);
    cudaGetSymbolAddress((void**)&cntfill, g_cntfill);
    cudaGetSymbolAddress((void**)&offsets, g_offsets);
    cudaGetSymbolAddress((void**)&srcs, g_srcs);

    int* cnt  = cntfill;
    int* fill = cntfill + MAXN;

    // dynamic smem opt-in (idempotent, host-side, capture-legal)
    constexpr int SM_128 = pipe_smem_bytes<128, 128, 32, 4>();  // 80 KB
    constexpr int SM_64  = pipe_smem_bytes<128, 64, 32, 4>();   // 60 KB
    cudaFuncSetAttribute(
        (const void*)h16_gemm_pipe_kernel<128, 128, 32, 64, 32, 4, true, true>,
        cudaFuncAttributeMaxDynamicSharedMemorySize, SM_128);
    cudaFuncSetAttribute(
        (const void*)h16_gemm_pipe_kernel<128, 128, 32, 64, 32, 4, false, true>,
        cudaFuncAttributeMaxDynamicSharedMemorySize, SM_128);
    cudaFuncSetAttribute(
        (const void*)h16_gemm_pipe_kernel<128, 64, 32, 64, 16, 4, false, true>,
        cudaFuncAttributeMaxDynamicSharedMemorySize, SM_64);

    // ---------------- CSR build (by destination) ----------------------------
    cudaMemsetAsync(cntfill, 0, 2 * MAXN * sizeof(int));
    hist_kernel<<<ceil_div(E, 256), 256>>>(E, ei, cnt);
    scan_kernel<<<1, 1024>>>(N, cnt, offsets);
    scatter_kernel<<<ceil_div(E, 256), 256>>>(E, ei, offsets, fill, srcs);

    // ---------------- Weight prep (fp16 transposed) -------------------------
    w1pt_kernel<<<ceil_div(H1 * C1 * KP, 256), 256>>>(W1, W1pt);
    w2t_kernel<<<ceil_div(D2 * D1, 256), 256>>>(W2, W2t);
    w3t_kernel<<<ceil_div(D3 * D2, 256), 256>>>(W3, W3t);

    // ---------------- Layer 1 (x-space aggregation; h1 never materialized) --
    proj1_kernel<<<ceil_div(H1 * F_IN * 32, 256), 256>>>(W1, as1, ad1, qs1, qd1);
    esed1_kernel<<<ceil_div(N, 32), 256>>>(N, x, qs1, qd1, es1, ed1);
    agg1_csr_kernel<<<ceil_div(N * 32, 256), 256>>>(
        N, x, es1, ed1, offsets, cnt, srcs, aggX);
    {
        // per-head block-diagonal fp16 GEMM with fused bias+ELU -> agg1 (half)
        dim3 grid(1, ceil_div(N, 128), H1);
        h16_gemm_pipe_kernel<128, 128, 32, 64, 32, 4, true, true>
            <<<grid, 256, SM_128>>>(
            N, C1, KP,
            aggX, XHP, (long long)KP,
            W1pt, KP, (long long)C1 * KP,
            agg1, D1, (long long)C1,
            b1);
    }

    // ---------------- Layer 2: 1024 -> 128 (fp16 features) ------------------
    {
        dim3 grid(1, ceil_div(N, 128), 1);
        h16_gemm_pipe_kernel<128, 128, 32, 64, 32, 4, false, true>
            <<<grid, 256, SM_128>>>(
            N, D2, D1, agg1, D1, 0, W2t, D1, 0, h2, D2, 0, nullptr);
    }
    esed_h_kernel<D2><<<ceil_div(N * 32, 256), 256>>>(N, h2, as2, ad2, es2, ed2);
    agg_csr_kernel<D2, true, true><<<ceil_div(N * 32, 256), 256>>>(
        N, h2, es2, ed2, offsets, cnt, srcs, b2, agg2);

    // ---------------- Layer 3: 128 -> 64 (fp16 features) --------------------
    {
        dim3 grid(1, ceil_div(N, 128), 1);
        h16_gemm_pipe_kernel<128, 64, 32, 64, 16, 4, false, true>
            <<<grid, 256, SM_64>>>(
            N, D3, D2, agg2, D2, 0, W3t, D2, 0, h3, D3, 0, nullptr);
    }
    esed_h_kernel<D3><<<ceil_div(N * 32, 256), 256>>>(N, h3, as3, ad3, es3, ed3);
    agg_csr_kernel<D3, false, false><<<ceil_div(N * 32, 256), 256>>>(
        N, h3, es3, ed3, offsets, cnt, srcs, nullptr, agg3);

    // ---------------- Regressor (fused bias+ELU+dot+sigmoid) ----------------
    final_kernel<<<ceil_div(N * 32, 256), 256>>>(N, agg3, b3, Wr, br, out);
}